// round 1
// baseline (speedup 1.0000x reference)
#include <cuda_runtime.h>
#include <math.h>

// Problem dims (fixed by setup_inputs)
#define Bz 2
#define Sz 2048
#define Dz 1024
#define Tz 4096           // B*S
#define Hz 16
#define DHz 64
#define HIz 4
#define DIz 64
#define TKz 512
#define Ez 4
#define DFz 4096
#define NEGV -1e9f

// ---------------- scratch (device globals; no allocation allowed) --------------
__device__ float g_xn [Tz*Dz];
__device__ float g_q  [Tz*Dz];
__device__ float g_k  [Tz*Dz];
__device__ float g_v  [Tz*Dz];
__device__ float g_qI [Tz*HIz*DIz];
__device__ float g_kI [Tz*DIz];
__device__ float g_wI [Tz*HIz];
__device__ float g_sc [(size_t)Bz*Sz*Sz];     // indexer scores, only s<=t valid
__device__ int   g_selidx[(size_t)Tz*TKz];
__device__ int   g_selcnt[Tz];
__device__ float g_ao [Tz*Dz];
__device__ float g_x2 [Tz*Dz];
__device__ float g_xn2[Tz*Dz];
__device__ float g_wd [Tz*Ez];                // combine weights (0 for unselected)
__device__ float g_pr [Tz*Ez];                // gate probs (pre top-k)
__device__ float g_h  [(size_t)Tz*DFz];       // MoE hidden (reused per expert)
__device__ float g_ff [Tz*Dz];

// ---------------- helpers ------------------------------------------------------
__device__ __forceinline__ float gelu_f(float x) {
    // jax.nn.gelu default (approximate=True, tanh form)
    float x3 = x * x * x;
    return 0.5f * x * (1.0f + tanhf(0.7978845608028654f * (x + 0.044715f * x3)));
}

// ---------------- rmsnorm ------------------------------------------------------
__global__ void rmsnorm_kernel(const float* __restrict__ x, const float* __restrict__ w,
                               float* __restrict__ y) {
    int t = blockIdx.x;
    int tid = threadIdx.x;
    const float* xr = x + (size_t)t * Dz;
    float s = 0.f;
    for (int i = tid; i < Dz; i += 256) { float v = xr[i]; s += v * v; }
    __shared__ float red[256];
    red[tid] = s; __syncthreads();
    for (int off = 128; off; off >>= 1) {
        if (tid < off) red[tid] += red[tid + off];
        __syncthreads();
    }
    float inv = rsqrtf(red[0] * (1.0f / Dz) + 1e-6f);
    float* yr = y + (size_t)t * Dz;
    for (int i = tid; i < Dz; i += 256) yr[i] = xr[i] * inv * w[i];
}

// ---------------- generic SGEMM: C = epi(A[MxK] * B[KxN]) ----------------------
// epi 0: C = AB
// epi 1: C = AB + resid
// epi 2: C = gelu(AB + bias[col])
// epi 3: C += rowscale[row*rs_stride] * (AB + bias[col])
__global__ void __launch_bounds__(256)
sgemm_kernel(const float* __restrict__ A, const float* __restrict__ B,
             float* __restrict__ C, int M, int N, int K,
             int epi, const float* __restrict__ bias,
             const float* __restrict__ resid,
             const float* __restrict__ rowscale, int rs_stride) {
    const int BM = 128, BN = 128, BK = 8, TM = 8, TN = 8;
    __shared__ float As[BK][BM];
    __shared__ float Bs[BK][BN];
    int tid = threadIdx.x;
    int bm = blockIdx.y * BM;
    int bn = blockIdx.x * BN;
    int trow = (tid / 16) * TM;
    int tcol = (tid % 16) * TN;
    float acc[TM][TN];
#pragma unroll
    for (int i = 0; i < TM; i++)
#pragma unroll
        for (int j = 0; j < TN; j++) acc[i][j] = 0.f;

    int arow = tid >> 1, acol = (tid & 1) * 4;     // A: 128x8 tile, 1 float4/thread
    int brow = tid >> 5, bcol = (tid & 31) * 4;    // B: 8x128 tile, 1 float4/thread
    const float* Aptr = A + (size_t)(bm + arow) * K;

    for (int k0 = 0; k0 < K; k0 += BK) {
        float4 av = *(const float4*)(Aptr + k0 + acol);
        As[acol + 0][arow] = av.x;
        As[acol + 1][arow] = av.y;
        As[acol + 2][arow] = av.z;
        As[acol + 3][arow] = av.w;
        int bc = bn + bcol;
        if (bc + 4 <= N) {
            float4 bv = *(const float4*)(B + (size_t)(k0 + brow) * N + bc);
            *(float4*)&Bs[brow][bcol] = bv;
        } else {
#pragma unroll
            for (int j = 0; j < 4; j++)
                Bs[brow][bcol + j] = (bc + j < N) ? B[(size_t)(k0 + brow) * N + bc + j] : 0.f;
        }
        __syncthreads();
#pragma unroll
        for (int kk = 0; kk < BK; kk++) {
            float ar[TM], br[TN];
#pragma unroll
            for (int i = 0; i < TM; i++) ar[i] = As[kk][trow + i];
#pragma unroll
            for (int j = 0; j < TN; j++) br[j] = Bs[kk][tcol + j];
#pragma unroll
            for (int i = 0; i < TM; i++)
#pragma unroll
                for (int j = 0; j < TN; j++) acc[i][j] += ar[i] * br[j];
        }
        __syncthreads();
    }
#pragma unroll
    for (int i = 0; i < TM; i++) {
        int r = bm + trow + i;
#pragma unroll
        for (int j = 0; j < TN; j++) {
            int c = bn + tcol + j;
            if (c < N) {
                float val = acc[i][j];
                size_t idx = (size_t)r * N + c;
                if (epi == 0)      C[idx] = val;
                else if (epi == 1) C[idx] = val + resid[idx];
                else if (epi == 2) C[idx] = gelu_f(val + bias[c]);
                else               C[idx] += rowscale[(size_t)r * rs_stride] * (val + bias[c]);
            }
        }
    }
}

// ---------------- indexer scores: sc[b,t,s] = sum_h wI[t,h]*relu(qI[t,h,:].kI[s,:])
// block tile: 16 t x 64 s; threads (16,16), each thread 4 s values
__global__ void idxscore_kernel(const float* __restrict__ qI, const float* __restrict__ kI,
                                const float* __restrict__ wI, float* __restrict__ sc) {
    int b  = blockIdx.z;
    int t0 = blockIdx.y * 16;
    int s0 = blockIdx.x * 64;
    if (s0 > t0 + 15) return;   // entirely above diagonal
    __shared__ float qIs[16][257];
    __shared__ float kIs[64][65];
    __shared__ float wIs[16][4];
    int tx = threadIdx.x, ty = threadIdx.y;
    int tid = ty * 16 + tx;
    for (int idx = tid; idx < 16 * 256; idx += 256) {
        int r = idx >> 8, c = idx & 255;
        qIs[r][c] = qI[((size_t)(b * Sz + t0 + r)) * 256 + c];
    }
    for (int idx = tid; idx < 64 * 64; idx += 256) {
        int r = idx >> 6, c = idx & 63;
        kIs[r][c] = kI[((size_t)(b * Sz + s0 + r)) * 64 + c];
    }
    if (tid < 64) wIs[tid >> 2][tid & 3] = wI[((size_t)(b * Sz + t0 + (tid >> 2))) * 4 + (tid & 3)];
    __syncthreads();

    float acc4[4] = {0.f, 0.f, 0.f, 0.f};
#pragma unroll
    for (int h = 0; h < 4; h++) {
        float dot[4] = {0.f, 0.f, 0.f, 0.f};
#pragma unroll
        for (int d = 0; d < 64; d++) {
            float qv = qIs[ty][h * 64 + d];
            dot[0] += qv * kIs[tx +  0][d];
            dot[1] += qv * kIs[tx + 16][d];
            dot[2] += qv * kIs[tx + 32][d];
            dot[3] += qv * kIs[tx + 48][d];
        }
        float wv = wIs[ty][h];
#pragma unroll
        for (int j = 0; j < 4; j++) acc4[j] += wv * fmaxf(dot[j], 0.f);
    }
    int t = t0 + ty;
#pragma unroll
    for (int j = 0; j < 4; j++) {
        int s = s0 + tx + 16 * j;
        if (s <= t) sc[((size_t)(b * Sz + t)) * Sz + s] = acc4[j];
    }
}

// ---------------- top-k (512) per (b,t), jax tie-break (value desc, index asc) -
__global__ void topk_kernel(const float* __restrict__ sc, int* __restrict__ selidx,
                            int* __restrict__ selcnt) {
    int bt = blockIdx.x;
    int t = bt & (Sz - 1);
    int n = t + 1;
    int tid = threadIdx.x;
    int* outp = selidx + (size_t)bt * TKz;
    if (n <= TKz) {
        for (int i = tid; i < n; i += 256) outp[i] = i;
        if (tid == 0) selcnt[bt] = n;
        return;
    }
    const float* row = sc + (size_t)bt * Sz;
    __shared__ unsigned keys[Sz];
    for (int i = tid; i < n; i += 256) {
        unsigned u = __float_as_uint(row[i]);
        keys[i] = (u & 0x80000000u) ? ~u : (u | 0x80000000u);
    }
    __shared__ int cnt_s;
    unsigned p = 0;
    for (int bit = 31; bit >= 0; bit--) {
        unsigned q = p | (1u << bit);
        if (tid == 0) cnt_s = 0;
        __syncthreads();
        int c = 0;
        for (int i = tid; i < n; i += 256) c += (keys[i] >= q);
        for (int off = 16; off; off >>= 1) c += __shfl_xor_sync(0xffffffffu, c, off);
        if ((tid & 31) == 0) atomicAdd(&cnt_s, c);
        __syncthreads();
        int cv = cnt_s;
        __syncthreads();
        if (cv >= TKz) p = q;
    }
    // select all keys > p, then ties (== p) by ascending index
    __shared__ int pos;
    if (tid == 0) pos = 0;
    __syncthreads();
    for (int i = tid; i < n; i += 256)
        if (keys[i] > p) { int j = atomicAdd(&pos, 1); outp[j] = i; }
    __syncthreads();
    if (tid == 0) {
        int j = pos;
        for (int i = 0; i < n && j < TKz; i++)
            if (keys[i] == p) outp[j++] = i;
        selcnt[bt] = TKz;
    }
}

// ---------------- sparse attention over selected set ---------------------------
// block per (b,t); 8 warps, each warp 2 heads; online softmax; lane covers d,d+32
__global__ void attn_kernel(const float* __restrict__ q, const float* __restrict__ k,
                            const float* __restrict__ v, const int* __restrict__ selidx,
                            const int* __restrict__ selcnt, float* __restrict__ ao) {
    int bt = blockIdx.x;
    int b = bt >> 11;             // /Sz
    int tid = threadIdx.x;
    __shared__ float qs[Hz * DHz];
    __shared__ int sels[TKz];
    int n = selcnt[bt];
    for (int i = tid; i < Dz; i += 256) qs[i] = q[(size_t)bt * Dz + i];
    for (int i = tid; i < n; i += 256) sels[i] = selidx[(size_t)bt * TKz + i];
    __syncthreads();
    int warp = tid >> 5, lane = tid & 31;
    for (int h = warp; h < Hz; h += 8) {
        float m = -3.0e38f, l = 0.f, o0 = 0.f, o1 = 0.f;
        float q0 = qs[h * 64 + lane], q1 = qs[h * 64 + 32 + lane];
        for (int i = 0; i < n; i++) {
            int s = sels[i];
            const float* kp = k + ((size_t)(b * Sz + s)) * Dz + h * 64;
            float part = q0 * kp[lane] + q1 * kp[32 + lane];
#pragma unroll
            for (int off = 16; off; off >>= 1) part += __shfl_xor_sync(0xffffffffu, part, off);
            float score = part * 0.125f;
            float mn = fmaxf(m, score);
            float scale = __expf(m - mn);
            float pw = __expf(score - mn);
            const float* vp = v + ((size_t)(b * Sz + s)) * Dz + h * 64;
            o0 = o0 * scale + pw * vp[lane];
            o1 = o1 * scale + pw * vp[32 + lane];
            l = l * scale + pw;
            m = mn;
        }
        float inv = 1.0f / l;
        ao[(size_t)bt * Dz + h * 64 + lane]      = o0 * inv;
        ao[(size_t)bt * Dz + h * 64 + 32 + lane] = o1 * inv;
    }
}

// ---------------- gate: softmax(4) + top-2 + combine weights -------------------
__global__ void gate_kernel(const float* __restrict__ xn2, const float* __restrict__ gw,
                            float* __restrict__ wdense, float* __restrict__ probsb) {
    int t = blockIdx.x;
    int tid = threadIdx.x;
    const float* xr = xn2 + (size_t)t * Dz;
    float le[4] = {0.f, 0.f, 0.f, 0.f};
    for (int d = tid; d < Dz; d += 256) {
        float xv = xr[d];
        const float* g = gw + (size_t)d * 4;
        le[0] += xv * g[0]; le[1] += xv * g[1];
        le[2] += xv * g[2]; le[3] += xv * g[3];
    }
    __shared__ float red[4][256];
    for (int e = 0; e < 4; e++) red[e][tid] = le[e];
    __syncthreads();
    for (int off = 128; off; off >>= 1) {
        if (tid < off)
            for (int e = 0; e < 4; e++) red[e][tid] += red[e][tid + off];
        __syncthreads();
    }
    if (tid == 0) {
        float lg[4], pr[4];
        float mx = -3.0e38f;
        for (int e = 0; e < 4; e++) { lg[e] = red[e][0]; mx = fmaxf(mx, lg[e]); }
        float sum = 0.f;
        for (int e = 0; e < 4; e++) { pr[e] = expf(lg[e] - mx); sum += pr[e]; }
        float inv = 1.0f / sum;
        for (int e = 0; e < 4; e++) { pr[e] *= inv; probsb[(size_t)t * 4 + e] = pr[e]; }
        int i1 = 0;
        for (int e = 1; e < 4; e++) if (pr[e] > pr[i1]) i1 = e;
        int i2 = -1; float b2v = -1.f;
        for (int e = 0; e < 4; e++) if (e != i1 && pr[e] > b2v) { b2v = pr[e]; i2 = e; }
        float wsum = pr[i1] + pr[i2];
        float wd[4] = {0.f, 0.f, 0.f, 0.f};
        wd[i1] = pr[i1] / wsum;
        wd[i2] = pr[i2] / wsum;
        for (int e = 0; e < 4; e++) wdense[(size_t)t * 4 + e] = wd[e];
    }
}

// ---------------- aux loss (deterministic single-block reduction) --------------
__global__ void aux_kernel(const float* __restrict__ probsb, const float* __restrict__ wdense,
                           float* __restrict__ out_aux) {
    int tid = threadIdx.x;
    float sP[4] = {0.f, 0.f, 0.f, 0.f}, sF[4] = {0.f, 0.f, 0.f, 0.f};
    for (int t = tid; t < Tz; t += 256)
        for (int e = 0; e < 4; e++) {
            sP[e] += probsb[(size_t)t * 4 + e];
            sF[e] += (wdense[(size_t)t * 4 + e] > 0.f) ? 1.f : 0.f;
        }
    __shared__ float rP[4][256], rF[4][256];
    for (int e = 0; e < 4; e++) { rP[e][tid] = sP[e]; rF[e][tid] = sF[e]; }
    __syncthreads();
    for (int off = 128; off; off >>= 1) {
        if (tid < off)
            for (int e = 0; e < 4; e++) {
                rP[e][tid] += rP[e][tid + off];
                rF[e][tid] += rF[e][tid + off];
            }
        __syncthreads();
    }
    if (tid == 0) {
        float aux = 0.f;
        for (int e = 0; e < 4; e++)
            aux += (rF[e][0] * (1.0f / Tz)) * (rP[e][0] * (1.0f / Tz));
        *out_aux = (float)Ez * aux;
    }
}

// ---------------- misc elementwise ---------------------------------------------
__global__ void zero_kernel(float* __restrict__ p, int n) {
    for (int i = blockIdx.x * blockDim.x + threadIdx.x; i < n; i += gridDim.x * blockDim.x)
        p[i] = 0.f;
}
__global__ void final_kernel(const float* __restrict__ x2, const float* __restrict__ ff,
                             float* __restrict__ out) {
    for (int i = blockIdx.x * blockDim.x + threadIdx.x; i < Tz * Dz;
         i += gridDim.x * blockDim.x)
        out[i] = x2[i] + ff[i];
}

// ---------------- launch -------------------------------------------------------
extern "C" void kernel_launch(void* const* d_in, const int* in_sizes, int n_in,
                              void* d_out, int out_size) {
    const float* x      = (const float*)d_in[0];
    const float* n1w    = (const float*)d_in[1];
    const float* n2w    = (const float*)d_in[2];
    const float* wq     = (const float*)d_in[3];
    const float* wk     = (const float*)d_in[4];
    const float* wv     = (const float*)d_in[5];
    const float* wo     = (const float*)d_in[6];
    const float* idx_wq = (const float*)d_in[7];
    const float* idx_wk = (const float*)d_in[8];
    const float* idx_ww = (const float*)d_in[9];
    const float* gate_w = (const float*)d_in[10];
    const float* w1     = (const float*)d_in[11];
    const float* b1     = (const float*)d_in[12];
    const float* w2     = (const float*)d_in[13];
    const float* b2     = (const float*)d_in[14];
    float* out = (float*)d_out;

    float *xn, *q, *k, *v, *qI, *kI, *wI, *sc, *ao, *x2, *xn2, *wd, *pr, *hb, *ff;
    int *selidx, *selcnt;
    cudaGetSymbolAddress((void**)&xn,  g_xn);
    cudaGetSymbolAddress((void**)&q,   g_q);
    cudaGetSymbolAddress((void**)&k,   g_k);
    cudaGetSymbolAddress((void**)&v,   g_v);
    cudaGetSymbolAddress((void**)&qI,  g_qI);
    cudaGetSymbolAddress((void**)&kI,  g_kI);
    cudaGetSymbolAddress((void**)&wI,  g_wI);
    cudaGetSymbolAddress((void**)&sc,  g_sc);
    cudaGetSymbolAddress((void**)&selidx, g_selidx);
    cudaGetSymbolAddress((void**)&selcnt, g_selcnt);
    cudaGetSymbolAddress((void**)&ao,  g_ao);
    cudaGetSymbolAddress((void**)&x2,  g_x2);
    cudaGetSymbolAddress((void**)&xn2, g_xn2);
    cudaGetSymbolAddress((void**)&wd,  g_wd);
    cudaGetSymbolAddress((void**)&pr,  g_pr);
    cudaGetSymbolAddress((void**)&hb,  g_h);
    cudaGetSymbolAddress((void**)&ff,  g_ff);

    zero_kernel<<<4096, 256>>>(ff, Tz * Dz);

    // ---- attention path ----
    rmsnorm_kernel<<<Tz, 256>>>(x, n1w, xn);
    sgemm_kernel<<<dim3(8, 32), 256>>>(xn, wq, q, Tz, Dz, Dz, 0, nullptr, nullptr, nullptr, 0);
    sgemm_kernel<<<dim3(8, 32), 256>>>(xn, wk, k, Tz, Dz, Dz, 0, nullptr, nullptr, nullptr, 0);
    sgemm_kernel<<<dim3(8, 32), 256>>>(xn, wv, v, Tz, Dz, Dz, 0, nullptr, nullptr, nullptr, 0);
    sgemm_kernel<<<dim3(2, 32), 256>>>(xn, idx_wq, qI, Tz, 256, Dz, 0, nullptr, nullptr, nullptr, 0);
    sgemm_kernel<<<dim3(1, 32), 256>>>(xn, idx_wk, kI, Tz, 64, Dz, 0, nullptr, nullptr, nullptr, 0);
    sgemm_kernel<<<dim3(1, 32), 256>>>(xn, idx_ww, wI, Tz, 4, Dz, 0, nullptr, nullptr, nullptr, 0);

    idxscore_kernel<<<dim3(Sz / 64, Sz / 16, Bz), dim3(16, 16)>>>(qI, kI, wI, sc);
    topk_kernel<<<Tz, 256>>>(sc, selidx, selcnt);
    attn_kernel<<<Tz, 256>>>(q, k, v, selidx, selcnt, ao);
    sgemm_kernel<<<dim3(8, 32), 256>>>(ao, wo, x2, Tz, Dz, Dz, 1, nullptr, x, nullptr, 0);

    // ---- MoE path ----
    rmsnorm_kernel<<<Tz, 256>>>(x2, n2w, xn2);
    gate_kernel<<<Tz, 256>>>(xn2, gate_w, wd, pr);
    for (int e = 0; e < Ez; e++) {
        sgemm_kernel<<<dim3(32, 32), 256>>>(xn2, w1 + (size_t)e * Dz * DFz, hb,
                                            Tz, DFz, Dz, 2, b1 + (size_t)e * DFz,
                                            nullptr, nullptr, 0);
        sgemm_kernel<<<dim3(8, 32), 256>>>(hb, w2 + (size_t)e * DFz * Dz, ff,
                                           Tz, Dz, DFz, 3, b2 + (size_t)e * Dz,
                                           nullptr, wd + e, Ez);
    }

    aux_kernel<<<1, 256>>>(pr, wd, out + (out_size - 1));
    final_kernel<<<8192, 256>>>(x2, ff, out);
}

// round 5
// speedup vs baseline: 1.2448x; 1.2448x over previous
#include <cuda_runtime.h>
#include <math.h>

// Problem dims (fixed by setup_inputs)
#define Bz 2
#define Sz 2048
#define Dz 1024
#define Tz 4096           // B*S
#define Hz 16
#define DHz 64
#define HIz 4
#define DIz 64
#define TKz 512
#define Ez 4
#define DFz 4096

// ---------------- scratch (device globals; no allocation allowed) --------------
__device__ float g_xn [Tz*Dz];
__device__ float g_q  [Tz*Dz];
__device__ float g_k  [Tz*Dz];
__device__ float g_v  [Tz*Dz];
__device__ float g_qI [Tz*HIz*DIz];
__device__ float g_kI [Tz*DIz];
__device__ float g_wI [Tz*HIz];
__device__ float g_sc [(size_t)Bz*Sz*Sz];     // indexer scores, only s<=t valid
__device__ int   g_selidx[(size_t)Tz*TKz];
__device__ int   g_selcnt[Tz];
__device__ float g_ao [Tz*Dz];
__device__ float g_x2 [Tz*Dz];
__device__ float g_xn2[Tz*Dz];
__device__ float g_wd [Tz*Ez];                // combine weights (0 for unselected)
__device__ float g_pr [Tz*Ez];                // gate probs (pre top-k)
__device__ float g_h  [(size_t)Tz*DFz];       // MoE hidden (reused per expert)
__device__ float g_ff [Tz*Dz];

// ---------------- helpers ------------------------------------------------------
__device__ __forceinline__ float gelu_f(float x) {
    float x3 = x * x * x;
    return 0.5f * x * (1.0f + tanhf(0.7978845608028654f * (x + 0.044715f * x3)));
}

// ---------------- rmsnorm ------------------------------------------------------
__global__ void rmsnorm_kernel(const float* __restrict__ x, const float* __restrict__ w,
                               float* __restrict__ y) {
    int t = blockIdx.x;
    int tid = threadIdx.x;
    const float* xr = x + (size_t)t * Dz;
    float s = 0.f;
    for (int i = tid; i < Dz; i += 256) { float v = xr[i]; s += v * v; }
    __shared__ float red[256];
    red[tid] = s; __syncthreads();
    for (int off = 128; off; off >>= 1) {
        if (tid < off) red[tid] += red[tid + off];
        __syncthreads();
    }
    float inv = rsqrtf(red[0] * (1.0f / Dz) + 1e-6f);
    float* yr = y + (size_t)t * Dz;
    for (int i = tid; i < Dz; i += 256) yr[i] = xr[i] * inv * w[i];
}

// ---------------- SGEMM v2: BM=BN=128, BK=16, double-buffered ------------------
// EPI 0: C = AB
// EPI 1: C = AB + resid
// EPI 2: C = gelu(AB + bias[col])
// EPI 3: C += rowscale[row*rs_stride] * (AB + bias[col])
// EPI 4: C  = rowscale[row*rs_stride] * (AB + bias[col])
template<int EPI>
__global__ void __launch_bounds__(256, 2)
sgemm2_kernel(const float* __restrict__ A, const float* __restrict__ B,
              float* __restrict__ C, int M, int N, int K,
              const float* __restrict__ bias, const float* __restrict__ resid,
              const float* __restrict__ rowscale, int rs_stride) {
    const int BM = 128, BN = 128, BK = 16;
    __shared__ float As[2][BK][BM];
    __shared__ float Bs[2][BK][BN];
    int tid = threadIdx.x;
    int bm = blockIdx.y * BM;
    int bn = blockIdx.x * BN;
    int tx = tid & 15, ty = tid >> 4;

    // global load mapping
    int arow = tid >> 2;          // 0..63 (+64 for second)
    int acol = (tid & 3) * 4;     // 0,4,8,12
    int brow = tid >> 5;          // 0..7  (+8 for second)
    int bcol = (tid & 31) * 4;    // 0..124

    const float* Ap0 = A + (size_t)(bm + arow) * K + acol;
    const float* Ap1 = Ap0 + (size_t)64 * K;
    const float* Bp  = B + (size_t)brow * N + bn + bcol;
    bool bok = (bn + bcol + 4) <= N;

    float acc[8][8];
#pragma unroll
    for (int i = 0; i < 8; i++)
#pragma unroll
        for (int j = 0; j < 8; j++) acc[i][j] = 0.f;

    float4 a0, a1, b0, b1;
    // prologue: tile 0
    a0 = *(const float4*)(Ap0);
    a1 = *(const float4*)(Ap1);
    if (bok) {
        b0 = *(const float4*)(Bp);
        b1 = *(const float4*)(Bp + (size_t)8 * N);
    } else { b0 = make_float4(0,0,0,0); b1 = b0; }
    As[0][acol + 0][arow] = a0.x; As[0][acol + 1][arow] = a0.y;
    As[0][acol + 2][arow] = a0.z; As[0][acol + 3][arow] = a0.w;
    As[0][acol + 0][arow + 64] = a1.x; As[0][acol + 1][arow + 64] = a1.y;
    As[0][acol + 2][arow + 64] = a1.z; As[0][acol + 3][arow + 64] = a1.w;
    *(float4*)&Bs[0][brow][bcol] = b0;
    *(float4*)&Bs[0][brow + 8][bcol] = b1;
    __syncthreads();

    int KT = K / BK;
    int buf = 0;
    for (int kt = 0; kt < KT; kt++) {
        if (kt + 1 < KT) {
            const float* ap0 = Ap0 + (kt + 1) * BK;
            const float* ap1 = Ap1 + (kt + 1) * BK;
            a0 = *(const float4*)(ap0);
            a1 = *(const float4*)(ap1);
            if (bok) {
                const float* bp = Bp + (size_t)(kt + 1) * BK * N;
                b0 = *(const float4*)(bp);
                b1 = *(const float4*)(bp + (size_t)8 * N);
            }
        }
#pragma unroll
        for (int kk = 0; kk < BK; kk++) {
            float4 x0 = *(const float4*)&As[buf][kk][ty * 4];
            float4 x1 = *(const float4*)&As[buf][kk][ty * 4 + 64];
            float4 y0 = *(const float4*)&Bs[buf][kk][tx * 4];
            float4 y1 = *(const float4*)&Bs[buf][kk][tx * 4 + 64];
            float av[8] = {x0.x, x0.y, x0.z, x0.w, x1.x, x1.y, x1.z, x1.w};
            float bv[8] = {y0.x, y0.y, y0.z, y0.w, y1.x, y1.y, y1.z, y1.w};
#pragma unroll
            for (int i = 0; i < 8; i++)
#pragma unroll
                for (int j = 0; j < 8; j++) acc[i][j] += av[i] * bv[j];
        }
        if (kt + 1 < KT) {
            buf ^= 1;
            As[buf][acol + 0][arow] = a0.x; As[buf][acol + 1][arow] = a0.y;
            As[buf][acol + 2][arow] = a0.z; As[buf][acol + 3][arow] = a0.w;
            As[buf][acol + 0][arow + 64] = a1.x; As[buf][acol + 1][arow + 64] = a1.y;
            As[buf][acol + 2][arow + 64] = a1.z; As[buf][acol + 3][arow + 64] = a1.w;
            *(float4*)&Bs[buf][brow][bcol] = b0;
            *(float4*)&Bs[buf][brow + 8][bcol] = b1;
            __syncthreads();
        }
    }

#pragma unroll
    for (int i = 0; i < 8; i++) {
        int r = bm + ((i < 4) ? (ty * 4 + i) : (64 + ty * 4 + i - 4));
        float rsc = 0.f;
        if (EPI >= 3) rsc = rowscale[(size_t)r * rs_stride];
#pragma unroll
        for (int j = 0; j < 8; j++) {
            int c = bn + ((j < 4) ? (tx * 4 + j) : (64 + tx * 4 + j - 4));
            if (c < N) {
                float val = acc[i][j];
                size_t idx = (size_t)r * N + c;
                if (EPI == 0)      C[idx] = val;
                else if (EPI == 1) C[idx] = val + resid[idx];
                else if (EPI == 2) C[idx] = gelu_f(val + bias[c]);
                else if (EPI == 3) C[idx] += rsc * (val + bias[c]);
                else               C[idx] = rsc * (val + bias[c]);
            }
        }
    }
}

// ---------------- indexer scores ------------------------------------------------
__global__ void idxscore_kernel(const float* __restrict__ qI, const float* __restrict__ kI,
                                const float* __restrict__ wI, float* __restrict__ sc) {
    int b  = blockIdx.z;
    int t0 = blockIdx.y * 16;
    int s0 = blockIdx.x * 64;
    if (s0 > t0 + 15) return;
    __shared__ float qIs[16][257];
    __shared__ float kIs[64][65];
    __shared__ float wIs[16][4];
    int tx = threadIdx.x, ty = threadIdx.y;
    int tid = ty * 16 + tx;
    for (int idx = tid; idx < 16 * 256; idx += 256) {
        int r = idx >> 8, c = idx & 255;
        qIs[r][c] = qI[((size_t)(b * Sz + t0 + r)) * 256 + c];
    }
    for (int idx = tid; idx < 64 * 64; idx += 256) {
        int r = idx >> 6, c = idx & 63;
        kIs[r][c] = kI[((size_t)(b * Sz + s0 + r)) * 64 + c];
    }
    if (tid < 64) wIs[tid >> 2][tid & 3] = wI[((size_t)(b * Sz + (tid >> 2) + t0)) * 4 + (tid & 3)];
    __syncthreads();

    float acc4[4] = {0.f, 0.f, 0.f, 0.f};
#pragma unroll
    for (int h = 0; h < 4; h++) {
        float dot[4] = {0.f, 0.f, 0.f, 0.f};
#pragma unroll
        for (int d = 0; d < 64; d++) {
            float qv = qIs[ty][h * 64 + d];
            dot[0] += qv * kIs[tx +  0][d];
            dot[1] += qv * kIs[tx + 16][d];
            dot[2] += qv * kIs[tx + 32][d];
            dot[3] += qv * kIs[tx + 48][d];
        }
        float wv = wIs[ty][h];
#pragma unroll
        for (int j = 0; j < 4; j++) acc4[j] += wv * fmaxf(dot[j], 0.f);
    }
    int t = t0 + ty;
#pragma unroll
    for (int j = 0; j < 4; j++) {
        int s = s0 + tx + 16 * j;
        if (s <= t) sc[((size_t)(b * Sz + t)) * Sz + s] = acc4[j];
    }
}

// ---------------- top-k (512) per (b,t), jax tie-break --------------------------
__global__ void topk_kernel(const float* __restrict__ sc, int* __restrict__ selidx,
                            int* __restrict__ selcnt) {
    int bt = blockIdx.x;
    int t = bt & (Sz - 1);
    int n = t + 1;
    int tid = threadIdx.x;
    int* outp = selidx + (size_t)bt * TKz;
    if (n <= TKz) {
        for (int i = tid; i < n; i += 256) outp[i] = i;
        if (tid == 0) selcnt[bt] = n;
        return;
    }
    const float* row = sc + (size_t)bt * Sz;
    __shared__ unsigned keys[Sz];
    for (int i = tid; i < n; i += 256) {
        unsigned u = __float_as_uint(row[i]);
        keys[i] = (u & 0x80000000u) ? ~u : (u | 0x80000000u);
    }
    __shared__ int cnt_s;
    unsigned p = 0;
    for (int bit = 31; bit >= 0; bit--) {
        unsigned q = p | (1u << bit);
        if (tid == 0) cnt_s = 0;
        __syncthreads();
        int c = 0;
        for (int i = tid; i < n; i += 256) c += (keys[i] >= q);
        for (int off = 16; off; off >>= 1) c += __shfl_xor_sync(0xffffffffu, c, off);
        if ((tid & 31) == 0) atomicAdd(&cnt_s, c);
        __syncthreads();
        int cv = cnt_s;
        __syncthreads();
        if (cv >= TKz) p = q;
    }
    __shared__ int pos;
    if (tid == 0) pos = 0;
    __syncthreads();
    for (int i = tid; i < n; i += 256)
        if (keys[i] > p) { int j = atomicAdd(&pos, 1); outp[j] = i; }
    __syncthreads();
    if (tid == 0) {
        int j = pos;
        for (int i = 0; i < n && j < TKz; i++)
            if (keys[i] == p) outp[j++] = i;
        selcnt[bt] = TKz;
    }
}

// ---------------- sparse attention: block per (b,t), warp per head -------------
__global__ void __launch_bounds__(512)
attn_kernel(const float* __restrict__ q, const float* __restrict__ k,
            const float* __restrict__ v, const int* __restrict__ selidx,
            const int* __restrict__ selcnt, float* __restrict__ ao) {
    int bt = blockIdx.x;
    int b = bt >> 11;
    int tid = threadIdx.x;
    __shared__ float qs[Hz * DHz];
    __shared__ int sels[TKz];
    int n = selcnt[bt];
    for (int i = tid; i < Dz; i += 512) qs[i] = q[(size_t)bt * Dz + i];
    for (int i = tid; i < n; i += 512) sels[i] = selidx[(size_t)bt * TKz + i];
    __syncthreads();
    int h = tid >> 5, lane = tid & 31;
    float m = -3.0e38f, l = 0.f, o0 = 0.f, o1 = 0.f;
    float q0 = qs[h * 64 + lane], q1 = qs[h * 64 + 32 + lane];
    for (int i = 0; i < n; i++) {
        int s = sels[i];
        const float* kp = k + ((size_t)(b * Sz + s)) * Dz + h * 64;
        float part = q0 * kp[lane] + q1 * kp[32 + lane];
#pragma unroll
        for (int off = 16; off; off >>= 1) part += __shfl_xor_sync(0xffffffffu, part, off);
        float score = part * 0.125f;
        float mn = fmaxf(m, score);
        float scale = __expf(m - mn);
        float pw = __expf(score - mn);
        const float* vp = v + ((size_t)(b * Sz + s)) * Dz + h * 64;
        o0 = o0 * scale + pw * vp[lane];
        o1 = o1 * scale + pw * vp[32 + lane];
        l = l * scale + pw;
        m = mn;
    }
    float inv = 1.0f / l;
    ao[(size_t)bt * Dz + h * 64 + lane]      = o0 * inv;
    ao[(size_t)bt * Dz + h * 64 + 32 + lane] = o1 * inv;
}

// ---------------- gate: softmax(4) + top-2 + combine weights -------------------
__global__ void gate_kernel(const float* __restrict__ xn2, const float* __restrict__ gw,
                            float* __restrict__ wdense, float* __restrict__ probsb) {
    int t = blockIdx.x;
    int tid = threadIdx.x;
    const float* xr = xn2 + (size_t)t * Dz;
    float le[4] = {0.f, 0.f, 0.f, 0.f};
    for (int d = tid; d < Dz; d += 256) {
        float xv = xr[d];
        const float* g = gw + (size_t)d * 4;
        le[0] += xv * g[0]; le[1] += xv * g[1];
        le[2] += xv * g[2]; le[3] += xv * g[3];
    }
    __shared__ float red[4][256];
    for (int e = 0; e < 4; e++) red[e][tid] = le[e];
    __syncthreads();
    for (int off = 128; off; off >>= 1) {
        if (tid < off)
            for (int e = 0; e < 4; e++) red[e][tid] += red[e][tid + off];
        __syncthreads();
    }
    if (tid == 0) {
        float lg[4], pr[4];
        float mx = -3.0e38f;
        for (int e = 0; e < 4; e++) { lg[e] = red[e][0]; mx = fmaxf(mx, lg[e]); }
        float sum = 0.f;
        for (int e = 0; e < 4; e++) { pr[e] = expf(lg[e] - mx); sum += pr[e]; }
        float inv = 1.0f / sum;
        for (int e = 0; e < 4; e++) { pr[e] *= inv; probsb[(size_t)t * 4 + e] = pr[e]; }
        int i1 = 0;
        for (int e = 1; e < 4; e++) if (pr[e] > pr[i1]) i1 = e;
        int i2 = -1; float b2v = -1.f;
        for (int e = 0; e < 4; e++) if (e != i1 && pr[e] > b2v) { b2v = pr[e]; i2 = e; }
        float wsum = pr[i1] + pr[i2];
        float wd[4] = {0.f, 0.f, 0.f, 0.f};
        wd[i1] = pr[i1] / wsum;
        wd[i2] = pr[i2] / wsum;
        for (int e = 0; e < 4; e++) wdense[(size_t)t * 4 + e] = wd[e];
    }
}

// ---------------- aux loss ------------------------------------------------------
__global__ void aux_kernel(const float* __restrict__ probsb, const float* __restrict__ wdense,
                           float* __restrict__ out_aux) {
    int tid = threadIdx.x;
    float sP[4] = {0.f, 0.f, 0.f, 0.f}, sF[4] = {0.f, 0.f, 0.f, 0.f};
    for (int t = tid; t < Tz; t += 256)
        for (int e = 0; e < 4; e++) {
            sP[e] += probsb[(size_t)t * 4 + e];
            sF[e] += (wdense[(size_t)t * 4 + e] > 0.f) ? 1.f : 0.f;
        }
    __shared__ float rP[4][256], rF[4][256];
    for (int e = 0; e < 4; e++) { rP[e][tid] = sP[e]; rF[e][tid] = sF[e]; }
    __syncthreads();
    for (int off = 128; off; off >>= 1) {
        if (tid < off)
            for (int e = 0; e < 4; e++) {
                rP[e][tid] += rP[e][tid + off];
                rF[e][tid] += rF[e][tid + off];
            }
        __syncthreads();
    }
    if (tid == 0) {
        float aux = 0.f;
        for (int e = 0; e < 4; e++)
            aux += (rF[e][0] * (1.0f / Tz)) * (rP[e][0] * (1.0f / Tz));
        *out_aux = (float)Ez * aux;
    }
}

__global__ void final_kernel(const float* __restrict__ x2, const float* __restrict__ ff,
                             float* __restrict__ out) {
    for (int i = blockIdx.x * blockDim.x + threadIdx.x; i < Tz * Dz;
         i += gridDim.x * blockDim.x)
        out[i] = x2[i] + ff[i];
}

// ---------------- launch -------------------------------------------------------
extern "C" void kernel_launch(void* const* d_in, const int* in_sizes, int n_in,
                              void* d_out, int out_size) {
    const float* x      = (const float*)d_in[0];
    const float* n1w    = (const float*)d_in[1];
    const float* n2w    = (const float*)d_in[2];
    const float* wq     = (const float*)d_in[3];
    const float* wk     = (const float*)d_in[4];
    const float* wv     = (const float*)d_in[5];
    const float* wo     = (const float*)d_in[6];
    const float* idx_wq = (const float*)d_in[7];
    const float* idx_wk = (const float*)d_in[8];
    const float* idx_ww = (const float*)d_in[9];
    const float* gate_w = (const float*)d_in[10];
    const float* w1     = (const float*)d_in[11];
    const float* b1     = (const float*)d_in[12];
    const float* w2     = (const float*)d_in[13];
    const float* b2     = (const float*)d_in[14];
    float* out = (float*)d_out;

    float *xn, *q, *k, *v, *qI, *kI, *wI, *sc, *ao, *x2, *xn2, *wd, *pr, *hb, *ff;
    int *selidx, *selcnt;
    cudaGetSymbolAddress((void**)&xn,  g_xn);
    cudaGetSymbolAddress((void**)&q,   g_q);
    cudaGetSymbolAddress((void**)&k,   g_k);
    cudaGetSymbolAddress((void**)&v,   g_v);
    cudaGetSymbolAddress((void**)&qI,  g_qI);
    cudaGetSymbolAddress((void**)&kI,  g_kI);
    cudaGetSymbolAddress((void**)&wI,  g_wI);
    cudaGetSymbolAddress((void**)&sc,  g_sc);
    cudaGetSymbolAddress((void**)&selidx, g_selidx);
    cudaGetSymbolAddress((void**)&selcnt, g_selcnt);
    cudaGetSymbolAddress((void**)&ao,  g_ao);
    cudaGetSymbolAddress((void**)&x2,  g_x2);
    cudaGetSymbolAddress((void**)&xn2, g_xn2);
    cudaGetSymbolAddress((void**)&wd,  g_wd);
    cudaGetSymbolAddress((void**)&pr,  g_pr);
    cudaGetSymbolAddress((void**)&hb,  g_h);
    cudaGetSymbolAddress((void**)&ff,  g_ff);

    // ---- attention path ----
    rmsnorm_kernel<<<Tz, 256>>>(x, n1w, xn);
    sgemm2_kernel<0><<<dim3(8, 32), 256>>>(xn, wq, q, Tz, Dz, Dz, nullptr, nullptr, nullptr, 0);
    sgemm2_kernel<0><<<dim3(8, 32), 256>>>(xn, wk, k, Tz, Dz, Dz, nullptr, nullptr, nullptr, 0);
    sgemm2_kernel<0><<<dim3(8, 32), 256>>>(xn, wv, v, Tz, Dz, Dz, nullptr, nullptr, nullptr, 0);
    sgemm2_kernel<0><<<dim3(2, 32), 256>>>(xn, idx_wq, qI, Tz, 256, Dz, nullptr, nullptr, nullptr, 0);
    sgemm2_kernel<0><<<dim3(1, 32), 256>>>(xn, idx_wk, kI, Tz, 64, Dz, nullptr, nullptr, nullptr, 0);
    sgemm2_kernel<0><<<dim3(1, 32), 256>>>(xn, idx_ww, wI, Tz, 4, Dz, nullptr, nullptr, nullptr, 0);

    idxscore_kernel<<<dim3(Sz / 64, Sz / 16, Bz), dim3(16, 16)>>>(qI, kI, wI, sc);
    topk_kernel<<<Tz, 256>>>(sc, selidx, selcnt);
    attn_kernel<<<Tz, 512>>>(q, k, v, selidx, selcnt, ao);
    sgemm2_kernel<1><<<dim3(8, 32), 256>>>(ao, wo, x2, Tz, Dz, Dz, nullptr, x, nullptr, 0);

    // ---- MoE path ----
    rmsnorm_kernel<<<Tz, 256>>>(x2, n2w, xn2);
    gate_kernel<<<Tz, 256>>>(xn2, gate_w, wd, pr);
    for (int e = 0; e < Ez; e++) {
        sgemm2_kernel<2><<<dim3(32, 32), 256>>>(xn2, w1 + (size_t)e * Dz * DFz, hb,
                                                Tz, DFz, Dz, b1 + (size_t)e * DFz,
                                                nullptr, nullptr, 0);
        if (e == 0)
            sgemm2_kernel<4><<<dim3(8, 32), 256>>>(hb, w2 + (size_t)e * DFz * Dz, ff,
                                                   Tz, Dz, DFz, b2 + (size_t)e * Dz,
                                                   nullptr, wd + e, Ez);
        else
            sgemm2_kernel<3><<<dim3(8, 32), 256>>>(hb, w2 + (size_t)e * DFz * Dz, ff,
                                                   Tz, Dz, DFz, b2 + (size_t)e * Dz,
                                                   nullptr, wd + e, Ez);
    }

    aux_kernel<<<1, 256>>>(pr, wd, out + (out_size - 1));
    final_kernel<<<8192, 256>>>(x2, ff, out);
}

// round 7
// speedup vs baseline: 1.9561x; 1.5715x over previous
#include <cuda_runtime.h>
#include <cuda_bf16.h>
#include <math.h>
#include <stdint.h>

// Problem dims (fixed by setup_inputs)
#define Bz 2
#define Sz 2048
#define Dz 1024
#define Tz 4096           // B*S
#define Hz 16
#define DHz 64
#define HIz 4
#define DIz 64
#define TKz 512
#define Ez 4
#define DFz 4096

typedef __nv_bfloat16 bf16;

// ---------------- scratch (device globals; no allocation allowed) --------------
__device__ float g_xn [Tz*Dz];                 // fp32 norm1(x) (for small gemms)
__device__ float g_q  [Tz*Dz];
__device__ float g_k  [Tz*Dz];
__device__ float g_v  [Tz*Dz];
__device__ float g_qI [Tz*HIz*DIz];
__device__ float g_kI [Tz*DIz];
__device__ float g_wI [Tz*HIz];
__device__ float g_sc [(size_t)Bz*Sz*Sz];
__device__ int   g_selidx[(size_t)Tz*TKz];
__device__ int   g_selcnt[Tz];
__device__ float g_x2 [Tz*Dz];
__device__ float g_xn2[Tz*Dz];
__device__ float g_wd [Tz*Ez];
__device__ float g_pr [Tz*Ez];
__device__ float g_ff [Tz*Dz];

// bf16 split-expanded operands (activations: [hi|hi|lo] cols; weights: [hi;lo;hi] rows)
__device__ bf16 g_xnx  [(size_t)Tz*3*Dz];
__device__ bf16 g_xn2x [(size_t)Tz*3*Dz];
__device__ bf16 g_aox  [(size_t)Tz*3*Dz];
__device__ bf16 g_hx   [(size_t)Tz*3*DFz];    // gelu output, expanded
__device__ bf16 g_wqx  [3*Dz*Dz];
__device__ bf16 g_wkx  [3*Dz*Dz];
__device__ bf16 g_wvx  [3*Dz*Dz];
__device__ bf16 g_wox  [3*Dz*Dz];
__device__ bf16 g_iwqx [3*Dz*HIz*DIz];
__device__ bf16 g_w1x  [(size_t)Ez*3*Dz*DFz];
__device__ bf16 g_w2x  [(size_t)Ez*3*DFz*Dz];

// ---------------- helpers ------------------------------------------------------
__device__ __forceinline__ float gelu_f(float x) {
    float x3 = x * x * x;
    return 0.5f * x * (1.0f + tanhf(0.7978845608028654f * (x + 0.044715f * x3)));
}
__device__ __forceinline__ uint32_t smem_u32(const void* p) {
    return (uint32_t)__cvta_generic_to_shared(p);
}
__device__ __forceinline__ void ldsm4(uint32_t& r0, uint32_t& r1, uint32_t& r2,
                                      uint32_t& r3, uint32_t a) {
    asm volatile("ldmatrix.sync.aligned.m8n8.x4.shared.b16 {%0,%1,%2,%3}, [%4];\n"
                 : "=r"(r0), "=r"(r1), "=r"(r2), "=r"(r3) : "r"(a));
}
__device__ __forceinline__ void ldsm4t(uint32_t& r0, uint32_t& r1, uint32_t& r2,
                                       uint32_t& r3, uint32_t a) {
    asm volatile("ldmatrix.sync.aligned.m8n8.x4.trans.shared.b16 {%0,%1,%2,%3}, [%4];\n"
                 : "=r"(r0), "=r"(r1), "=r"(r2), "=r"(r3) : "r"(a));
}
__device__ __forceinline__ void mma_bf16(float c[4], uint32_t a0, uint32_t a1,
                                         uint32_t a2, uint32_t a3,
                                         uint32_t b0, uint32_t b1) {
    asm volatile("mma.sync.aligned.m16n8k16.row.col.f32.bf16.bf16.f32 "
                 "{%0,%1,%2,%3}, {%4,%5,%6,%7}, {%8,%9}, {%0,%1,%2,%3};\n"
                 : "+f"(c[0]), "+f"(c[1]), "+f"(c[2]), "+f"(c[3])
                 : "r"(a0), "r"(a1), "r"(a2), "r"(a3), "r"(b0), "r"(b1));
}
#define CPA16(dst, src) \
    asm volatile("cp.async.cg.shared.global [%0], [%1], 16;\n" :: "r"(dst), "l"(src))
#define CPA_COMMIT() asm volatile("cp.async.commit_group;\n" ::)
#define CPA_WAIT0()  asm volatile("cp.async.wait_group 0;\n" ::)

// ---------------- rmsnorm (fp32 out optional + bf16 split-expanded out) --------
__global__ void rmsnorm2_kernel(const float* __restrict__ x, const float* __restrict__ w,
                                float* __restrict__ y, bf16* __restrict__ yx) {
    int t = blockIdx.x;
    int tid = threadIdx.x;
    const float* xr = x + (size_t)t * Dz;
    float s = 0.f;
    for (int i = tid; i < Dz; i += 256) { float v = xr[i]; s += v * v; }
    __shared__ float red[256];
    red[tid] = s; __syncthreads();
    for (int off = 128; off; off >>= 1) {
        if (tid < off) red[tid] += red[tid + off];
        __syncthreads();
    }
    float inv = rsqrtf(red[0] * (1.0f / Dz) + 1e-6f);
    bf16* yr = yx + (size_t)t * 3 * Dz;
    for (int i = tid; i < Dz; i += 256) {
        float v = xr[i] * inv * w[i];
        if (y) y[(size_t)t * Dz + i] = v;
        bf16 hi = __float2bfloat16(v);
        bf16 lo = __float2bfloat16(v - __bfloat162float(hi));
        yr[i] = hi;
        yr[Dz + i] = hi;
        yr[2 * Dz + i] = lo;
    }
}

// ---------------- weight split-expansion: [K][N] fp32 -> [3K][N] bf16 ----------
__global__ void convw_kernel(const float* __restrict__ src, bf16* __restrict__ dst,
                             int K, int N) {
    size_t total = (size_t)K * N;
    for (size_t i = blockIdx.x * blockDim.x + threadIdx.x; i < total;
         i += (size_t)gridDim.x * blockDim.x) {
        int k = (int)(i / N), n = (int)(i % N);
        float a = src[i];
        bf16 hi = __float2bfloat16(a);
        bf16 lo = __float2bfloat16(a - __bfloat162float(hi));
        dst[(size_t)k * N + n] = hi;
        dst[(size_t)(K + k) * N + n] = lo;
        dst[(size_t)(2 * K + k) * N + n] = hi;
    }
}

// ---------------- bf16 tensor-core GEMM ----------------------------------------
// C[M,N] = epi(A[M,K]bf16 row-major x B[K,N]bf16 row-major), K % 32 == 0,
// M % 128 == 0, N % 128 == 0. BM=BN=128, BK=32, 256 threads, warp tile 64x32.
// EPI 0: Cf = val
// EPI 1: Cf = val + resid
// EPI 2: Cb (bf16, row stride 3N): hi @ c, hi @ N+c, lo @ 2N+c of gelu(val+bias)
// EPI 3: Cf += rowscale[r*rs_stride] * (val + bias[c])
// EPI 4: Cf  = rowscale[r*rs_stride] * (val + bias[c])
template<int EPI>
__global__ void __launch_bounds__(256, 2)
hgemm_kernel(const bf16* __restrict__ A, const bf16* __restrict__ B,
             float* __restrict__ Cf, bf16* __restrict__ Cb,
             int M, int N, int K,
             const float* __restrict__ bias, const float* __restrict__ resid,
             const float* __restrict__ rowscale, int rs_stride) {
    __shared__ __align__(16) bf16 As[2][128][40];   // pad 8 -> 80B rows
    __shared__ __align__(16) bf16 Bs[2][32][136];   // pad 8 -> 272B rows
    int tid = threadIdx.x;
    int bm = blockIdx.y * 128, bn = blockIdx.x * 128;
    int warp = tid >> 5, lane = tid & 31;
    int wm = (warp & 1) * 64, wn = (warp >> 1) * 32;

    // global sources for cp.async (2 x 16B for A, 2 x 16B for B per thread)
    int arow = tid >> 2, acol = (tid & 3) * 8;      // A: rows 0..63 (+64)
    int brow = tid >> 4, bcol = (tid & 15) * 8;     // B: rows 0..15 (+16)
    const bf16* Ag0 = A + (size_t)(bm + arow) * K + acol;
    const bf16* Ag1 = Ag0 + (size_t)64 * K;
    const bf16* Bg0 = B + (size_t)brow * N + bn + bcol;
    const bf16* Bg1 = Bg0 + (size_t)16 * N;

    float c[4][4][4];
#pragma unroll
    for (int mi = 0; mi < 4; mi++)
#pragma unroll
        for (int ni = 0; ni < 4; ni++)
#pragma unroll
            for (int j = 0; j < 4; j++) c[mi][ni][j] = 0.f;

    int KT = K >> 5;
    // prologue: issue tile 0 into buf 0
    {
        CPA16(smem_u32(&As[0][arow][acol]), Ag0);
        CPA16(smem_u32(&As[0][arow + 64][acol]), Ag1);
        CPA16(smem_u32(&Bs[0][brow][bcol]), Bg0);
        CPA16(smem_u32(&Bs[0][brow + 16][bcol]), Bg1);
        CPA_COMMIT();
    }
    int buf = 0;
    for (int kt = 0; kt < KT; kt++) {
        CPA_WAIT0();
        __syncthreads();
        if (kt + 1 < KT) {
            int nb = buf ^ 1;
            const bf16* a0 = Ag0 + (kt + 1) * 32;
            const bf16* a1 = Ag1 + (kt + 1) * 32;
            const bf16* b0 = Bg0 + (size_t)(kt + 1) * 32 * N;
            const bf16* b1 = Bg1 + (size_t)(kt + 1) * 32 * N;
            CPA16(smem_u32(&As[nb][arow][acol]), a0);
            CPA16(smem_u32(&As[nb][arow + 64][acol]), a1);
            CPA16(smem_u32(&Bs[nb][brow][bcol]), b0);
            CPA16(smem_u32(&Bs[nb][brow + 16][bcol]), b1);
            CPA_COMMIT();
        }
#pragma unroll
        for (int kk = 0; kk < 32; kk += 16) {
            uint32_t a[4][4], b[4][2];
#pragma unroll
            for (int mi = 0; mi < 4; mi++) {
                uint32_t addr = smem_u32(
                    &As[buf][wm + mi * 16 + (lane & 15)][kk + ((lane >> 4) << 3)]);
                ldsm4(a[mi][0], a[mi][1], a[mi][2], a[mi][3], addr);
            }
#pragma unroll
            for (int nj = 0; nj < 2; nj++) {
                uint32_t addr = smem_u32(
                    &Bs[buf][kk + (lane & 15)][wn + nj * 16 + ((lane >> 4) << 3)]);
                ldsm4t(b[2 * nj][0], b[2 * nj][1], b[2 * nj + 1][0], b[2 * nj + 1][1], addr);
            }
#pragma unroll
            for (int mi = 0; mi < 4; mi++)
#pragma unroll
                for (int ni = 0; ni < 4; ni++)
                    mma_bf16(c[mi][ni], a[mi][0], a[mi][1], a[mi][2], a[mi][3],
                             b[ni][0], b[ni][1]);
        }
        buf ^= 1;
    }

    // epilogue: lane l owns (r0 = l/4, c0 = (l%4)*2) within each m16n8 tile
#pragma unroll
    for (int mi = 0; mi < 4; mi++) {
#pragma unroll
        for (int rr = 0; rr < 2; rr++) {
            int r = bm + wm + mi * 16 + (lane >> 2) + rr * 8;
            float rsc = 0.f;
            if (EPI >= 3) rsc = rowscale[(size_t)r * rs_stride];
#pragma unroll
            for (int ni = 0; ni < 4; ni++) {
#pragma unroll
                for (int cc = 0; cc < 2; cc++) {
                    int col = bn + wn + ni * 8 + (lane & 3) * 2 + cc;
                    float val = c[mi][ni][rr * 2 + cc];
                    if (EPI == 0) {
                        Cf[(size_t)r * N + col] = val;
                    } else if (EPI == 1) {
                        Cf[(size_t)r * N + col] = val + resid[(size_t)r * N + col];
                    } else if (EPI == 2) {
                        float g = gelu_f(val + bias[col]);
                        bf16 hi = __float2bfloat16(g);
                        bf16 lo = __float2bfloat16(g - __bfloat162float(hi));
                        size_t base = (size_t)r * 3 * N;
                        Cb[base + col] = hi;
                        Cb[base + N + col] = hi;
                        Cb[base + 2 * N + col] = lo;
                    } else if (EPI == 3) {
                        Cf[(size_t)r * N + col] += rsc * (val + bias[col]);
                    } else {
                        Cf[(size_t)r * N + col] = rsc * (val + bias[col]);
                    }
                }
            }
        }
    }
}

// ---------------- small fp32 GEMM (kI: N=64, wI: N=4) --------------------------
__global__ void __launch_bounds__(256, 2)
sgemm_small_kernel(const float* __restrict__ A, const float* __restrict__ B,
                   float* __restrict__ C, int M, int N, int K) {
    const int BM = 128, BN = 128, BK = 8, TM = 8, TN = 8;
    __shared__ float As[BK][BM];
    __shared__ float Bs[BK][BN];
    int tid = threadIdx.x;
    int bm = blockIdx.y * BM;
    int bn = blockIdx.x * BN;
    int trow = (tid / 16) * TM;
    int tcol = (tid % 16) * TN;
    float acc[TM][TN];
#pragma unroll
    for (int i = 0; i < TM; i++)
#pragma unroll
        for (int j = 0; j < TN; j++) acc[i][j] = 0.f;
    int arow = tid >> 1, acol = (tid & 1) * 4;
    int brow = tid >> 5, bcol = (tid & 31) * 4;
    const float* Aptr = A + (size_t)(bm + arow) * K;
    for (int k0 = 0; k0 < K; k0 += BK) {
        float4 av = *(const float4*)(Aptr + k0 + acol);
        As[acol + 0][arow] = av.x; As[acol + 1][arow] = av.y;
        As[acol + 2][arow] = av.z; As[acol + 3][arow] = av.w;
        int bc = bn + bcol;
#pragma unroll
        for (int j = 0; j < 4; j++)
            Bs[brow][bcol + j] = (bc + j < N) ? B[(size_t)(k0 + brow) * N + bc + j] : 0.f;
        __syncthreads();
#pragma unroll
        for (int kk = 0; kk < BK; kk++) {
            float ar[TM], br[TN];
#pragma unroll
            for (int i = 0; i < TM; i++) ar[i] = As[kk][trow + i];
#pragma unroll
            for (int j = 0; j < TN; j++) br[j] = Bs[kk][tcol + j];
#pragma unroll
            for (int i = 0; i < TM; i++)
#pragma unroll
                for (int j = 0; j < TN; j++) acc[i][j] += ar[i] * br[j];
        }
        __syncthreads();
    }
#pragma unroll
    for (int i = 0; i < TM; i++) {
        int r = bm + trow + i;
#pragma unroll
        for (int j = 0; j < TN; j++) {
            int cidx = bn + tcol + j;
            if (cidx < N) C[(size_t)r * N + cidx] = acc[i][j];
        }
    }
}

// ---------------- indexer scores ------------------------------------------------
__global__ void idxscore_kernel(const float* __restrict__ qI, const float* __restrict__ kI,
                                const float* __restrict__ wI, float* __restrict__ sc) {
    int b  = blockIdx.z;
    int t0 = blockIdx.y * 16;
    int s0 = blockIdx.x * 64;
    if (s0 > t0 + 15) return;
    __shared__ float qIs[16][257];
    __shared__ float kIs[64][65];
    __shared__ float wIs[16][4];
    int tx = threadIdx.x, ty = threadIdx.y;
    int tid = ty * 16 + tx;
    for (int idx = tid; idx < 16 * 256; idx += 256) {
        int r = idx >> 8, c = idx & 255;
        qIs[r][c] = qI[((size_t)(b * Sz + t0 + r)) * 256 + c];
    }
    for (int idx = tid; idx < 64 * 64; idx += 256) {
        int r = idx >> 6, c = idx & 63;
        kIs[r][c] = kI[((size_t)(b * Sz + s0 + r)) * 64 + c];
    }
    if (tid < 64) wIs[tid >> 2][tid & 3] = wI[((size_t)(b * Sz + (tid >> 2) + t0)) * 4 + (tid & 3)];
    __syncthreads();

    float acc4[4] = {0.f, 0.f, 0.f, 0.f};
#pragma unroll
    for (int h = 0; h < 4; h++) {
        float dot[4] = {0.f, 0.f, 0.f, 0.f};
#pragma unroll
        for (int d = 0; d < 64; d++) {
            float qv = qIs[ty][h * 64 + d];
            dot[0] += qv * kIs[tx +  0][d];
            dot[1] += qv * kIs[tx + 16][d];
            dot[2] += qv * kIs[tx + 32][d];
            dot[3] += qv * kIs[tx + 48][d];
        }
        float wv = wIs[ty][h];
#pragma unroll
        for (int j = 0; j < 4; j++) acc4[j] += wv * fmaxf(dot[j], 0.f);
    }
    int t = t0 + ty;
#pragma unroll
    for (int j = 0; j < 4; j++) {
        int s = s0 + tx + 16 * j;
        if (s <= t) sc[((size_t)(b * Sz + t)) * Sz + s] = acc4[j];
    }
}

// ---------------- top-k (512) per (b,t), jax tie-break --------------------------
__global__ void topk_kernel(const float* __restrict__ sc, int* __restrict__ selidx,
                            int* __restrict__ selcnt) {
    int bt = blockIdx.x;
    int t = bt & (Sz - 1);
    int n = t + 1;
    int tid = threadIdx.x;
    int* outp = selidx + (size_t)bt * TKz;
    if (n <= TKz) {
        for (int i = tid; i < n; i += 256) outp[i] = i;
        if (tid == 0) selcnt[bt] = n;
        return;
    }
    const float* row = sc + (size_t)bt * Sz;
    __shared__ unsigned keys[Sz];
    for (int i = tid; i < n; i += 256) {
        unsigned u = __float_as_uint(row[i]);
        keys[i] = (u & 0x80000000u) ? ~u : (u | 0x80000000u);
    }
    __shared__ int cnt_s;
    unsigned p = 0;
    for (int bit = 31; bit >= 0; bit--) {
        unsigned q = p | (1u << bit);
        if (tid == 0) cnt_s = 0;
        __syncthreads();
        int c = 0;
        for (int i = tid; i < n; i += 256) c += (keys[i] >= q);
        for (int off = 16; off; off >>= 1) c += __shfl_xor_sync(0xffffffffu, c, off);
        if ((tid & 31) == 0) atomicAdd(&cnt_s, c);
        __syncthreads();
        int cv = cnt_s;
        __syncthreads();
        if (cv >= TKz) p = q;
    }
    __shared__ int pos;
    if (tid == 0) pos = 0;
    __syncthreads();
    for (int i = tid; i < n; i += 256)
        if (keys[i] > p) { int j = atomicAdd(&pos, 1); outp[j] = i; }
    __syncthreads();
    if (tid == 0) {
        int j = pos;
        for (int i = 0; i < n && j < TKz; i++)
            if (keys[i] == p) outp[j++] = i;
        selcnt[bt] = TKz;
    }
}

// ---------------- sparse attention: writes split-expanded bf16 ao' --------------
__global__ void __launch_bounds__(512)
attn_kernel(const float* __restrict__ q, const float* __restrict__ k,
            const float* __restrict__ v, const int* __restrict__ selidx,
            const int* __restrict__ selcnt, bf16* __restrict__ aox) {
    int bt = blockIdx.x;
    int b = bt >> 11;
    int tid = threadIdx.x;
    __shared__ float qs[Hz * DHz];
    __shared__ int sels[TKz];
    int n = selcnt[bt];
    for (int i = tid; i < Dz; i += 512) qs[i] = q[(size_t)bt * Dz + i];
    for (int i = tid; i < n; i += 512) sels[i] = selidx[(size_t)bt * TKz + i];
    __syncthreads();
    int h = tid >> 5, lane = tid & 31;
    float m = -3.0e38f, l = 0.f, o0 = 0.f, o1 = 0.f;
    float q0 = qs[h * 64 + lane], q1 = qs[h * 64 + 32 + lane];
    for (int i = 0; i < n; i++) {
        int s = sels[i];
        const float* kp = k + ((size_t)(b * Sz + s)) * Dz + h * 64;
        float part = q0 * kp[lane] + q1 * kp[32 + lane];
#pragma unroll
        for (int off = 16; off; off >>= 1) part += __shfl_xor_sync(0xffffffffu, part, off);
        float score = part * 0.125f;
        float mn = fmaxf(m, score);
        float scale = __expf(m - mn);
        float pw = __expf(score - mn);
        const float* vp = v + ((size_t)(b * Sz + s)) * Dz + h * 64;
        o0 = o0 * scale + pw * vp[lane];
        o1 = o1 * scale + pw * vp[32 + lane];
        l = l * scale + pw;
        m = mn;
    }
    float inv = 1.0f / l;
    o0 *= inv; o1 *= inv;
    size_t base = (size_t)bt * 3 * Dz;
    int c0 = h * 64 + lane, c1 = c0 + 32;
    bf16 h0 = __float2bfloat16(o0);
    bf16 l0 = __float2bfloat16(o0 - __bfloat162float(h0));
    bf16 h1 = __float2bfloat16(o1);
    bf16 l1 = __float2bfloat16(o1 - __bfloat162float(h1));
    aox[base + c0] = h0;           aox[base + c1] = h1;
    aox[base + Dz + c0] = h0;      aox[base + Dz + c1] = h1;
    aox[base + 2 * Dz + c0] = l0;  aox[base + 2 * Dz + c1] = l1;
}

// ---------------- gate: softmax(4) + top-2 + combine weights -------------------
__global__ void gate_kernel(const float* __restrict__ xn2, const float* __restrict__ gw,
                            float* __restrict__ wdense, float* __restrict__ probsb) {
    int t = blockIdx.x;
    int tid = threadIdx.x;
    const float* xr = xn2 + (size_t)t * Dz;
    float le[4] = {0.f, 0.f, 0.f, 0.f};
    for (int d = tid; d < Dz; d += 256) {
        float xv = xr[d];
        const float* g = gw + (size_t)d * 4;
        le[0] += xv * g[0]; le[1] += xv * g[1];
        le[2] += xv * g[2]; le[3] += xv * g[3];
    }
    __shared__ float red[4][256];
    for (int e = 0; e < 4; e++) red[e][tid] = le[e];
    __syncthreads();
    for (int off = 128; off; off >>= 1) {
        if (tid < off)
            for (int e = 0; e < 4; e++) red[e][tid] += red[e][tid + off];
        __syncthreads();
    }
    if (tid == 0) {
        float lg[4], pr[4];
        float mx = -3.0e38f;
        for (int e = 0; e < 4; e++) { lg[e] = red[e][0]; mx = fmaxf(mx, lg[e]); }
        float sum = 0.f;
        for (int e = 0; e < 4; e++) { pr[e] = expf(lg[e] - mx); sum += pr[e]; }
        float inv = 1.0f / sum;
        for (int e = 0; e < 4; e++) { pr[e] *= inv; probsb[(size_t)t * 4 + e] = pr[e]; }
        int i1 = 0;
        for (int e = 1; e < 4; e++) if (pr[e] > pr[i1]) i1 = e;
        int i2 = -1; float b2v = -1.f;
        for (int e = 0; e < 4; e++) if (e != i1 && pr[e] > b2v) { b2v = pr[e]; i2 = e; }
        float wsum = pr[i1] + pr[i2];
        float wd[4] = {0.f, 0.f, 0.f, 0.f};
        wd[i1] = pr[i1] / wsum;
        wd[i2] = pr[i2] / wsum;
        for (int e = 0; e < 4; e++) wdense[(size_t)t * 4 + e] = wd[e];
    }
}

// ---------------- aux loss ------------------------------------------------------
__global__ void aux_kernel(const float* __restrict__ probsb, const float* __restrict__ wdense,
                           float* __restrict__ out_aux) {
    int tid = threadIdx.x;
    float sP[4] = {0.f, 0.f, 0.f, 0.f}, sF[4] = {0.f, 0.f, 0.f, 0.f};
    for (int t = tid; t < Tz; t += 256)
        for (int e = 0; e < 4; e++) {
            sP[e] += probsb[(size_t)t * 4 + e];
            sF[e] += (wdense[(size_t)t * 4 + e] > 0.f) ? 1.f : 0.f;
        }
    __shared__ float rP[4][256], rF[4][256];
    for (int e = 0; e < 4; e++) { rP[e][tid] = sP[e]; rF[e][tid] = sF[e]; }
    __syncthreads();
    for (int off = 128; off; off >>= 1) {
        if (tid < off)
            for (int e = 0; e < 4; e++) {
                rP[e][tid] += rP[e][tid + off];
                rF[e][tid] += rF[e][tid + off];
            }
        __syncthreads();
    }
    if (tid == 0) {
        float aux = 0.f;
        for (int e = 0; e < 4; e++)
            aux += (rF[e][0] * (1.0f / Tz)) * (rP[e][0] * (1.0f / Tz));
        *out_aux = (float)Ez * aux;
    }
}

__global__ void final_kernel(const float* __restrict__ x2, const float* __restrict__ ff,
                             float* __restrict__ out) {
    for (int i = blockIdx.x * blockDim.x + threadIdx.x; i < Tz * Dz;
         i += gridDim.x * blockDim.x)
        out[i] = x2[i] + ff[i];
}

// ---------------- launch -------------------------------------------------------
extern "C" void kernel_launch(void* const* d_in, const int* in_sizes, int n_in,
                              void* d_out, int out_size) {
    const float* x      = (const float*)d_in[0];
    const float* n1w    = (const float*)d_in[1];
    const float* n2w    = (const float*)d_in[2];
    const float* wq     = (const float*)d_in[3];
    const float* wk     = (const float*)d_in[4];
    const float* wv     = (const float*)d_in[5];
    const float* wo     = (const float*)d_in[6];
    const float* idx_wq = (const float*)d_in[7];
    const float* idx_wk = (const float*)d_in[8];
    const float* idx_ww = (const float*)d_in[9];
    const float* gate_w = (const float*)d_in[10];
    const float* w1     = (const float*)d_in[11];
    const float* b1     = (const float*)d_in[12];
    const float* w2     = (const float*)d_in[13];
    const float* b2     = (const float*)d_in[14];
    float* out = (float*)d_out;

    float *xn, *q, *k, *v, *qI, *kI, *wI, *sc, *x2, *xn2, *wd, *pr, *ff;
    int *selidx, *selcnt;
    bf16 *xnx, *xn2x, *aox, *hx, *wqx, *wkx, *wvx, *wox, *iwqx, *w1x, *w2x;
    cudaGetSymbolAddress((void**)&xn,  g_xn);
    cudaGetSymbolAddress((void**)&q,   g_q);
    cudaGetSymbolAddress((void**)&k,   g_k);
    cudaGetSymbolAddress((void**)&v,   g_v);
    cudaGetSymbolAddress((void**)&qI,  g_qI);
    cudaGetSymbolAddress((void**)&kI,  g_kI);
    cudaGetSymbolAddress((void**)&wI,  g_wI);
    cudaGetSymbolAddress((void**)&sc,  g_sc);
    cudaGetSymbolAddress((void**)&selidx, g_selidx);
    cudaGetSymbolAddress((void**)&selcnt, g_selcnt);
    cudaGetSymbolAddress((void**)&x2,  g_x2);
    cudaGetSymbolAddress((void**)&xn2, g_xn2);
    cudaGetSymbolAddress((void**)&wd,  g_wd);
    cudaGetSymbolAddress((void**)&pr,  g_pr);
    cudaGetSymbolAddress((void**)&ff,  g_ff);
    cudaGetSymbolAddress((void**)&xnx,  g_xnx);
    cudaGetSymbolAddress((void**)&xn2x, g_xn2x);
    cudaGetSymbolAddress((void**)&aox,  g_aox);
    cudaGetSymbolAddress((void**)&hx,   g_hx);
    cudaGetSymbolAddress((void**)&wqx,  g_wqx);
    cudaGetSymbolAddress((void**)&wkx,  g_wkx);
    cudaGetSymbolAddress((void**)&wvx,  g_wvx);
    cudaGetSymbolAddress((void**)&wox,  g_wox);
    cudaGetSymbolAddress((void**)&iwqx, g_iwqx);
    cudaGetSymbolAddress((void**)&w1x,  g_w1x);
    cudaGetSymbolAddress((void**)&w2x,  g_w2x);

    // ---- weight split-expansion (independent; front-loaded) ----
    convw_kernel<<<2048, 256>>>(wq, wqx, Dz, Dz);
    convw_kernel<<<2048, 256>>>(wk, wkx, Dz, Dz);
    convw_kernel<<<2048, 256>>>(wv, wvx, Dz, Dz);
    convw_kernel<<<2048, 256>>>(wo, wox, Dz, Dz);
    convw_kernel<<<512, 256>>>(idx_wq, iwqx, Dz, HIz * DIz);
    for (int e = 0; e < Ez; e++) {
        convw_kernel<<<4096, 256>>>(w1 + (size_t)e * Dz * DFz,
                                    w1x + (size_t)e * 3 * Dz * DFz, Dz, DFz);
        convw_kernel<<<4096, 256>>>(w2 + (size_t)e * DFz * Dz,
                                    w2x + (size_t)e * 3 * DFz * Dz, DFz, Dz);
    }

    // ---- attention path ----
    rmsnorm2_kernel<<<Tz, 256>>>(x, n1w, xn, xnx);
    hgemm_kernel<0><<<dim3(8, 32), 256>>>(xnx, wqx, q, nullptr, Tz, Dz, 3 * Dz,
                                          nullptr, nullptr, nullptr, 0);
    hgemm_kernel<0><<<dim3(8, 32), 256>>>(xnx, wkx, k, nullptr, Tz, Dz, 3 * Dz,
                                          nullptr, nullptr, nullptr, 0);
    hgemm_kernel<0><<<dim3(8, 32), 256>>>(xnx, wvx, v, nullptr, Tz, Dz, 3 * Dz,
                                          nullptr, nullptr, nullptr, 0);
    hgemm_kernel<0><<<dim3(2, 32), 256>>>(xnx, iwqx, qI, nullptr, Tz, HIz * DIz, 3 * Dz,
                                          nullptr, nullptr, nullptr, 0);
    sgemm_small_kernel<<<dim3(1, 32), 256>>>(xn, idx_wk, kI, Tz, DIz, Dz);
    sgemm_small_kernel<<<dim3(1, 32), 256>>>(xn, idx_ww, wI, Tz, HIz, Dz);

    idxscore_kernel<<<dim3(Sz / 64, Sz / 16, Bz), dim3(16, 16)>>>(qI, kI, wI, sc);
    topk_kernel<<<Tz, 256>>>(sc, selidx, selcnt);
    attn_kernel<<<Tz, 512>>>(q, k, v, selidx, selcnt, aox);
    hgemm_kernel<1><<<dim3(8, 32), 256>>>(aox, wox, x2, nullptr, Tz, Dz, 3 * Dz,
                                          nullptr, x, nullptr, 0);

    // ---- MoE path ----
    rmsnorm2_kernel<<<Tz, 256>>>(x2, n2w, xn2, xn2x);
    gate_kernel<<<Tz, 256>>>(xn2, gate_w, wd, pr);
    for (int e = 0; e < Ez; e++) {
        hgemm_kernel<2><<<dim3(32, 32), 256>>>(xn2x, w1x + (size_t)e * 3 * Dz * DFz,
                                               nullptr, hx, Tz, DFz, 3 * Dz,
                                               b1 + (size_t)e * DFz, nullptr, nullptr, 0);
        if (e == 0)
            hgemm_kernel<4><<<dim3(8, 32), 256>>>(hx, w2x + (size_t)e * 3 * DFz * Dz,
                                                  ff, nullptr, Tz, Dz, 3 * DFz,
                                                  b2 + (size_t)e * Dz, nullptr, wd + e, Ez);
        else
            hgemm_kernel<3><<<dim3(8, 32), 256>>>(hx, w2x + (size_t)e * 3 * DFz * Dz,
                                                  ff, nullptr, Tz, Dz, 3 * DFz,
                                                  b2 + (size_t)e * Dz, nullptr, wd + e, Ez);
    }

    aux_kernel<<<1, 256>>>(pr, wd, out + (out_size - 1));
    final_kernel<<<8192, 256>>>(x2, ff, out);
}

// round 8
// speedup vs baseline: 2.2279x; 1.1389x over previous
#include <cuda_runtime.h>
#include <cuda_bf16.h>
#include <math.h>
#include <stdint.h>

// Problem dims (fixed by setup_inputs)
#define Bz 2
#define Sz 2048
#define Dz 1024
#define Tz 4096           // B*S
#define Hz 16
#define DHz 64
#define HIz 4
#define DIz 64
#define TKz 512
#define Ez 4
#define DFz 4096

typedef __nv_bfloat16 bf16;

// ---------------- scratch (device globals; no allocation allowed) --------------
__device__ float g_xn [Tz*Dz];                 // fp32 norm1(x) (for small gemms)
__device__ float g_q  [Tz*Dz];
__device__ float g_k  [Tz*Dz];
__device__ float g_v  [Tz*Dz];
__device__ float g_qI [Tz*HIz*DIz];
__device__ float g_kI [Tz*DIz];
__device__ float g_wI [Tz*HIz];
__device__ float g_sc [(size_t)Bz*Sz*Sz];
__device__ int   g_selidx[(size_t)Tz*TKz];
__device__ int   g_selcnt[Tz];
__device__ float g_x2 [Tz*Dz];
__device__ float g_xn2[Tz*Dz];
__device__ float g_wd [Tz*Ez];
__device__ float g_pr [Tz*Ez];
__device__ int   g_ecnt[Ez];
__device__ int   g_elist[Ez*Tz];

// bf16 split-expanded operands (activations: [hi|hi|lo] cols; weights: [hi;lo;hi] rows)
__device__ bf16 g_xnx  [(size_t)Tz*3*Dz];
__device__ bf16 g_xn2x [(size_t)Tz*3*Dz];
__device__ bf16 g_aox  [(size_t)Tz*3*Dz];
__device__ bf16 g_hx   [(size_t)Tz*3*DFz];    // gelu output, expanded (gathered rows)
__device__ bf16 g_wqx  [3*Dz*Dz];
__device__ bf16 g_wkx  [3*Dz*Dz];
__device__ bf16 g_wvx  [3*Dz*Dz];
__device__ bf16 g_wox  [3*Dz*Dz];
__device__ bf16 g_iwqx [3*Dz*HIz*DIz];
__device__ bf16 g_w1x  [(size_t)Ez*3*Dz*DFz];
__device__ bf16 g_w2x  [(size_t)Ez*3*DFz*Dz];

// ---------------- helpers ------------------------------------------------------
__device__ __forceinline__ float gelu_f(float x) {
    float x3 = x * x * x;
    return 0.5f * x * (1.0f + tanhf(0.7978845608028654f * (x + 0.044715f * x3)));
}
__device__ __forceinline__ uint32_t smem_u32(const void* p) {
    return (uint32_t)__cvta_generic_to_shared(p);
}
__device__ __forceinline__ void ldsm4(uint32_t& r0, uint32_t& r1, uint32_t& r2,
                                      uint32_t& r3, uint32_t a) {
    asm volatile("ldmatrix.sync.aligned.m8n8.x4.shared.b16 {%0,%1,%2,%3}, [%4];\n"
                 : "=r"(r0), "=r"(r1), "=r"(r2), "=r"(r3) : "r"(a));
}
__device__ __forceinline__ void ldsm4t(uint32_t& r0, uint32_t& r1, uint32_t& r2,
                                       uint32_t& r3, uint32_t a) {
    asm volatile("ldmatrix.sync.aligned.m8n8.x4.trans.shared.b16 {%0,%1,%2,%3}, [%4];\n"
                 : "=r"(r0), "=r"(r1), "=r"(r2), "=r"(r3) : "r"(a));
}
__device__ __forceinline__ void mma_bf16(float c[4], uint32_t a0, uint32_t a1,
                                         uint32_t a2, uint32_t a3,
                                         uint32_t b0, uint32_t b1) {
    asm volatile("mma.sync.aligned.m16n8k16.row.col.f32.bf16.bf16.f32 "
                 "{%0,%1,%2,%3}, {%4,%5,%6,%7}, {%8,%9}, {%0,%1,%2,%3};\n"
                 : "+f"(c[0]), "+f"(c[1]), "+f"(c[2]), "+f"(c[3])
                 : "r"(a0), "r"(a1), "r"(a2), "r"(a3), "r"(b0), "r"(b1));
}
#define CPA16(dst, src) \
    asm volatile("cp.async.cg.shared.global [%0], [%1], 16;\n" :: "r"(dst), "l"(src))
#define CPA_COMMIT() asm volatile("cp.async.commit_group;\n" ::)
#define CPA_WAIT0()  asm volatile("cp.async.wait_group 0;\n" ::)

// ---------------- rmsnorm (fp32 out optional + bf16 split-expanded out) --------
__global__ void rmsnorm2_kernel(const float* __restrict__ x, const float* __restrict__ w,
                                float* __restrict__ y, bf16* __restrict__ yx) {
    int t = blockIdx.x;
    int tid = threadIdx.x;
    const float* xr = x + (size_t)t * Dz;
    float s = 0.f;
    for (int i = tid; i < Dz; i += 256) { float v = xr[i]; s += v * v; }
    __shared__ float red[256];
    red[tid] = s; __syncthreads();
    for (int off = 128; off; off >>= 1) {
        if (tid < off) red[tid] += red[tid + off];
        __syncthreads();
    }
    float inv = rsqrtf(red[0] * (1.0f / Dz) + 1e-6f);
    bf16* yr = yx + (size_t)t * 3 * Dz;
    for (int i = tid; i < Dz; i += 256) {
        float v = xr[i] * inv * w[i];
        if (y) y[(size_t)t * Dz + i] = v;
        bf16 hi = __float2bfloat16(v);
        bf16 lo = __float2bfloat16(v - __bfloat162float(hi));
        yr[i] = hi;
        yr[Dz + i] = hi;
        yr[2 * Dz + i] = lo;
    }
}

// ---------------- weight split-expansion: [K][N] fp32 -> [3K][N] bf16 ----------
// N % 4 == 0. float4 loads, 8B stores x3 streams.
__global__ void convw_kernel(const float* __restrict__ src, bf16* __restrict__ dst,
                             int K, int N) {
    size_t total = ((size_t)K * N) >> 2;
    for (size_t i = blockIdx.x * blockDim.x + threadIdx.x; i < total;
         i += (size_t)gridDim.x * blockDim.x) {
        size_t base = i << 2;
        int k = (int)(base / N), n = (int)(base % N);
        float4 a = ((const float4*)src)[i];
        __align__(8) bf16 hv[4], lv[4];
        hv[0] = __float2bfloat16(a.x); lv[0] = __float2bfloat16(a.x - __bfloat162float(hv[0]));
        hv[1] = __float2bfloat16(a.y); lv[1] = __float2bfloat16(a.y - __bfloat162float(hv[1]));
        hv[2] = __float2bfloat16(a.z); lv[2] = __float2bfloat16(a.z - __bfloat162float(hv[2]));
        hv[3] = __float2bfloat16(a.w); lv[3] = __float2bfloat16(a.w - __bfloat162float(hv[3]));
        uint2 hu = *(uint2*)hv, lu = *(uint2*)lv;
        *(uint2*)&dst[(size_t)k * N + n] = hu;
        *(uint2*)&dst[(size_t)(K + k) * N + n] = lu;
        *(uint2*)&dst[(size_t)(2 * K + k) * N + n] = hu;
    }
}

// ---------------- bf16 tensor-core GEMM ----------------------------------------
// C[M,N] = epi(A[M,K] x B[K,N]) bf16 row-major, K%32==0, N%128==0.
// Optional row gather (arowidx) for A, device row count (dcnt) for early-exit,
// optional scatter list (crowidx) for the output rows.
// EPI 0: Cf = val
// EPI 1: Cf = val + resid
// EPI 2: Cb (bf16, row stride 3N): hi @ c, hi @ N+c, lo @ 2N+c of gelu(val+bias)
// EPI 3: masked scatter-add: Cf[crowidx[r]*N+c] += rowscale[tok*rs]*(val+bias[c])
template<int EPI>
__global__ void __launch_bounds__(256, 2)
hgemm_kernel(const bf16* __restrict__ A, const bf16* __restrict__ B,
             float* __restrict__ Cf, bf16* __restrict__ Cb,
             int M, int N, int K,
             const float* __restrict__ bias, const float* __restrict__ resid,
             const float* __restrict__ rowscale, int rs_stride,
             const int* __restrict__ arowidx, const int* __restrict__ crowidx,
             const int* __restrict__ dcnt) {
    int bm = blockIdx.y * 128, bn = blockIdx.x * 128;
    int cnt = M;
    if (dcnt) {
        cnt = *dcnt;
        int padded = (cnt + 127) & ~127;
        if (bm >= padded) return;
    }
    __shared__ __align__(16) bf16 As[2][128][40];   // pad 8 -> 80B rows
    __shared__ __align__(16) bf16 Bs[2][32][136];   // pad 8 -> 272B rows
    int tid = threadIdx.x;
    int warp = tid >> 5, lane = tid & 31;
    int wm = (warp & 1) * 64, wn = (warp >> 1) * 32;

    int arow = tid >> 2, acol = (tid & 3) * 8;      // A: rows 0..63 (+64)
    int brow = tid >> 4, bcol = (tid & 15) * 8;     // B: rows 0..15 (+16)
    int gr0 = bm + arow, gr1 = bm + arow + 64;
    if (arowidx) { gr0 = arowidx[gr0]; gr1 = arowidx[gr1]; }
    const bf16* Ag0 = A + (size_t)gr0 * K + acol;
    const bf16* Ag1 = A + (size_t)gr1 * K + acol;
    const bf16* Bg0 = B + (size_t)brow * N + bn + bcol;
    const bf16* Bg1 = Bg0 + (size_t)16 * N;

    float c[4][4][4];
#pragma unroll
    for (int mi = 0; mi < 4; mi++)
#pragma unroll
        for (int ni = 0; ni < 4; ni++)
#pragma unroll
            for (int j = 0; j < 4; j++) c[mi][ni][j] = 0.f;

    int KT = K >> 5;
    {
        CPA16(smem_u32(&As[0][arow][acol]), Ag0);
        CPA16(smem_u32(&As[0][arow + 64][acol]), Ag1);
        CPA16(smem_u32(&Bs[0][brow][bcol]), Bg0);
        CPA16(smem_u32(&Bs[0][brow + 16][bcol]), Bg1);
        CPA_COMMIT();
    }
    int buf = 0;
    for (int kt = 0; kt < KT; kt++) {
        CPA_WAIT0();
        __syncthreads();
        if (kt + 1 < KT) {
            int nb = buf ^ 1;
            CPA16(smem_u32(&As[nb][arow][acol]), Ag0 + (kt + 1) * 32);
            CPA16(smem_u32(&As[nb][arow + 64][acol]), Ag1 + (kt + 1) * 32);
            CPA16(smem_u32(&Bs[nb][brow][bcol]), Bg0 + (size_t)(kt + 1) * 32 * N);
            CPA16(smem_u32(&Bs[nb][brow + 16][bcol]), Bg1 + (size_t)(kt + 1) * 32 * N);
            CPA_COMMIT();
        }
#pragma unroll
        for (int kk = 0; kk < 32; kk += 16) {
            uint32_t a[4][4], b[4][2];
#pragma unroll
            for (int mi = 0; mi < 4; mi++) {
                uint32_t addr = smem_u32(
                    &As[buf][wm + mi * 16 + (lane & 15)][kk + ((lane >> 4) << 3)]);
                ldsm4(a[mi][0], a[mi][1], a[mi][2], a[mi][3], addr);
            }
#pragma unroll
            for (int nj = 0; nj < 2; nj++) {
                uint32_t addr = smem_u32(
                    &Bs[buf][kk + (lane & 15)][wn + nj * 16 + ((lane >> 4) << 3)]);
                ldsm4t(b[2 * nj][0], b[2 * nj][1], b[2 * nj + 1][0], b[2 * nj + 1][1], addr);
            }
#pragma unroll
            for (int mi = 0; mi < 4; mi++)
#pragma unroll
                for (int ni = 0; ni < 4; ni++)
                    mma_bf16(c[mi][ni], a[mi][0], a[mi][1], a[mi][2], a[mi][3],
                             b[ni][0], b[ni][1]);
        }
        buf ^= 1;
    }

#pragma unroll
    for (int mi = 0; mi < 4; mi++) {
#pragma unroll
        for (int rr = 0; rr < 2; rr++) {
            int r = bm + wm + mi * 16 + (lane >> 2) + rr * 8;
            if (EPI == 3) {
                if (r < cnt) {
                    int tok = crowidx[r];
                    float rsc = rowscale[(size_t)tok * rs_stride];
#pragma unroll
                    for (int ni = 0; ni < 4; ni++)
#pragma unroll
                        for (int cc = 0; cc < 2; cc++) {
                            int col = bn + wn + ni * 8 + (lane & 3) * 2 + cc;
                            float val = c[mi][ni][rr * 2 + cc];
                            Cf[(size_t)tok * N + col] += rsc * (val + bias[col]);
                        }
                }
            } else {
#pragma unroll
                for (int ni = 0; ni < 4; ni++)
#pragma unroll
                    for (int cc = 0; cc < 2; cc++) {
                        int col = bn + wn + ni * 8 + (lane & 3) * 2 + cc;
                        float val = c[mi][ni][rr * 2 + cc];
                        if (EPI == 0) {
                            Cf[(size_t)r * N + col] = val;
                        } else if (EPI == 1) {
                            Cf[(size_t)r * N + col] = val + resid[(size_t)r * N + col];
                        } else if (EPI == 2) {
                            float g = gelu_f(val + bias[col]);
                            bf16 hi = __float2bfloat16(g);
                            bf16 lo = __float2bfloat16(g - __bfloat162float(hi));
                            size_t base = (size_t)r * 3 * N;
                            Cb[base + col] = hi;
                            Cb[base + N + col] = hi;
                            Cb[base + 2 * N + col] = lo;
                        }
                    }
            }
        }
    }
}

// ---------------- small fp32 GEMM (kI: N=64, wI: N=4) --------------------------
__global__ void __launch_bounds__(256, 2)
sgemm_small_kernel(const float* __restrict__ A, const float* __restrict__ B,
                   float* __restrict__ C, int M, int N, int K) {
    const int BM = 128, BN = 128, BK = 8, TM = 8, TN = 8;
    __shared__ float As[BK][BM];
    __shared__ float Bs[BK][BN];
    int tid = threadIdx.x;
    int bm = blockIdx.y * BM;
    int bn = blockIdx.x * BN;
    int trow = (tid / 16) * TM;
    int tcol = (tid % 16) * TN;
    float acc[TM][TN];
#pragma unroll
    for (int i = 0; i < TM; i++)
#pragma unroll
        for (int j = 0; j < TN; j++) acc[i][j] = 0.f;
    int arow = tid >> 1, acol = (tid & 1) * 4;
    int brow = tid >> 5, bcol = (tid & 31) * 4;
    const float* Aptr = A + (size_t)(bm + arow) * K;
    for (int k0 = 0; k0 < K; k0 += BK) {
        float4 av = *(const float4*)(Aptr + k0 + acol);
        As[acol + 0][arow] = av.x; As[acol + 1][arow] = av.y;
        As[acol + 2][arow] = av.z; As[acol + 3][arow] = av.w;
        int bc = bn + bcol;
#pragma unroll
        for (int j = 0; j < 4; j++)
            Bs[brow][bcol + j] = (bc + j < N) ? B[(size_t)(k0 + brow) * N + bc + j] : 0.f;
        __syncthreads();
#pragma unroll
        for (int kk = 0; kk < BK; kk++) {
            float ar[TM], br[TN];
#pragma unroll
            for (int i = 0; i < TM; i++) ar[i] = As[kk][trow + i];
#pragma unroll
            for (int j = 0; j < TN; j++) br[j] = Bs[kk][tcol + j];
#pragma unroll
            for (int i = 0; i < TM; i++)
#pragma unroll
                for (int j = 0; j < TN; j++) acc[i][j] += ar[i] * br[j];
        }
        __syncthreads();
    }
#pragma unroll
    for (int i = 0; i < TM; i++) {
        int r = bm + trow + i;
#pragma unroll
        for (int j = 0; j < TN; j++) {
            int cidx = bn + tcol + j;
            if (cidx < N) C[(size_t)r * N + cidx] = acc[i][j];
        }
    }
}

// ---------------- indexer scores ------------------------------------------------
__global__ void idxscore_kernel(const float* __restrict__ qI, const float* __restrict__ kI,
                                const float* __restrict__ wI, float* __restrict__ sc) {
    int b  = blockIdx.z;
    int t0 = blockIdx.y * 16;
    int s0 = blockIdx.x * 64;
    if (s0 > t0 + 15) return;
    __shared__ float qIs[16][257];
    __shared__ float kIs[64][65];
    __shared__ float wIs[16][4];
    int tx = threadIdx.x, ty = threadIdx.y;
    int tid = ty * 16 + tx;
    for (int idx = tid; idx < 16 * 256; idx += 256) {
        int r = idx >> 8, c = idx & 255;
        qIs[r][c] = qI[((size_t)(b * Sz + t0 + r)) * 256 + c];
    }
    for (int idx = tid; idx < 64 * 64; idx += 256) {
        int r = idx >> 6, c = idx & 63;
        kIs[r][c] = kI[((size_t)(b * Sz + s0 + r)) * 64 + c];
    }
    if (tid < 64) wIs[tid >> 2][tid & 3] = wI[((size_t)(b * Sz + (tid >> 2) + t0)) * 4 + (tid & 3)];
    __syncthreads();

    float acc4[4] = {0.f, 0.f, 0.f, 0.f};
#pragma unroll
    for (int h = 0; h < 4; h++) {
        float dot[4] = {0.f, 0.f, 0.f, 0.f};
#pragma unroll
        for (int d = 0; d < 64; d++) {
            float qv = qIs[ty][h * 64 + d];
            dot[0] += qv * kIs[tx +  0][d];
            dot[1] += qv * kIs[tx + 16][d];
            dot[2] += qv * kIs[tx + 32][d];
            dot[3] += qv * kIs[tx + 48][d];
        }
        float wv = wIs[ty][h];
#pragma unroll
        for (int j = 0; j < 4; j++) acc4[j] += wv * fmaxf(dot[j], 0.f);
    }
    int t = t0 + ty;
#pragma unroll
    for (int j = 0; j < 4; j++) {
        int s = s0 + tx + 16 * j;
        if (s <= t) sc[((size_t)(b * Sz + t)) * Sz + s] = acc4[j];
    }
}

// ---------------- top-k (512) per (b,t), jax tie-break --------------------------
__global__ void topk_kernel(const float* __restrict__ sc, int* __restrict__ selidx,
                            int* __restrict__ selcnt) {
    int bt = blockIdx.x;
    int t = bt & (Sz - 1);
    int n = t + 1;
    int tid = threadIdx.x;
    int* outp = selidx + (size_t)bt * TKz;
    if (n <= TKz) {
        for (int i = tid; i < n; i += 256) outp[i] = i;
        if (tid == 0) selcnt[bt] = n;
        return;
    }
    const float* row = sc + (size_t)bt * Sz;
    __shared__ unsigned keys[Sz];
    for (int i = tid; i < n; i += 256) {
        unsigned u = __float_as_uint(row[i]);
        keys[i] = (u & 0x80000000u) ? ~u : (u | 0x80000000u);
    }
    __shared__ int cnt_s;
    unsigned p = 0;
    for (int bit = 31; bit >= 0; bit--) {
        unsigned q = p | (1u << bit);
        if (tid == 0) cnt_s = 0;
        __syncthreads();
        int c = 0;
        for (int i = tid; i < n; i += 256) c += (keys[i] >= q);
        for (int off = 16; off; off >>= 1) c += __shfl_xor_sync(0xffffffffu, c, off);
        if ((tid & 31) == 0) atomicAdd(&cnt_s, c);
        __syncthreads();
        int cv = cnt_s;
        __syncthreads();
        if (cv >= TKz) p = q;
    }
    __shared__ int pos;
    if (tid == 0) pos = 0;
    __syncthreads();
    for (int i = tid; i < n; i += 256)
        if (keys[i] > p) { int j = atomicAdd(&pos, 1); outp[j] = i; }
    __syncthreads();
    if (tid == 0) {
        int j = pos;
        for (int i = 0; i < n && j < TKz; i++)
            if (keys[i] == p) outp[j++] = i;
        selcnt[bt] = TKz;
    }
}

// ---------------- sparse attention: writes split-expanded bf16 ao' --------------
__global__ void __launch_bounds__(512)
attn_kernel(const float* __restrict__ q, const float* __restrict__ k,
            const float* __restrict__ v, const int* __restrict__ selidx,
            const int* __restrict__ selcnt, bf16* __restrict__ aox) {
    int bt = blockIdx.x;
    int b = bt >> 11;
    int tid = threadIdx.x;
    __shared__ float qs[Hz * DHz];
    __shared__ int sels[TKz];
    int n = selcnt[bt];
    for (int i = tid; i < Dz; i += 512) qs[i] = q[(size_t)bt * Dz + i];
    for (int i = tid; i < n; i += 512) sels[i] = selidx[(size_t)bt * TKz + i];
    __syncthreads();
    int h = tid >> 5, lane = tid & 31;
    float m = -3.0e38f, l = 0.f, o0 = 0.f, o1 = 0.f;
    float q0 = qs[h * 64 + lane], q1 = qs[h * 64 + 32 + lane];
    for (int i = 0; i < n; i++) {
        int s = sels[i];
        const float* kp = k + ((size_t)(b * Sz + s)) * Dz + h * 64;
        float part = q0 * kp[lane] + q1 * kp[32 + lane];
#pragma unroll
        for (int off = 16; off; off >>= 1) part += __shfl_xor_sync(0xffffffffu, part, off);
        float score = part * 0.125f;
        float mn = fmaxf(m, score);
        float scale = __expf(m - mn);
        float pw = __expf(score - mn);
        const float* vp = v + ((size_t)(b * Sz + s)) * Dz + h * 64;
        o0 = o0 * scale + pw * vp[lane];
        o1 = o1 * scale + pw * vp[32 + lane];
        l = l * scale + pw;
        m = mn;
    }
    float inv = 1.0f / l;
    o0 *= inv; o1 *= inv;
    size_t base = (size_t)bt * 3 * Dz;
    int c0 = h * 64 + lane, c1 = c0 + 32;
    bf16 h0 = __float2bfloat16(o0);
    bf16 l0 = __float2bfloat16(o0 - __bfloat162float(h0));
    bf16 h1 = __float2bfloat16(o1);
    bf16 l1 = __float2bfloat16(o1 - __bfloat162float(h1));
    aox[base + c0] = h0;           aox[base + c1] = h1;
    aox[base + Dz + c0] = h0;      aox[base + Dz + c1] = h1;
    aox[base + 2 * Dz + c0] = l0;  aox[base + 2 * Dz + c1] = l1;
}

// ---------------- gate: softmax(4) + top-2 + combine weights -------------------
__global__ void gate_kernel(const float* __restrict__ xn2, const float* __restrict__ gw,
                            float* __restrict__ wdense, float* __restrict__ probsb) {
    int t = blockIdx.x;
    int tid = threadIdx.x;
    const float* xr = xn2 + (size_t)t * Dz;
    float le[4] = {0.f, 0.f, 0.f, 0.f};
    for (int d = tid; d < Dz; d += 256) {
        float xv = xr[d];
        const float* g = gw + (size_t)d * 4;
        le[0] += xv * g[0]; le[1] += xv * g[1];
        le[2] += xv * g[2]; le[3] += xv * g[3];
    }
    __shared__ float red[4][256];
    for (int e = 0; e < 4; e++) red[e][tid] = le[e];
    __syncthreads();
    for (int off = 128; off; off >>= 1) {
        if (tid < off)
            for (int e = 0; e < 4; e++) red[e][tid] += red[e][tid + off];
        __syncthreads();
    }
    if (tid == 0) {
        float lg[4], pr[4];
        float mx = -3.0e38f;
        for (int e = 0; e < 4; e++) { lg[e] = red[e][0]; mx = fmaxf(mx, lg[e]); }
        float sum = 0.f;
        for (int e = 0; e < 4; e++) { pr[e] = expf(lg[e] - mx); sum += pr[e]; }
        float inv = 1.0f / sum;
        for (int e = 0; e < 4; e++) { pr[e] *= inv; probsb[(size_t)t * 4 + e] = pr[e]; }
        int i1 = 0;
        for (int e = 1; e < 4; e++) if (pr[e] > pr[i1]) i1 = e;
        int i2 = -1; float b2v = -1.f;
        for (int e = 0; e < 4; e++) if (e != i1 && pr[e] > b2v) { b2v = pr[e]; i2 = e; }
        float wsum = pr[i1] + pr[i2];
        float wd[4] = {0.f, 0.f, 0.f, 0.f};
        wd[i1] = pr[i1] / wsum;
        wd[i2] = pr[i2] / wsum;
        for (int e = 0; e < 4; e++) wdense[(size_t)t * 4 + e] = wd[e];
    }
}

// ---------------- routing: compact token lists per expert ----------------------
__global__ void route_zero_kernel(int* __restrict__ ecnt) {
    if (threadIdx.x < Ez) ecnt[threadIdx.x] = 0;
}
__global__ void route_kernel(const float* __restrict__ wd, int* __restrict__ ecnt,
                             int* __restrict__ elist) {
    int t = blockIdx.x * blockDim.x + threadIdx.x;
    if (t < Tz) {
#pragma unroll
        for (int e = 0; e < Ez; e++)
            if (wd[(size_t)t * Ez + e] > 0.f) {
                int p = atomicAdd(&ecnt[e], 1);
                elist[e * Tz + p] = t;
            }
    }
}
__global__ void route_pad_kernel(const int* __restrict__ ecnt, int* __restrict__ elist) {
    int e = blockIdx.x;
    int cnt = ecnt[e];
    int padded = (cnt + 127) & ~127;
    for (int i = cnt + threadIdx.x; i < padded; i += blockDim.x) elist[e * Tz + i] = 0;
}

// ---------------- aux loss ------------------------------------------------------
__global__ void aux_kernel(const float* __restrict__ probsb, const float* __restrict__ wdense,
                           float* __restrict__ out_aux) {
    int tid = threadIdx.x;
    float sP[4] = {0.f, 0.f, 0.f, 0.f}, sF[4] = {0.f, 0.f, 0.f, 0.f};
    for (int t = tid; t < Tz; t += 256)
        for (int e = 0; e < 4; e++) {
            sP[e] += probsb[(size_t)t * 4 + e];
            sF[e] += (wdense[(size_t)t * 4 + e] > 0.f) ? 1.f : 0.f;
        }
    __shared__ float rP[4][256], rF[4][256];
    for (int e = 0; e < 4; e++) { rP[e][tid] = sP[e]; rF[e][tid] = sF[e]; }
    __syncthreads();
    for (int off = 128; off; off >>= 1) {
        if (tid < off)
            for (int e = 0; e < 4; e++) {
                rP[e][tid] += rP[e][tid + off];
                rF[e][tid] += rF[e][tid + off];
            }
        __syncthreads();
    }
    if (tid == 0) {
        float aux = 0.f;
        for (int e = 0; e < 4; e++)
            aux += (rF[e][0] * (1.0f / Tz)) * (rP[e][0] * (1.0f / Tz));
        *out_aux = (float)Ez * aux;
    }
}

// ---------------- out init: out = x2 (experts scatter-add on top) --------------
__global__ void initout_kernel(const float* __restrict__ x2, float* __restrict__ out) {
    for (int i = blockIdx.x * blockDim.x + threadIdx.x; i < Tz * Dz;
         i += gridDim.x * blockDim.x)
        out[i] = x2[i];
}

// ---------------- launch -------------------------------------------------------
extern "C" void kernel_launch(void* const* d_in, const int* in_sizes, int n_in,
                              void* d_out, int out_size) {
    const float* x      = (const float*)d_in[0];
    const float* n1w    = (const float*)d_in[1];
    const float* n2w    = (const float*)d_in[2];
    const float* wq     = (const float*)d_in[3];
    const float* wk     = (const float*)d_in[4];
    const float* wv     = (const float*)d_in[5];
    const float* wo     = (const float*)d_in[6];
    const float* idx_wq = (const float*)d_in[7];
    const float* idx_wk = (const float*)d_in[8];
    const float* idx_ww = (const float*)d_in[9];
    const float* gate_w = (const float*)d_in[10];
    const float* w1     = (const float*)d_in[11];
    const float* b1     = (const float*)d_in[12];
    const float* w2     = (const float*)d_in[13];
    const float* b2     = (const float*)d_in[14];
    float* out = (float*)d_out;

    float *xn, *q, *k, *v, *qI, *kI, *wI, *sc, *x2, *xn2, *wd, *pr;
    int *selidx, *selcnt, *ecnt, *elist;
    bf16 *xnx, *xn2x, *aox, *hx, *wqx, *wkx, *wvx, *wox, *iwqx, *w1x, *w2x;
    cudaGetSymbolAddress((void**)&xn,  g_xn);
    cudaGetSymbolAddress((void**)&q,   g_q);
    cudaGetSymbolAddress((void**)&k,   g_k);
    cudaGetSymbolAddress((void**)&v,   g_v);
    cudaGetSymbolAddress((void**)&qI,  g_qI);
    cudaGetSymbolAddress((void**)&kI,  g_kI);
    cudaGetSymbolAddress((void**)&wI,  g_wI);
    cudaGetSymbolAddress((void**)&sc,  g_sc);
    cudaGetSymbolAddress((void**)&selidx, g_selidx);
    cudaGetSymbolAddress((void**)&selcnt, g_selcnt);
    cudaGetSymbolAddress((void**)&x2,  g_x2);
    cudaGetSymbolAddress((void**)&xn2, g_xn2);
    cudaGetSymbolAddress((void**)&wd,  g_wd);
    cudaGetSymbolAddress((void**)&pr,  g_pr);
    cudaGetSymbolAddress((void**)&ecnt,  g_ecnt);
    cudaGetSymbolAddress((void**)&elist, g_elist);
    cudaGetSymbolAddress((void**)&xnx,  g_xnx);
    cudaGetSymbolAddress((void**)&xn2x, g_xn2x);
    cudaGetSymbolAddress((void**)&aox,  g_aox);
    cudaGetSymbolAddress((void**)&hx,   g_hx);
    cudaGetSymbolAddress((void**)&wqx,  g_wqx);
    cudaGetSymbolAddress((void**)&wkx,  g_wkx);
    cudaGetSymbolAddress((void**)&wvx,  g_wvx);
    cudaGetSymbolAddress((void**)&wox,  g_wox);
    cudaGetSymbolAddress((void**)&iwqx, g_iwqx);
    cudaGetSymbolAddress((void**)&w1x,  g_w1x);
    cudaGetSymbolAddress((void**)&w2x,  g_w2x);

    // ---- weight split-expansion ----
    convw_kernel<<<1024, 256>>>(wq, wqx, Dz, Dz);
    convw_kernel<<<1024, 256>>>(wk, wkx, Dz, Dz);
    convw_kernel<<<1024, 256>>>(wv, wvx, Dz, Dz);
    convw_kernel<<<1024, 256>>>(wo, wox, Dz, Dz);
    convw_kernel<<<256, 256>>>(idx_wq, iwqx, Dz, HIz * DIz);
    for (int e = 0; e < Ez; e++) {
        convw_kernel<<<2048, 256>>>(w1 + (size_t)e * Dz * DFz,
                                    w1x + (size_t)e * 3 * Dz * DFz, Dz, DFz);
        convw_kernel<<<2048, 256>>>(w2 + (size_t)e * DFz * Dz,
                                    w2x + (size_t)e * 3 * DFz * Dz, DFz, Dz);
    }

    // ---- attention path ----
    rmsnorm2_kernel<<<Tz, 256>>>(x, n1w, xn, xnx);
    hgemm_kernel<0><<<dim3(8, 32), 256>>>(xnx, wqx, q, nullptr, Tz, Dz, 3 * Dz,
                                          nullptr, nullptr, nullptr, 0,
                                          nullptr, nullptr, nullptr);
    hgemm_kernel<0><<<dim3(8, 32), 256>>>(xnx, wkx, k, nullptr, Tz, Dz, 3 * Dz,
                                          nullptr, nullptr, nullptr, 0,
                                          nullptr, nullptr, nullptr);
    hgemm_kernel<0><<<dim3(8, 32), 256>>>(xnx, wvx, v, nullptr, Tz, Dz, 3 * Dz,
                                          nullptr, nullptr, nullptr, 0,
                                          nullptr, nullptr, nullptr);
    hgemm_kernel<0><<<dim3(2, 32), 256>>>(xnx, iwqx, qI, nullptr, Tz, HIz * DIz, 3 * Dz,
                                          nullptr, nullptr, nullptr, 0,
                                          nullptr, nullptr, nullptr);
    sgemm_small_kernel<<<dim3(1, 32), 256>>>(xn, idx_wk, kI, Tz, DIz, Dz);
    sgemm_small_kernel<<<dim3(1, 32), 256>>>(xn, idx_ww, wI, Tz, HIz, Dz);

    idxscore_kernel<<<dim3(Sz / 64, Sz / 16, Bz), dim3(16, 16)>>>(qI, kI, wI, sc);
    topk_kernel<<<Tz, 256>>>(sc, selidx, selcnt);
    attn_kernel<<<Tz, 512>>>(q, k, v, selidx, selcnt, aox);
    hgemm_kernel<1><<<dim3(8, 32), 256>>>(aox, wox, x2, nullptr, Tz, Dz, 3 * Dz,
                                          nullptr, x, nullptr, 0,
                                          nullptr, nullptr, nullptr);

    // ---- MoE path (routed: only selected tokens per expert) ----
    rmsnorm2_kernel<<<Tz, 256>>>(x2, n2w, xn2, xn2x);
    gate_kernel<<<Tz, 256>>>(xn2, gate_w, wd, pr);
    route_zero_kernel<<<1, 32>>>(ecnt);
    route_kernel<<<Tz / 256, 256>>>(wd, ecnt, elist);
    route_pad_kernel<<<Ez, 128>>>(ecnt, elist);
    initout_kernel<<<8192, 256>>>(x2, out);
    for (int e = 0; e < Ez; e++) {
        hgemm_kernel<2><<<dim3(32, 32), 256>>>(xn2x, w1x + (size_t)e * 3 * Dz * DFz,
                                               nullptr, hx, Tz, DFz, 3 * Dz,
                                               b1 + (size_t)e * DFz, nullptr, nullptr, 0,
                                               elist + e * Tz, nullptr, ecnt + e);
        hgemm_kernel<3><<<dim3(8, 32), 256>>>(hx, w2x + (size_t)e * 3 * DFz * Dz,
                                              out, nullptr, Tz, Dz, 3 * DFz,
                                              b2 + (size_t)e * Dz, nullptr, wd + e, Ez,
                                              nullptr, elist + e * Tz, ecnt + e);
    }

    aux_kernel<<<1, 256>>>(pr, wd, out + (out_size - 1));
}

// round 9
// speedup vs baseline: 2.6456x; 1.1875x over previous
#include <cuda_runtime.h>
#include <cuda_bf16.h>
#include <math.h>
#include <stdint.h>

// Problem dims (fixed by setup_inputs)
#define Bz 2
#define Sz 2048
#define Dz 1024
#define Tz 4096           // B*S
#define Hz 16
#define DHz 64
#define HIz 4
#define DIz 64
#define TKz 512
#define Ez 4
#define DFz 4096

typedef __nv_bfloat16 bf16;

// ---------------- scratch (device globals; no allocation allowed) --------------
__device__ float g_xn [Tz*Dz];                 // fp32 norm1(x) (for small gemms)
__device__ float g_q  [Tz*Dz];
__device__ float g_qI [Tz*HIz*DIz];
__device__ float g_kI [Tz*DIz];
__device__ float g_wI [Tz*HIz];
__device__ float g_sc [(size_t)Bz*Sz*Sz];
__device__ int   g_selidx[(size_t)Tz*TKz];
__device__ int   g_selcnt[Tz];
__device__ float g_x2 [Tz*Dz];
__device__ float g_xn2[Tz*Dz];
__device__ float g_wd [Tz*Ez];
__device__ float g_pr [Tz*Ez];
__device__ int   g_ecnt[Ez];
__device__ int   g_elist[Ez*Tz];
__device__ float g_ffe[(size_t)Ez*Tz*Dz];      // per-expert FFN outputs (scatter)

// bf16 operands
__device__ bf16 g_kvb  [(size_t)2*Tz*Dz];      // K,V plain bf16 for attention
__device__ bf16 g_xnx  [(size_t)Tz*3*Dz];
__device__ bf16 g_xn2x [(size_t)Tz*3*Dz];
__device__ bf16 g_aox  [(size_t)Tz*3*Dz];
__device__ bf16 g_hx   [(size_t)Ez*Tz*3*DFz]; // gelu out, expanded, per expert
__device__ bf16 g_wqkvx[(size_t)3*3*Dz*Dz];   // wq|wk|wv split-expanded
__device__ bf16 g_wox  [3*Dz*Dz];
__device__ bf16 g_iwqx [3*Dz*HIz*DIz];
__device__ bf16 g_w1x  [(size_t)Ez*3*Dz*DFz];
__device__ bf16 g_w2x  [(size_t)Ez*3*DFz*Dz];

// ---------------- helpers ------------------------------------------------------
__device__ __forceinline__ float gelu_f(float x) {
    float x3 = x * x * x;
    return 0.5f * x * (1.0f + tanhf(0.7978845608028654f * (x + 0.044715f * x3)));
}
__device__ __forceinline__ uint32_t smem_u32(const void* p) {
    return (uint32_t)__cvta_generic_to_shared(p);
}
__device__ __forceinline__ void ldsm4(uint32_t& r0, uint32_t& r1, uint32_t& r2,
                                      uint32_t& r3, uint32_t a) {
    asm volatile("ldmatrix.sync.aligned.m8n8.x4.shared.b16 {%0,%1,%2,%3}, [%4];\n"
                 : "=r"(r0), "=r"(r1), "=r"(r2), "=r"(r3) : "r"(a));
}
__device__ __forceinline__ void ldsm4t(uint32_t& r0, uint32_t& r1, uint32_t& r2,
                                       uint32_t& r3, uint32_t a) {
    asm volatile("ldmatrix.sync.aligned.m8n8.x4.trans.shared.b16 {%0,%1,%2,%3}, [%4];\n"
                 : "=r"(r0), "=r"(r1), "=r"(r2), "=r"(r3) : "r"(a));
}
__device__ __forceinline__ void mma_bf16(float c[4], uint32_t a0, uint32_t a1,
                                         uint32_t a2, uint32_t a3,
                                         uint32_t b0, uint32_t b1) {
    asm volatile("mma.sync.aligned.m16n8k16.row.col.f32.bf16.bf16.f32 "
                 "{%0,%1,%2,%3}, {%4,%5,%6,%7}, {%8,%9}, {%0,%1,%2,%3};\n"
                 : "+f"(c[0]), "+f"(c[1]), "+f"(c[2]), "+f"(c[3])
                 : "r"(a0), "r"(a1), "r"(a2), "r"(a3), "r"(b0), "r"(b1));
}
#define CPA16(dst, src) \
    asm volatile("cp.async.cg.shared.global [%0], [%1], 16;\n" :: "r"(dst), "l"(src))
#define CPA_COMMIT() asm volatile("cp.async.commit_group;\n" ::)
#define CPA_WAIT0()  asm volatile("cp.async.wait_group 0;\n" ::)

// ---------------- rmsnorm (fp32 out optional + bf16 split-expanded out) --------
__global__ void rmsnorm2_kernel(const float* __restrict__ x, const float* __restrict__ w,
                                float* __restrict__ y, bf16* __restrict__ yx) {
    int t = blockIdx.x;
    int tid = threadIdx.x;
    const float* xr = x + (size_t)t * Dz;
    float s = 0.f;
    for (int i = tid; i < Dz; i += 256) { float v = xr[i]; s += v * v; }
    __shared__ float red[256];
    red[tid] = s; __syncthreads();
    for (int off = 128; off; off >>= 1) {
        if (tid < off) red[tid] += red[tid + off];
        __syncthreads();
    }
    float inv = rsqrtf(red[0] * (1.0f / Dz) + 1e-6f);
    bf16* yr = yx + (size_t)t * 3 * Dz;
    for (int i = tid; i < Dz; i += 256) {
        float v = xr[i] * inv * w[i];
        if (y) y[(size_t)t * Dz + i] = v;
        bf16 hi = __float2bfloat16(v);
        bf16 lo = __float2bfloat16(v - __bfloat162float(hi));
        yr[i] = hi;
        yr[Dz + i] = hi;
        yr[2 * Dz + i] = lo;
    }
}

// ---------------- weight split-expansion: [K][N] fp32 -> [3K][N] bf16 ----------
__global__ void convw_kernel(const float* __restrict__ src, bf16* __restrict__ dst,
                             int K, int N) {
    size_t total = ((size_t)K * N) >> 2;
    for (size_t i = blockIdx.x * blockDim.x + threadIdx.x; i < total;
         i += (size_t)gridDim.x * blockDim.x) {
        size_t base = i << 2;
        int k = (int)(base / N), n = (int)(base % N);
        float4 a = ((const float4*)src)[i];
        __align__(8) bf16 hv[4], lv[4];
        hv[0] = __float2bfloat16(a.x); lv[0] = __float2bfloat16(a.x - __bfloat162float(hv[0]));
        hv[1] = __float2bfloat16(a.y); lv[1] = __float2bfloat16(a.y - __bfloat162float(hv[1]));
        hv[2] = __float2bfloat16(a.z); lv[2] = __float2bfloat16(a.z - __bfloat162float(hv[2]));
        hv[3] = __float2bfloat16(a.w); lv[3] = __float2bfloat16(a.w - __bfloat162float(hv[3]));
        uint2 hu = *(uint2*)hv, lu = *(uint2*)lv;
        *(uint2*)&dst[(size_t)k * N + n] = hu;
        *(uint2*)&dst[(size_t)(K + k) * N + n] = lu;
        *(uint2*)&dst[(size_t)(2 * K + k) * N + n] = hu;
    }
}

// ---------------- bf16 tensor-core GEMM (z-batched) -----------------------------
// EPI 0: Cf = val
// EPI 1: Cf = val + resid
// EPI 2: gather A rows via elist[z]; Cb+z*c_zs gets split-bf16 gelu(val+bias)
// EPI 3: scatter by token: (Cf+z*c_zs)[tok*N+c] = wdv[tok*Ez+z]*(val+bias[c])
// EPI 5: QKV: z==0 -> Cf fp32; z>=1 -> (Cb+(z-1)*c_zs) plain bf16
template<int EPI>
__global__ void __launch_bounds__(256, 2)
hgemm_kernel(const bf16* __restrict__ A, const bf16* __restrict__ B,
             float* __restrict__ Cf, bf16* __restrict__ Cb,
             int M, int N, int K,
             const float* __restrict__ bias, const float* __restrict__ resid,
             const float* __restrict__ wdv,
             const int* __restrict__ elist, const int* __restrict__ ecnt,
             size_t a_zs, size_t b_zs, size_t c_zs, int bias_zs) {
    int z = blockIdx.z;
    int bm = blockIdx.y * 128, bn = blockIdx.x * 128;
    int cnt = M;
    if (ecnt) {
        cnt = ecnt[z];
        int padded = (cnt + 127) & ~127;
        if (bm >= padded) return;
    }
    A += (size_t)z * a_zs;
    B += (size_t)z * b_zs;
    if (bias) bias += (size_t)z * bias_zs;
    const int* lst = elist ? elist + (size_t)z * Tz : nullptr;

    __shared__ __align__(16) bf16 As[2][128][40];
    __shared__ __align__(16) bf16 Bs[2][32][136];
    int tid = threadIdx.x;
    int warp = tid >> 5, lane = tid & 31;
    int wm = (warp & 1) * 64, wn = (warp >> 1) * 32;

    int arow = tid >> 2, acol = (tid & 3) * 8;
    int brow = tid >> 4, bcol = (tid & 15) * 8;
    int gr0 = bm + arow, gr1 = bm + arow + 64;
    if (EPI == 2) { gr0 = lst[gr0]; gr1 = lst[gr1]; }
    const bf16* Ag0 = A + (size_t)gr0 * K + acol;
    const bf16* Ag1 = A + (size_t)gr1 * K + acol;
    const bf16* Bg0 = B + (size_t)brow * N + bn + bcol;
    const bf16* Bg1 = Bg0 + (size_t)16 * N;

    float c[4][4][4];
#pragma unroll
    for (int mi = 0; mi < 4; mi++)
#pragma unroll
        for (int ni = 0; ni < 4; ni++)
#pragma unroll
            for (int j = 0; j < 4; j++) c[mi][ni][j] = 0.f;

    int KT = K >> 5;
    {
        CPA16(smem_u32(&As[0][arow][acol]), Ag0);
        CPA16(smem_u32(&As[0][arow + 64][acol]), Ag1);
        CPA16(smem_u32(&Bs[0][brow][bcol]), Bg0);
        CPA16(smem_u32(&Bs[0][brow + 16][bcol]), Bg1);
        CPA_COMMIT();
    }
    int buf = 0;
    for (int kt = 0; kt < KT; kt++) {
        CPA_WAIT0();
        __syncthreads();
        if (kt + 1 < KT) {
            int nb = buf ^ 1;
            CPA16(smem_u32(&As[nb][arow][acol]), Ag0 + (kt + 1) * 32);
            CPA16(smem_u32(&As[nb][arow + 64][acol]), Ag1 + (kt + 1) * 32);
            CPA16(smem_u32(&Bs[nb][brow][bcol]), Bg0 + (size_t)(kt + 1) * 32 * N);
            CPA16(smem_u32(&Bs[nb][brow + 16][bcol]), Bg1 + (size_t)(kt + 1) * 32 * N);
            CPA_COMMIT();
        }
#pragma unroll
        for (int kk = 0; kk < 32; kk += 16) {
            uint32_t a[4][4], b[4][2];
#pragma unroll
            for (int mi = 0; mi < 4; mi++) {
                uint32_t addr = smem_u32(
                    &As[buf][wm + mi * 16 + (lane & 15)][kk + ((lane >> 4) << 3)]);
                ldsm4(a[mi][0], a[mi][1], a[mi][2], a[mi][3], addr);
            }
#pragma unroll
            for (int nj = 0; nj < 2; nj++) {
                uint32_t addr = smem_u32(
                    &Bs[buf][kk + (lane & 15)][wn + nj * 16 + ((lane >> 4) << 3)]);
                ldsm4t(b[2 * nj][0], b[2 * nj][1], b[2 * nj + 1][0], b[2 * nj + 1][1], addr);
            }
#pragma unroll
            for (int mi = 0; mi < 4; mi++)
#pragma unroll
                for (int ni = 0; ni < 4; ni++)
                    mma_bf16(c[mi][ni], a[mi][0], a[mi][1], a[mi][2], a[mi][3],
                             b[ni][0], b[ni][1]);
        }
        buf ^= 1;
    }

#pragma unroll
    for (int mi = 0; mi < 4; mi++) {
#pragma unroll
        for (int rr = 0; rr < 2; rr++) {
            int r = bm + wm + mi * 16 + (lane >> 2) + rr * 8;
            if (EPI == 3) {
                if (r < cnt) {
                    int tok = lst[r];
                    float rsc = wdv[(size_t)tok * Ez + z];
                    float* dst = Cf + (size_t)z * c_zs;
#pragma unroll
                    for (int ni = 0; ni < 4; ni++)
#pragma unroll
                        for (int cc = 0; cc < 2; cc++) {
                            int col = bn + wn + ni * 8 + (lane & 3) * 2 + cc;
                            dst[(size_t)tok * N + col] =
                                rsc * (c[mi][ni][rr * 2 + cc] + bias[col]);
                        }
                }
            } else if (EPI == 5) {
                if (z == 0) {
#pragma unroll
                    for (int ni = 0; ni < 4; ni++)
#pragma unroll
                        for (int cc = 0; cc < 2; cc++) {
                            int col = bn + wn + ni * 8 + (lane & 3) * 2 + cc;
                            Cf[(size_t)r * N + col] = c[mi][ni][rr * 2 + cc];
                        }
                } else {
                    bf16* dst = Cb + (size_t)(z - 1) * c_zs;
#pragma unroll
                    for (int ni = 0; ni < 4; ni++) {
                        int colb = bn + wn + ni * 8 + (lane & 3) * 2;
                        __nv_bfloat162 p;
                        p.x = __float2bfloat16(c[mi][ni][rr * 2]);
                        p.y = __float2bfloat16(c[mi][ni][rr * 2 + 1]);
                        *(__nv_bfloat162*)&dst[(size_t)r * N + colb] = p;
                    }
                }
            } else if (EPI == 2) {
                bf16* dstb = Cb + (size_t)z * c_zs;
#pragma unroll
                for (int ni = 0; ni < 4; ni++)
#pragma unroll
                    for (int cc = 0; cc < 2; cc++) {
                        int col = bn + wn + ni * 8 + (lane & 3) * 2 + cc;
                        float g = gelu_f(c[mi][ni][rr * 2 + cc] + bias[col]);
                        bf16 hi = __float2bfloat16(g);
                        bf16 lo = __float2bfloat16(g - __bfloat162float(hi));
                        size_t base = (size_t)r * 3 * N;
                        dstb[base + col] = hi;
                        dstb[base + N + col] = hi;
                        dstb[base + 2 * N + col] = lo;
                    }
            } else {
#pragma unroll
                for (int ni = 0; ni < 4; ni++)
#pragma unroll
                    for (int cc = 0; cc < 2; cc++) {
                        int col = bn + wn + ni * 8 + (lane & 3) * 2 + cc;
                        float val = c[mi][ni][rr * 2 + cc];
                        if (EPI == 0) Cf[(size_t)r * N + col] = val;
                        else          Cf[(size_t)r * N + col] = val + resid[(size_t)r * N + col];
                    }
            }
        }
    }
}

// ---------------- small fp32 GEMM (kI: N=64, wI: N=4) --------------------------
__global__ void __launch_bounds__(256, 2)
sgemm_small_kernel(const float* __restrict__ A, const float* __restrict__ B,
                   float* __restrict__ C, int M, int N, int K) {
    const int BM = 128, BN = 128, BK = 8, TM = 8, TN = 8;
    __shared__ float As[BK][BM];
    __shared__ float Bs[BK][BN];
    int tid = threadIdx.x;
    int bm = blockIdx.y * BM;
    int bn = blockIdx.x * BN;
    int trow = (tid / 16) * TM;
    int tcol = (tid % 16) * TN;
    float acc[TM][TN];
#pragma unroll
    for (int i = 0; i < TM; i++)
#pragma unroll
        for (int j = 0; j < TN; j++) acc[i][j] = 0.f;
    int arow = tid >> 1, acol = (tid & 1) * 4;
    int brow = tid >> 5, bcol = (tid & 31) * 4;
    const float* Aptr = A + (size_t)(bm + arow) * K;
    for (int k0 = 0; k0 < K; k0 += BK) {
        float4 av = *(const float4*)(Aptr + k0 + acol);
        As[acol + 0][arow] = av.x; As[acol + 1][arow] = av.y;
        As[acol + 2][arow] = av.z; As[acol + 3][arow] = av.w;
        int bc = bn + bcol;
#pragma unroll
        for (int j = 0; j < 4; j++)
            Bs[brow][bcol + j] = (bc + j < N) ? B[(size_t)(k0 + brow) * N + bc + j] : 0.f;
        __syncthreads();
#pragma unroll
        for (int kk = 0; kk < BK; kk++) {
            float ar[TM], br[TN];
#pragma unroll
            for (int i = 0; i < TM; i++) ar[i] = As[kk][trow + i];
#pragma unroll
            for (int j = 0; j < TN; j++) br[j] = Bs[kk][tcol + j];
#pragma unroll
            for (int i = 0; i < TM; i++)
#pragma unroll
                for (int j = 0; j < TN; j++) acc[i][j] += ar[i] * br[j];
        }
        __syncthreads();
    }
#pragma unroll
    for (int i = 0; i < TM; i++) {
        int r = bm + trow + i;
#pragma unroll
        for (int j = 0; j < TN; j++) {
            int cidx = bn + tcol + j;
            if (cidx < N) C[(size_t)r * N + cidx] = acc[i][j];
        }
    }
}

// ---------------- indexer scores ------------------------------------------------
__global__ void idxscore_kernel(const float* __restrict__ qI, const float* __restrict__ kI,
                                const float* __restrict__ wI, float* __restrict__ sc) {
    int b  = blockIdx.z;
    int t0 = blockIdx.y * 16;
    int s0 = blockIdx.x * 64;
    if (s0 > t0 + 15) return;
    __shared__ float qIs[16][257];
    __shared__ float kIs[64][65];
    __shared__ float wIs[16][4];
    int tx = threadIdx.x, ty = threadIdx.y;
    int tid = ty * 16 + tx;
    for (int idx = tid; idx < 16 * 256; idx += 256) {
        int r = idx >> 8, c = idx & 255;
        qIs[r][c] = qI[((size_t)(b * Sz + t0 + r)) * 256 + c];
    }
    for (int idx = tid; idx < 64 * 64; idx += 256) {
        int r = idx >> 6, c = idx & 63;
        kIs[r][c] = kI[((size_t)(b * Sz + s0 + r)) * 64 + c];
    }
    if (tid < 64) wIs[tid >> 2][tid & 3] = wI[((size_t)(b * Sz + (tid >> 2) + t0)) * 4 + (tid & 3)];
    __syncthreads();

    float acc4[4] = {0.f, 0.f, 0.f, 0.f};
#pragma unroll
    for (int h = 0; h < 4; h++) {
        float dot[4] = {0.f, 0.f, 0.f, 0.f};
#pragma unroll
        for (int d = 0; d < 64; d++) {
            float qv = qIs[ty][h * 64 + d];
            dot[0] += qv * kIs[tx +  0][d];
            dot[1] += qv * kIs[tx + 16][d];
            dot[2] += qv * kIs[tx + 32][d];
            dot[3] += qv * kIs[tx + 48][d];
        }
        float wv = wIs[ty][h];
#pragma unroll
        for (int j = 0; j < 4; j++) acc4[j] += wv * fmaxf(dot[j], 0.f);
    }
    int t = t0 + ty;
#pragma unroll
    for (int j = 0; j < 4; j++) {
        int s = s0 + tx + 16 * j;
        if (s <= t) sc[((size_t)(b * Sz + t)) * Sz + s] = acc4[j];
    }
}

// ---------------- top-k (512) per (b,t), jax tie-break --------------------------
__global__ void topk_kernel(const float* __restrict__ sc, int* __restrict__ selidx,
                            int* __restrict__ selcnt) {
    int bt = blockIdx.x;
    int t = bt & (Sz - 1);
    int n = t + 1;
    int tid = threadIdx.x;
    int* outp = selidx + (size_t)bt * TKz;
    if (n <= TKz) {
        for (int i = tid; i < n; i += 256) outp[i] = i;
        if (tid == 0) selcnt[bt] = n;
        return;
    }
    const float* row = sc + (size_t)bt * Sz;
    __shared__ unsigned keys[Sz];
    for (int i = tid; i < n; i += 256) {
        unsigned u = __float_as_uint(row[i]);
        keys[i] = (u & 0x80000000u) ? ~u : (u | 0x80000000u);
    }
    __shared__ int cnt_s;
    unsigned p = 0;
    for (int bit = 31; bit >= 0; bit--) {
        unsigned q = p | (1u << bit);
        if (tid == 0) cnt_s = 0;
        __syncthreads();
        int c = 0;
        for (int i = tid; i < n; i += 256) c += (keys[i] >= q);
        for (int off = 16; off; off >>= 1) c += __shfl_xor_sync(0xffffffffu, c, off);
        if ((tid & 31) == 0) atomicAdd(&cnt_s, c);
        __syncthreads();
        int cv = cnt_s;
        __syncthreads();
        if (cv >= TKz) p = q;
    }
    __shared__ int pos;
    if (tid == 0) pos = 0;
    __syncthreads();
    for (int i = tid; i < n; i += 256)
        if (keys[i] > p) { int j = atomicAdd(&pos, 1); outp[j] = i; }
    __syncthreads();
    if (tid == 0) {
        int j = pos;
        for (int i = 0; i < n && j < TKz; i++)
            if (keys[i] == p) outp[j++] = i;
        selcnt[bt] = TKz;
    }
}

// ---------------- sparse attention (bf16 K/V) -----------------------------------
__global__ void __launch_bounds__(512)
attn_kernel(const float* __restrict__ q, const bf16* __restrict__ kb,
            const bf16* __restrict__ vb, const int* __restrict__ selidx,
            const int* __restrict__ selcnt, bf16* __restrict__ aox) {
    int bt = blockIdx.x;
    int b = bt >> 11;
    int tid = threadIdx.x;
    __shared__ float qs[Hz * DHz];
    __shared__ int sels[TKz];
    int n = selcnt[bt];
    for (int i = tid; i < Dz; i += 512) qs[i] = q[(size_t)bt * Dz + i];
    for (int i = tid; i < n; i += 512) sels[i] = selidx[(size_t)bt * TKz + i];
    __syncthreads();
    int h = tid >> 5, lane = tid & 31;
    float m = -3.0e38f, l = 0.f, o0 = 0.f, o1 = 0.f;
    float q0 = qs[h * 64 + 2 * lane], q1 = qs[h * 64 + 2 * lane + 1];
    for (int i = 0; i < n; i++) {
        int s = sels[i];
        size_t roff = ((size_t)(b * Sz + s)) * Dz + h * 64 + 2 * lane;
        float2 kf = __bfloat1622float2(*(const __nv_bfloat162*)(kb + roff));
        float part = q0 * kf.x + q1 * kf.y;
#pragma unroll
        for (int off = 16; off; off >>= 1) part += __shfl_xor_sync(0xffffffffu, part, off);
        float score = part * 0.125f;
        float mn = fmaxf(m, score);
        float scale = __expf(m - mn);
        float pw = __expf(score - mn);
        float2 vf = __bfloat1622float2(*(const __nv_bfloat162*)(vb + roff));
        o0 = o0 * scale + pw * vf.x;
        o1 = o1 * scale + pw * vf.y;
        l = l * scale + pw;
        m = mn;
    }
    float inv = 1.0f / l;
    o0 *= inv; o1 *= inv;
    size_t base = (size_t)bt * 3 * Dz;
    int c0 = h * 64 + 2 * lane, c1 = c0 + 1;
    bf16 h0 = __float2bfloat16(o0);
    bf16 l0 = __float2bfloat16(o0 - __bfloat162float(h0));
    bf16 h1 = __float2bfloat16(o1);
    bf16 l1 = __float2bfloat16(o1 - __bfloat162float(h1));
    aox[base + c0] = h0;           aox[base + c1] = h1;
    aox[base + Dz + c0] = h0;      aox[base + Dz + c1] = h1;
    aox[base + 2 * Dz + c0] = l0;  aox[base + 2 * Dz + c1] = l1;
}

// ---------------- gate: softmax(4) + top-2 + combine weights -------------------
__global__ void gate_kernel(const float* __restrict__ xn2, const float* __restrict__ gw,
                            float* __restrict__ wdense, float* __restrict__ probsb) {
    int t = blockIdx.x;
    int tid = threadIdx.x;
    const float* xr = xn2 + (size_t)t * Dz;
    float le[4] = {0.f, 0.f, 0.f, 0.f};
    for (int d = tid; d < Dz; d += 256) {
        float xv = xr[d];
        const float* g = gw + (size_t)d * 4;
        le[0] += xv * g[0]; le[1] += xv * g[1];
        le[2] += xv * g[2]; le[3] += xv * g[3];
    }
    __shared__ float red[4][256];
    for (int e = 0; e < 4; e++) red[e][tid] = le[e];
    __syncthreads();
    for (int off = 128; off; off >>= 1) {
        if (tid < off)
            for (int e = 0; e < 4; e++) red[e][tid] += red[e][tid + off];
        __syncthreads();
    }
    if (tid == 0) {
        float lg[4], pr[4];
        float mx = -3.0e38f;
        for (int e = 0; e < 4; e++) { lg[e] = red[e][0]; mx = fmaxf(mx, lg[e]); }
        float sum = 0.f;
        for (int e = 0; e < 4; e++) { pr[e] = expf(lg[e] - mx); sum += pr[e]; }
        float inv = 1.0f / sum;
        for (int e = 0; e < 4; e++) { pr[e] *= inv; probsb[(size_t)t * 4 + e] = pr[e]; }
        int i1 = 0;
        for (int e = 1; e < 4; e++) if (pr[e] > pr[i1]) i1 = e;
        int i2 = -1; float b2v = -1.f;
        for (int e = 0; e < 4; e++) if (e != i1 && pr[e] > b2v) { b2v = pr[e]; i2 = e; }
        float wsum = pr[i1] + pr[i2];
        float wd[4] = {0.f, 0.f, 0.f, 0.f};
        wd[i1] = pr[i1] / wsum;
        wd[i2] = pr[i2] / wsum;
        for (int e = 0; e < 4; e++) wdense[(size_t)t * 4 + e] = wd[e];
    }
}

// ---------------- routing -------------------------------------------------------
__global__ void route_zero_kernel(int* __restrict__ ecnt) {
    if (threadIdx.x < Ez) ecnt[threadIdx.x] = 0;
}
__global__ void route_kernel(const float* __restrict__ wd, int* __restrict__ ecnt,
                             int* __restrict__ elist) {
    int t = blockIdx.x * blockDim.x + threadIdx.x;
    if (t < Tz) {
#pragma unroll
        for (int e = 0; e < Ez; e++)
            if (wd[(size_t)t * Ez + e] > 0.f) {
                int p = atomicAdd(&ecnt[e], 1);
                elist[e * Tz + p] = t;
            }
    }
}
__global__ void route_pad_kernel(const int* __restrict__ ecnt, int* __restrict__ elist) {
    int e = blockIdx.x;
    int cnt = ecnt[e];
    int padded = (cnt + 127) & ~127;
    for (int i = cnt + threadIdx.x; i < padded; i += blockDim.x) elist[e * Tz + i] = 0;
}

// ---------------- aux loss ------------------------------------------------------
__global__ void aux_kernel(const float* __restrict__ probsb, const float* __restrict__ wdense,
                           float* __restrict__ out_aux) {
    int tid = threadIdx.x;
    float sP[4] = {0.f, 0.f, 0.f, 0.f}, sF[4] = {0.f, 0.f, 0.f, 0.f};
    for (int t = tid; t < Tz; t += 256)
        for (int e = 0; e < 4; e++) {
            sP[e] += probsb[(size_t)t * 4 + e];
            sF[e] += (wdense[(size_t)t * 4 + e] > 0.f) ? 1.f : 0.f;
        }
    __shared__ float rP[4][256], rF[4][256];
    for (int e = 0; e < 4; e++) { rP[e][tid] = sP[e]; rF[e][tid] = sF[e]; }
    __syncthreads();
    for (int off = 128; off; off >>= 1) {
        if (tid < off)
            for (int e = 0; e < 4; e++) {
                rP[e][tid] += rP[e][tid + off];
                rF[e][tid] += rF[e][tid + off];
            }
        __syncthreads();
    }
    if (tid == 0) {
        float aux = 0.f;
        for (int e = 0; e < 4; e++)
            aux += (rF[e][0] * (1.0f / Tz)) * (rP[e][0] * (1.0f / Tz));
        *out_aux = (float)Ez * aux;
    }
}

// ---------------- final: out = x2 + sum_e masked ffe[e] -------------------------
__global__ void final_kernel(const float* __restrict__ x2, const float* __restrict__ ffe,
                             const float* __restrict__ wd, float* __restrict__ out) {
    for (int i = blockIdx.x * blockDim.x + threadIdx.x; i < Tz * Dz;
         i += gridDim.x * blockDim.x) {
        int t = i >> 10;
        float s = x2[i];
#pragma unroll
        for (int e = 0; e < Ez; e++)
            if (wd[(size_t)t * Ez + e] > 0.f) s += ffe[(size_t)e * Tz * Dz + i];
        out[i] = s;
    }
}

// ---------------- launch -------------------------------------------------------
extern "C" void kernel_launch(void* const* d_in, const int* in_sizes, int n_in,
                              void* d_out, int out_size) {
    const float* x      = (const float*)d_in[0];
    const float* n1w    = (const float*)d_in[1];
    const float* n2w    = (const float*)d_in[2];
    const float* wq     = (const float*)d_in[3];
    const float* wk     = (const float*)d_in[4];
    const float* wv     = (const float*)d_in[5];
    const float* wo     = (const float*)d_in[6];
    const float* idx_wq = (const float*)d_in[7];
    const float* idx_wk = (const float*)d_in[8];
    const float* idx_ww = (const float*)d_in[9];
    const float* gate_w = (const float*)d_in[10];
    const float* w1     = (const float*)d_in[11];
    const float* b1     = (const float*)d_in[12];
    const float* w2     = (const float*)d_in[13];
    const float* b2     = (const float*)d_in[14];
    float* out = (float*)d_out;

    float *xn, *q, *qI, *kI, *wI, *sc, *x2, *xn2, *wd, *pr, *ffe;
    int *selidx, *selcnt, *ecnt, *elist;
    bf16 *kvb, *xnx, *xn2x, *aox, *hx, *wqkvx, *wox, *iwqx, *w1x, *w2x;
    cudaGetSymbolAddress((void**)&xn,  g_xn);
    cudaGetSymbolAddress((void**)&q,   g_q);
    cudaGetSymbolAddress((void**)&qI,  g_qI);
    cudaGetSymbolAddress((void**)&kI,  g_kI);
    cudaGetSymbolAddress((void**)&wI,  g_wI);
    cudaGetSymbolAddress((void**)&sc,  g_sc);
    cudaGetSymbolAddress((void**)&selidx, g_selidx);
    cudaGetSymbolAddress((void**)&selcnt, g_selcnt);
    cudaGetSymbolAddress((void**)&x2,  g_x2);
    cudaGetSymbolAddress((void**)&xn2, g_xn2);
    cudaGetSymbolAddress((void**)&wd,  g_wd);
    cudaGetSymbolAddress((void**)&pr,  g_pr);
    cudaGetSymbolAddress((void**)&ffe, g_ffe);
    cudaGetSymbolAddress((void**)&ecnt,  g_ecnt);
    cudaGetSymbolAddress((void**)&elist, g_elist);
    cudaGetSymbolAddress((void**)&kvb,  g_kvb);
    cudaGetSymbolAddress((void**)&xnx,  g_xnx);
    cudaGetSymbolAddress((void**)&xn2x, g_xn2x);
    cudaGetSymbolAddress((void**)&aox,  g_aox);
    cudaGetSymbolAddress((void**)&hx,   g_hx);
    cudaGetSymbolAddress((void**)&wqkvx, g_wqkvx);
    cudaGetSymbolAddress((void**)&wox,  g_wox);
    cudaGetSymbolAddress((void**)&iwqx, g_iwqx);
    cudaGetSymbolAddress((void**)&w1x,  g_w1x);
    cudaGetSymbolAddress((void**)&w2x,  g_w2x);

    const size_t WZ = (size_t)3 * Dz * Dz;

    // ---- weight split-expansion ----
    convw_kernel<<<1024, 256>>>(wq, wqkvx, Dz, Dz);
    convw_kernel<<<1024, 256>>>(wk, wqkvx + WZ, Dz, Dz);
    convw_kernel<<<1024, 256>>>(wv, wqkvx + 2 * WZ, Dz, Dz);
    convw_kernel<<<1024, 256>>>(wo, wox, Dz, Dz);
    convw_kernel<<<256, 256>>>(idx_wq, iwqx, Dz, HIz * DIz);
    for (int e = 0; e < Ez; e++) {
        convw_kernel<<<2048, 256>>>(w1 + (size_t)e * Dz * DFz,
                                    w1x + (size_t)e * 3 * Dz * DFz, Dz, DFz);
        convw_kernel<<<2048, 256>>>(w2 + (size_t)e * DFz * Dz,
                                    w2x + (size_t)e * 3 * DFz * Dz, DFz, Dz);
    }

    // ---- attention path ----
    rmsnorm2_kernel<<<Tz, 256>>>(x, n1w, xn, xnx);
    // QKV batched: z=0 -> q fp32; z=1 -> K bf16; z=2 -> V bf16
    hgemm_kernel<5><<<dim3(8, 32, 3), 256>>>(xnx, wqkvx, q, kvb, Tz, Dz, 3 * Dz,
                                             nullptr, nullptr, nullptr, nullptr, nullptr,
                                             0, WZ, (size_t)Tz * Dz, 0);
    hgemm_kernel<0><<<dim3(2, 32), 256>>>(xnx, iwqx, qI, nullptr, Tz, HIz * DIz, 3 * Dz,
                                          nullptr, nullptr, nullptr, nullptr, nullptr,
                                          0, 0, 0, 0);
    sgemm_small_kernel<<<dim3(1, 32), 256>>>(xn, idx_wk, kI, Tz, DIz, Dz);
    sgemm_small_kernel<<<dim3(1, 32), 256>>>(xn, idx_ww, wI, Tz, HIz, Dz);

    idxscore_kernel<<<dim3(Sz / 64, Sz / 16, Bz), dim3(16, 16)>>>(qI, kI, wI, sc);
    topk_kernel<<<Tz, 256>>>(sc, selidx, selcnt);
    attn_kernel<<<Tz, 512>>>(q, kvb, kvb + (size_t)Tz * Dz, selidx, selcnt, aox);
    hgemm_kernel<1><<<dim3(8, 32), 256>>>(aox, wox, x2, nullptr, Tz, Dz, 3 * Dz,
                                          nullptr, x, nullptr, nullptr, nullptr,
                                          0, 0, 0, 0);

    // ---- MoE path (routed + expert-batched) ----
    rmsnorm2_kernel<<<Tz, 256>>>(x2, n2w, xn2, xn2x);
    gate_kernel<<<Tz, 256>>>(xn2, gate_w, wd, pr);
    route_zero_kernel<<<1, 32>>>(ecnt);
    route_kernel<<<Tz / 256, 256>>>(wd, ecnt, elist);
    route_pad_kernel<<<Ez, 128>>>(ecnt, elist);
    // w1: all experts, gather rows
    hgemm_kernel<2><<<dim3(32, 32, Ez), 256>>>(xn2x, w1x, nullptr, hx, Tz, DFz, 3 * Dz,
                                               b1, nullptr, nullptr, elist, ecnt,
                                               0, (size_t)3 * Dz * DFz,
                                               (size_t)Tz * 3 * DFz, DFz);
    // w2: all experts, scatter per-expert buffers
    hgemm_kernel<3><<<dim3(8, 32, Ez), 256>>>(hx, w2x, ffe, nullptr, Tz, Dz, 3 * DFz,
                                              b2, nullptr, wd, elist, ecnt,
                                              (size_t)Tz * 3 * DFz, (size_t)3 * DFz * Dz,
                                              (size_t)Tz * Dz, Dz);

    final_kernel<<<8192, 256>>>(x2, ffe, wd, out);
    aux_kernel<<<1, 256>>>(pr, wd, out + (out_size - 1));
}

// round 11
// speedup vs baseline: 2.8541x; 1.0788x over previous
#include <cuda_runtime.h>
#include <cuda_bf16.h>
#include <math.h>
#include <stdint.h>

// Problem dims (fixed by setup_inputs)
#define Bz 2
#define Sz 2048
#define Dz 1024
#define Tz 4096           // B*S
#define Hz 16
#define DHz 64
#define HIz 4
#define DIz 64
#define TKz 512
#define Ez 4
#define DFz 4096

typedef __nv_bfloat16 bf16;

// ---------------- scratch (device globals; no allocation allowed) --------------
__device__ float g_xn [Tz*Dz];
__device__ float g_q  [Tz*Dz];
__device__ float g_qI [Tz*HIz*DIz];
__device__ float g_kI [Tz*DIz];
__device__ float g_wI [Tz*HIz];
__device__ float g_sc [(size_t)Bz*Sz*Sz];
__device__ int   g_selidx[(size_t)Tz*TKz];
__device__ int   g_selcnt[Tz];
__device__ float g_x2 [Tz*Dz];
__device__ float g_xn2[Tz*Dz];
__device__ float g_wd [Tz*Ez];
__device__ float g_pr [Tz*Ez];
__device__ int   g_ecnt[Ez];
__device__ int   g_elist[Ez*Tz];
__device__ float g_ffe[(size_t)Ez*Tz*Dz];

// bf16 operands: split storage is [hi|lo] (2K); GEMM remaps k-blocks to get
// the 3-term product Ahi*Bhi + Ahi*Blo + Alo*Bhi.
__device__ bf16 g_kvb  [(size_t)2*Tz*Dz];
__device__ bf16 g_xnx  [(size_t)Tz*2*Dz];
__device__ bf16 g_xn2x [(size_t)Tz*2*Dz];
__device__ bf16 g_aox  [(size_t)Tz*2*Dz];
__device__ bf16 g_hx   [(size_t)Ez*Tz*2*DFz];
__device__ bf16 g_wqkvx[(size_t)3*2*Dz*Dz];
__device__ bf16 g_wox  [2*Dz*Dz];
__device__ bf16 g_iwqx [2*Dz*HIz*DIz];
__device__ bf16 g_w1x  [(size_t)Ez*2*Dz*DFz];
__device__ bf16 g_w2x  [(size_t)Ez*2*DFz*Dz];

// ---------------- helpers ------------------------------------------------------
__device__ __forceinline__ float gelu_f(float x) {
    float x3 = x * x * x;
    return 0.5f * x * (1.0f + tanhf(0.7978845608028654f * (x + 0.044715f * x3)));
}
__device__ __forceinline__ uint32_t smem_u32(const void* p) {
    return (uint32_t)__cvta_generic_to_shared(p);
}
__device__ __forceinline__ void ldsm4(uint32_t& r0, uint32_t& r1, uint32_t& r2,
                                      uint32_t& r3, uint32_t a) {
    asm volatile("ldmatrix.sync.aligned.m8n8.x4.shared.b16 {%0,%1,%2,%3}, [%4];\n"
                 : "=r"(r0), "=r"(r1), "=r"(r2), "=r"(r3) : "r"(a));
}
__device__ __forceinline__ void ldsm4t(uint32_t& r0, uint32_t& r1, uint32_t& r2,
                                       uint32_t& r3, uint32_t a) {
    asm volatile("ldmatrix.sync.aligned.m8n8.x4.trans.shared.b16 {%0,%1,%2,%3}, [%4];\n"
                 : "=r"(r0), "=r"(r1), "=r"(r2), "=r"(r3) : "r"(a));
}
__device__ __forceinline__ void mma_bf16(float c[4], uint32_t a0, uint32_t a1,
                                         uint32_t a2, uint32_t a3,
                                         uint32_t b0, uint32_t b1) {
    asm volatile("mma.sync.aligned.m16n8k16.row.col.f32.bf16.bf16.f32 "
                 "{%0,%1,%2,%3}, {%4,%5,%6,%7}, {%8,%9}, {%0,%1,%2,%3};\n"
                 : "+f"(c[0]), "+f"(c[1]), "+f"(c[2]), "+f"(c[3])
                 : "r"(a0), "r"(a1), "r"(a2), "r"(a3), "r"(b0), "r"(b1));
}
#define CPA16(dst, src) \
    asm volatile("cp.async.cg.shared.global [%0], [%1], 16;\n" :: "r"(dst), "l"(src))
#define CPA_COMMIT() asm volatile("cp.async.commit_group;\n" ::)
#define CPA_WAIT0()  asm volatile("cp.async.wait_group 0;\n" ::)

// ---------------- rmsnorm (fp32 out optional + bf16 [hi|lo] out) ---------------
__global__ void rmsnorm2_kernel(const float* __restrict__ x, const float* __restrict__ w,
                                float* __restrict__ y, bf16* __restrict__ yx) {
    int t = blockIdx.x;
    int tid = threadIdx.x;
    const float* xr = x + (size_t)t * Dz;
    float s = 0.f;
    for (int i = tid; i < Dz; i += 256) { float v = xr[i]; s += v * v; }
    __shared__ float red[256];
    red[tid] = s; __syncthreads();
    for (int off = 128; off; off >>= 1) {
        if (tid < off) red[tid] += red[tid + off];
        __syncthreads();
    }
    float inv = rsqrtf(red[0] * (1.0f / Dz) + 1e-6f);
    bf16* yr = yx + (size_t)t * 2 * Dz;
    for (int i = tid; i < Dz; i += 256) {
        float v = xr[i] * inv * w[i];
        if (y) y[(size_t)t * Dz + i] = v;
        bf16 hi = __float2bfloat16(v);
        bf16 lo = __float2bfloat16(v - __bfloat162float(hi));
        yr[i] = hi;
        yr[Dz + i] = lo;
    }
}

// ---------------- weight split: [K][N] fp32 -> [2K][N] bf16 [hi;lo] ------------
__global__ void convw_kernel(const float* __restrict__ src, bf16* __restrict__ dst,
                             int K, int N) {
    size_t total = ((size_t)K * N) >> 2;
    for (size_t i = blockIdx.x * blockDim.x + threadIdx.x; i < total;
         i += (size_t)gridDim.x * blockDim.x) {
        size_t base = i << 2;
        int k = (int)(base / N), n = (int)(base % N);
        float4 a = ((const float4*)src)[i];
        __align__(8) bf16 hv[4], lv[4];
        hv[0] = __float2bfloat16(a.x); lv[0] = __float2bfloat16(a.x - __bfloat162float(hv[0]));
        hv[1] = __float2bfloat16(a.y); lv[1] = __float2bfloat16(a.y - __bfloat162float(hv[1]));
        hv[2] = __float2bfloat16(a.z); lv[2] = __float2bfloat16(a.z - __bfloat162float(hv[2]));
        hv[3] = __float2bfloat16(a.w); lv[3] = __float2bfloat16(a.w - __bfloat162float(hv[3]));
        *(uint2*)&dst[(size_t)k * N + n] = *(uint2*)hv;
        *(uint2*)&dst[(size_t)(K + k) * N + n] = *(uint2*)lv;
    }
}

// ---------------- bf16 tensor-core GEMM (z-batched, 3-term remap) ---------------
// Logical C[M,N] = A[M,3*Kthird] x B[3*Kthird,N] where both are stored [hi|lo]
// (2*Kthird) and k-block kt maps: A-block = kt<KB?kt:kt-KB, B-block = kt<2KB?kt:kt-2KB.
// 128 threads, 4 warps, warp tile 64x64, CTA tile 128x128.
// EPI 0: Cf = val
// EPI 1: Cf = val + resid
// EPI 2: gather A rows via elist[z]; Cb+z*c_zs [hi|lo] (stride 2N) of gelu(val+bias)
// EPI 3: scatter: (Cf+z*c_zs)[tok*N+c] = wdv[tok*Ez+z]*(val+bias[c])
// EPI 5: QKV: z==0 -> Cf fp32; z>=1 -> (Cb+(z-1)*c_zs) plain bf16
template<int EPI>
__global__ void __launch_bounds__(128, 2)
hgemm_kernel(const bf16* __restrict__ A, const bf16* __restrict__ B,
             float* __restrict__ Cf, bf16* __restrict__ Cb,
             int M, int N, int Kthird,
             const float* __restrict__ bias, const float* __restrict__ resid,
             const float* __restrict__ wdv,
             const int* __restrict__ elist, const int* __restrict__ ecnt,
             size_t a_zs, size_t b_zs, size_t c_zs, int bias_zs) {
    int z = blockIdx.z;
    int bm = blockIdx.y * 128, bn = blockIdx.x * 128;
    int cnt = M;
    if (ecnt) {
        cnt = ecnt[z];
        int padded = (cnt + 127) & ~127;
        if (bm >= padded) return;
    }
    A += (size_t)z * a_zs;
    B += (size_t)z * b_zs;
    if (bias) bias += (size_t)z * bias_zs;
    const int* lst = elist ? elist + (size_t)z * Tz : nullptr;

    __shared__ __align__(16) bf16 As[2][128][40];
    __shared__ __align__(16) bf16 Bs[2][32][136];
    int tid = threadIdx.x;
    int warp = tid >> 5, lane = tid & 31;
    int wm = (warp & 1) * 64, wn = (warp >> 1) * 64;

    const int KB = Kthird >> 5;       // k-blocks per third
    const int KT = 3 * KB;
    const int AS = 2 * Kthird;        // A row stride

    int arow = tid >> 2, acol = (tid & 3) * 8;      // A rows arow+32*j, j=0..3
    int brow = tid >> 4, bcol = (tid & 15) * 8;     // B rows brow+8*j,  j=0..3
    const bf16* Ag[4];
#pragma unroll
    for (int j = 0; j < 4; j++) {
        int r = bm + arow + 32 * j;
        if (EPI == 2) r = lst[r];
        Ag[j] = A + (size_t)r * AS + acol;
    }
    const bf16* Bg = B + (size_t)brow * N + bn + bcol;

    float c[4][8][4];
#pragma unroll
    for (int mi = 0; mi < 4; mi++)
#pragma unroll
        for (int ni = 0; ni < 8; ni++)
#pragma unroll
            for (int j = 0; j < 4; j++) c[mi][ni][j] = 0.f;

    // prologue: kt=0 (ak=0, bk=0)
    {
#pragma unroll
        for (int j = 0; j < 4; j++)
            CPA16(smem_u32(&As[0][arow + 32 * j][acol]), Ag[j]);
#pragma unroll
        for (int j = 0; j < 4; j++)
            CPA16(smem_u32(&Bs[0][brow + 8 * j][bcol]), Bg + (size_t)(8 * j) * N);
        CPA_COMMIT();
    }
    int buf = 0;
    for (int kt = 0; kt < KT; kt++) {
        CPA_WAIT0();
        __syncthreads();
        if (kt + 1 < KT) {
            int nb = buf ^ 1;
            int k2 = kt + 1;
            int ak = (k2 < KB) ? k2 : k2 - KB;
            int bk = (k2 < 2 * KB) ? k2 : k2 - 2 * KB;
#pragma unroll
            for (int j = 0; j < 4; j++)
                CPA16(smem_u32(&As[nb][arow + 32 * j][acol]), Ag[j] + ak * 32);
#pragma unroll
            for (int j = 0; j < 4; j++)
                CPA16(smem_u32(&Bs[nb][brow + 8 * j][bcol]),
                      Bg + (size_t)(bk * 32 + 8 * j) * N);
            CPA_COMMIT();
        }
#pragma unroll
        for (int kk = 0; kk < 32; kk += 16) {
            uint32_t a[4][4], b[8][2];
#pragma unroll
            for (int mi = 0; mi < 4; mi++) {
                uint32_t addr = smem_u32(
                    &As[buf][wm + mi * 16 + (lane & 15)][kk + ((lane >> 4) << 3)]);
                ldsm4(a[mi][0], a[mi][1], a[mi][2], a[mi][3], addr);
            }
#pragma unroll
            for (int nj = 0; nj < 4; nj++) {
                uint32_t addr = smem_u32(
                    &Bs[buf][kk + (lane & 15)][wn + nj * 16 + ((lane >> 4) << 3)]);
                ldsm4t(b[2 * nj][0], b[2 * nj][1], b[2 * nj + 1][0], b[2 * nj + 1][1], addr);
            }
#pragma unroll
            for (int mi = 0; mi < 4; mi++)
#pragma unroll
                for (int ni = 0; ni < 8; ni++)
                    mma_bf16(c[mi][ni], a[mi][0], a[mi][1], a[mi][2], a[mi][3],
                             b[ni][0], b[ni][1]);
        }
        buf ^= 1;
    }

#pragma unroll
    for (int mi = 0; mi < 4; mi++) {
#pragma unroll
        for (int rr = 0; rr < 2; rr++) {
            int r = bm + wm + mi * 16 + (lane >> 2) + rr * 8;
            if (EPI == 3) {
                if (r < cnt) {
                    int tok = lst[r];
                    float rsc = wdv[(size_t)tok * Ez + z];
                    float* dst = Cf + (size_t)z * c_zs;
#pragma unroll
                    for (int ni = 0; ni < 8; ni++)
#pragma unroll
                        for (int cc = 0; cc < 2; cc++) {
                            int col = bn + wn + ni * 8 + (lane & 3) * 2 + cc;
                            dst[(size_t)tok * N + col] =
                                rsc * (c[mi][ni][rr * 2 + cc] + bias[col]);
                        }
                }
            } else if (EPI == 5) {
                if (z == 0) {
#pragma unroll
                    for (int ni = 0; ni < 8; ni++)
#pragma unroll
                        for (int cc = 0; cc < 2; cc++) {
                            int col = bn + wn + ni * 8 + (lane & 3) * 2 + cc;
                            Cf[(size_t)r * N + col] = c[mi][ni][rr * 2 + cc];
                        }
                } else {
                    bf16* dst = Cb + (size_t)(z - 1) * c_zs;
#pragma unroll
                    for (int ni = 0; ni < 8; ni++) {
                        int colb = bn + wn + ni * 8 + (lane & 3) * 2;
                        __nv_bfloat162 p;
                        p.x = __float2bfloat16(c[mi][ni][rr * 2]);
                        p.y = __float2bfloat16(c[mi][ni][rr * 2 + 1]);
                        *(__nv_bfloat162*)&dst[(size_t)r * N + colb] = p;
                    }
                }
            } else if (EPI == 2) {
                bf16* dstb = Cb + (size_t)z * c_zs;
#pragma unroll
                for (int ni = 0; ni < 8; ni++)
#pragma unroll
                    for (int cc = 0; cc < 2; cc++) {
                        int col = bn + wn + ni * 8 + (lane & 3) * 2 + cc;
                        float g = gelu_f(c[mi][ni][rr * 2 + cc] + bias[col]);
                        bf16 hi = __float2bfloat16(g);
                        bf16 lo = __float2bfloat16(g - __bfloat162float(hi));
                        size_t base = (size_t)r * 2 * N;
                        dstb[base + col] = hi;
                        dstb[base + N + col] = lo;
                    }
            } else {
#pragma unroll
                for (int ni = 0; ni < 8; ni++)
#pragma unroll
                    for (int cc = 0; cc < 2; cc++) {
                        int col = bn + wn + ni * 8 + (lane & 3) * 2 + cc;
                        float val = c[mi][ni][rr * 2 + cc];
                        if (EPI == 0) Cf[(size_t)r * N + col] = val;
                        else          Cf[(size_t)r * N + col] = val + resid[(size_t)r * N + col];
                    }
            }
        }
    }
}

// ---------------- small fp32 GEMM (kI: N=64, wI: N=4) --------------------------
__global__ void __launch_bounds__(256, 2)
sgemm_small_kernel(const float* __restrict__ A, const float* __restrict__ B,
                   float* __restrict__ C, int M, int N, int K) {
    const int BM = 128, BN = 128, BK = 8, TM = 8, TN = 8;
    __shared__ float As[BK][BM];
    __shared__ float Bs[BK][BN];
    int tid = threadIdx.x;
    int bm = blockIdx.y * BM;
    int bn = blockIdx.x * BN;
    int trow = (tid / 16) * TM;
    int tcol = (tid % 16) * TN;
    float acc[TM][TN];
#pragma unroll
    for (int i = 0; i < TM; i++)
#pragma unroll
        for (int j = 0; j < TN; j++) acc[i][j] = 0.f;
    int arow = tid >> 1, acol = (tid & 1) * 4;
    int brow = tid >> 5, bcol = (tid & 31) * 4;
    const float* Aptr = A + (size_t)(bm + arow) * K;
    for (int k0 = 0; k0 < K; k0 += BK) {
        float4 av = *(const float4*)(Aptr + k0 + acol);
        As[acol + 0][arow] = av.x; As[acol + 1][arow] = av.y;
        As[acol + 2][arow] = av.z; As[acol + 3][arow] = av.w;
        int bc = bn + bcol;
#pragma unroll
        for (int j = 0; j < 4; j++)
            Bs[brow][bcol + j] = (bc + j < N) ? B[(size_t)(k0 + brow) * N + bc + j] : 0.f;
        __syncthreads();
#pragma unroll
        for (int kk = 0; kk < BK; kk++) {
            float ar[TM], br[TN];
#pragma unroll
            for (int i = 0; i < TM; i++) ar[i] = As[kk][trow + i];
#pragma unroll
            for (int j = 0; j < TN; j++) br[j] = Bs[kk][tcol + j];
#pragma unroll
            for (int i = 0; i < TM; i++)
#pragma unroll
                for (int j = 0; j < TN; j++) acc[i][j] += ar[i] * br[j];
        }
        __syncthreads();
    }
#pragma unroll
    for (int i = 0; i < TM; i++) {
        int r = bm + trow + i;
#pragma unroll
        for (int j = 0; j < TN; j++) {
            int cidx = bn + tcol + j;
            if (cidx < N) C[(size_t)r * N + cidx] = acc[i][j];
        }
    }
}

// ---------------- indexer scores ------------------------------------------------
__global__ void idxscore_kernel(const float* __restrict__ qI, const float* __restrict__ kI,
                                const float* __restrict__ wI, float* __restrict__ sc) {
    int b  = blockIdx.z;
    int t0 = blockIdx.y * 16;
    int s0 = blockIdx.x * 64;
    if (s0 > t0 + 15) return;
    __shared__ float qIs[16][257];
    __shared__ float kIs[64][65];
    __shared__ float wIs[16][4];
    int tx = threadIdx.x, ty = threadIdx.y;
    int tid = ty * 16 + tx;
    for (int idx = tid; idx < 16 * 256; idx += 256) {
        int r = idx >> 8, c = idx & 255;
        qIs[r][c] = qI[((size_t)(b * Sz + t0 + r)) * 256 + c];
    }
    for (int idx = tid; idx < 64 * 64; idx += 256) {
        int r = idx >> 6, c = idx & 63;
        kIs[r][c] = kI[((size_t)(b * Sz + s0 + r)) * 64 + c];
    }
    if (tid < 64) wIs[tid >> 2][tid & 3] = wI[((size_t)(b * Sz + (tid >> 2) + t0)) * 4 + (tid & 3)];
    __syncthreads();

    float acc4[4] = {0.f, 0.f, 0.f, 0.f};
#pragma unroll
    for (int h = 0; h < 4; h++) {
        float dot[4] = {0.f, 0.f, 0.f, 0.f};
#pragma unroll
        for (int d = 0; d < 64; d++) {
            float qv = qIs[ty][h * 64 + d];
            dot[0] += qv * kIs[tx +  0][d];
            dot[1] += qv * kIs[tx + 16][d];
            dot[2] += qv * kIs[tx + 32][d];
            dot[3] += qv * kIs[tx + 48][d];
        }
        float wv = wIs[ty][h];
#pragma unroll
        for (int j = 0; j < 4; j++) acc4[j] += wv * fmaxf(dot[j], 0.f);
    }
    int t = t0 + ty;
#pragma unroll
    for (int j = 0; j < 4; j++) {
        int s = s0 + tx + 16 * j;
        if (s <= t) sc[((size_t)(b * Sz + t)) * Sz + s] = acc4[j];
    }
}

// ---------------- top-k (512) per (b,t), jax tie-break --------------------------
__global__ void topk_kernel(const float* __restrict__ sc, int* __restrict__ selidx,
                            int* __restrict__ selcnt) {
    int bt = blockIdx.x;
    int t = bt & (Sz - 1);
    int n = t + 1;
    int tid = threadIdx.x;
    int* outp = selidx + (size_t)bt * TKz;
    if (n <= TKz) {
        for (int i = tid; i < n; i += 256) outp[i] = i;
        if (tid == 0) selcnt[bt] = n;
        return;
    }
    const float* row = sc + (size_t)bt * Sz;
    __shared__ unsigned keys[Sz];
    for (int i = tid; i < n; i += 256) {
        unsigned u = __float_as_uint(row[i]);
        keys[i] = (u & 0x80000000u) ? ~u : (u | 0x80000000u);
    }
    __shared__ int cnt_s;
    unsigned p = 0;
    for (int bit = 31; bit >= 0; bit--) {
        unsigned q = p | (1u << bit);
        if (tid == 0) cnt_s = 0;
        __syncthreads();
        int c = 0;
        for (int i = tid; i < n; i += 256) c += (keys[i] >= q);
        for (int off = 16; off; off >>= 1) c += __shfl_xor_sync(0xffffffffu, c, off);
        if ((tid & 31) == 0) atomicAdd(&cnt_s, c);
        __syncthreads();
        int cv = cnt_s;
        __syncthreads();
        if (cv >= TKz) p = q;
    }
    __shared__ int pos;
    if (tid == 0) pos = 0;
    __syncthreads();
    for (int i = tid; i < n; i += 256)
        if (keys[i] > p) { int j = atomicAdd(&pos, 1); outp[j] = i; }
    __syncthreads();
    if (tid == 0) {
        int j = pos;
        for (int i = 0; i < n && j < TKz; i++)
            if (keys[i] == p) outp[j++] = i;
        selcnt[bt] = TKz;
    }
}

// ---------------- sparse attention (bf16 K/V), [hi|lo] output -------------------
__global__ void __launch_bounds__(512)
attn_kernel(const float* __restrict__ q, const bf16* __restrict__ kb,
            const bf16* __restrict__ vb, const int* __restrict__ selidx,
            const int* __restrict__ selcnt, bf16* __restrict__ aox) {
    int bt = blockIdx.x;
    int b = bt >> 11;
    int tid = threadIdx.x;
    __shared__ float qs[Hz * DHz];
    __shared__ int sels[TKz];
    int n = selcnt[bt];
    for (int i = tid; i < Dz; i += 512) qs[i] = q[(size_t)bt * Dz + i];
    for (int i = tid; i < n; i += 512) sels[i] = selidx[(size_t)bt * TKz + i];
    __syncthreads();
    int h = tid >> 5, lane = tid & 31;
    float m = -3.0e38f, l = 0.f, o0 = 0.f, o1 = 0.f;
    float q0 = qs[h * 64 + 2 * lane], q1 = qs[h * 64 + 2 * lane + 1];
    for (int i = 0; i < n; i++) {
        int s = sels[i];
        size_t roff = ((size_t)(b * Sz + s)) * Dz + h * 64 + 2 * lane;
        float2 kf = __bfloat1622float2(*(const __nv_bfloat162*)(kb + roff));
        float part = q0 * kf.x + q1 * kf.y;
#pragma unroll
        for (int off = 16; off; off >>= 1) part += __shfl_xor_sync(0xffffffffu, part, off);
        float score = part * 0.125f;
        float mn = fmaxf(m, score);
        float scale = __expf(m - mn);
        float pw = __expf(score - mn);
        float2 vf = __bfloat1622float2(*(const __nv_bfloat162*)(vb + roff));
        o0 = o0 * scale + pw * vf.x;
        o1 = o1 * scale + pw * vf.y;
        l = l * scale + pw;
        m = mn;
    }
    float inv = 1.0f / l;
    o0 *= inv; o1 *= inv;
    size_t base = (size_t)bt * 2 * Dz;
    int c0 = h * 64 + 2 * lane, c1 = c0 + 1;
    bf16 h0 = __float2bfloat16(o0);
    bf16 l0 = __float2bfloat16(o0 - __bfloat162float(h0));
    bf16 h1 = __float2bfloat16(o1);
    bf16 l1 = __float2bfloat16(o1 - __bfloat162float(h1));
    aox[base + c0] = h0;       aox[base + c1] = h1;
    aox[base + Dz + c0] = l0;  aox[base + Dz + c1] = l1;
}

// ---------------- gate: softmax(4) + top-2 + combine weights -------------------
__global__ void gate_kernel(const float* __restrict__ xn2, const float* __restrict__ gw,
                            float* __restrict__ wdense, float* __restrict__ probsb) {
    int t = blockIdx.x;
    int tid = threadIdx.x;
    const float* xr = xn2 + (size_t)t * Dz;
    float le[4] = {0.f, 0.f, 0.f, 0.f};
    for (int d = tid; d < Dz; d += 256) {
        float xv = xr[d];
        const float* g = gw + (size_t)d * 4;
        le[0] += xv * g[0]; le[1] += xv * g[1];
        le[2] += xv * g[2]; le[3] += xv * g[3];
    }
    __shared__ float red[4][256];
    for (int e = 0; e < 4; e++) red[e][tid] = le[e];
    __syncthreads();
    for (int off = 128; off; off >>= 1) {
        if (tid < off)
            for (int e = 0; e < 4; e++) red[e][tid] += red[e][tid + off];
        __syncthreads();
    }
    if (tid == 0) {
        float lg[4], pr[4];
        float mx = -3.0e38f;
        for (int e = 0; e < 4; e++) { lg[e] = red[e][0]; mx = fmaxf(mx, lg[e]); }
        float sum = 0.f;
        for (int e = 0; e < 4; e++) { pr[e] = expf(lg[e] - mx); sum += pr[e]; }
        float inv = 1.0f / sum;
        for (int e = 0; e < 4; e++) { pr[e] *= inv; probsb[(size_t)t * 4 + e] = pr[e]; }
        int i1 = 0;
        for (int e = 1; e < 4; e++) if (pr[e] > pr[i1]) i1 = e;
        int i2 = -1; float b2v = -1.f;
        for (int e = 0; e < 4; e++) if (e != i1 && pr[e] > b2v) { b2v = pr[e]; i2 = e; }
        float wsum = pr[i1] + pr[i2];
        float wd[4] = {0.f, 0.f, 0.f, 0.f};
        wd[i1] = pr[i1] / wsum;
        wd[i2] = pr[i2] / wsum;
        for (int e = 0; e < 4; e++) wdense[(size_t)t * 4 + e] = wd[e];
    }
}

// ---------------- routing -------------------------------------------------------
__global__ void route_zero_kernel(int* __restrict__ ecnt) {
    if (threadIdx.x < Ez) ecnt[threadIdx.x] = 0;
}
__global__ void route_kernel(const float* __restrict__ wd, int* __restrict__ ecnt,
                             int* __restrict__ elist) {
    int t = blockIdx.x * blockDim.x + threadIdx.x;
    if (t < Tz) {
#pragma unroll
        for (int e = 0; e < Ez; e++)
            if (wd[(size_t)t * Ez + e] > 0.f) {
                int p = atomicAdd(&ecnt[e], 1);
                elist[e * Tz + p] = t;
            }
    }
}
__global__ void route_pad_kernel(const int* __restrict__ ecnt, int* __restrict__ elist) {
    int e = blockIdx.x;
    int cnt = ecnt[e];
    int padded = (cnt + 127) & ~127;
    for (int i = cnt + threadIdx.x; i < padded; i += blockDim.x) elist[e * Tz + i] = 0;
}

// ---------------- aux loss ------------------------------------------------------
__global__ void aux_kernel(const float* __restrict__ probsb, const float* __restrict__ wdense,
                           float* __restrict__ out_aux) {
    int tid = threadIdx.x;
    float sP[4] = {0.f, 0.f, 0.f, 0.f}, sF[4] = {0.f, 0.f, 0.f, 0.f};
    for (int t = tid; t < Tz; t += 256)
        for (int e = 0; e < 4; e++) {
            sP[e] += probsb[(size_t)t * 4 + e];
            sF[e] += (wdense[(size_t)t * 4 + e] > 0.f) ? 1.f : 0.f;
        }
    __shared__ float rP[4][256], rF[4][256];
    for (int e = 0; e < 4; e++) { rP[e][tid] = sP[e]; rF[e][tid] = sF[e]; }
    __syncthreads();
    for (int off = 128; off; off >>= 1) {
        if (tid < off)
            for (int e = 0; e < 4; e++) {
                rP[e][tid] += rP[e][tid + off];
                rF[e][tid] += rF[e][tid + off];
            }
        __syncthreads();
    }
    if (tid == 0) {
        float aux = 0.f;
        for (int e = 0; e < 4; e++)
            aux += (rF[e][0] * (1.0f / Tz)) * (rP[e][0] * (1.0f / Tz));
        *out_aux = (float)Ez * aux;
    }
}

// ---------------- final: out = x2 + sum_e masked ffe[e] -------------------------
__global__ void final_kernel(const float* __restrict__ x2, const float* __restrict__ ffe,
                             const float* __restrict__ wd, float* __restrict__ out) {
    for (int i = blockIdx.x * blockDim.x + threadIdx.x; i < Tz * Dz;
         i += gridDim.x * blockDim.x) {
        int t = i >> 10;
        float s = x2[i];
#pragma unroll
        for (int e = 0; e < Ez; e++)
            if (wd[(size_t)t * Ez + e] > 0.f) s += ffe[(size_t)e * Tz * Dz + i];
        out[i] = s;
    }
}

// ---------------- launch -------------------------------------------------------
extern "C" void kernel_launch(void* const* d_in, const int* in_sizes, int n_in,
                              void* d_out, int out_size) {
    const float* x      = (const float*)d_in[0];
    const float* n1w    = (const float*)d_in[1];
    const float* n2w    = (const float*)d_in[2];
    const float* wq     = (const float*)d_in[3];
    const float* wk     = (const float*)d_in[4];
    const float* wv     = (const float*)d_in[5];
    const float* wo     = (const float*)d_in[6];
    const float* idx_wq = (const float*)d_in[7];
    const float* idx_wk = (const float*)d_in[8];
    const float* idx_ww = (const float*)d_in[9];
    const float* gate_w = (const float*)d_in[10];
    const float* w1     = (const float*)d_in[11];
    const float* b1     = (const float*)d_in[12];
    const float* w2     = (const float*)d_in[13];
    const float* b2     = (const float*)d_in[14];
    float* out = (float*)d_out;

    float *xn, *q, *qI, *kI, *wI, *sc, *x2, *xn2, *wd, *pr, *ffe;
    int *selidx, *selcnt, *ecnt, *elist;
    bf16 *kvb, *xnx, *xn2x, *aox, *hx, *wqkvx, *wox, *iwqx, *w1x, *w2x;
    cudaGetSymbolAddress((void**)&xn,  g_xn);
    cudaGetSymbolAddress((void**)&q,   g_q);
    cudaGetSymbolAddress((void**)&qI,  g_qI);
    cudaGetSymbolAddress((void**)&kI,  g_kI);
    cudaGetSymbolAddress((void**)&wI,  g_wI);
    cudaGetSymbolAddress((void**)&sc,  g_sc);
    cudaGetSymbolAddress((void**)&selidx, g_selidx);
    cudaGetSymbolAddress((void**)&selcnt, g_selcnt);
    cudaGetSymbolAddress((void**)&x2,  g_x2);
    cudaGetSymbolAddress((void**)&xn2, g_xn2);
    cudaGetSymbolAddress((void**)&wd,  g_wd);
    cudaGetSymbolAddress((void**)&pr,  g_pr);
    cudaGetSymbolAddress((void**)&ffe, g_ffe);
    cudaGetSymbolAddress((void**)&ecnt,  g_ecnt);
    cudaGetSymbolAddress((void**)&elist, g_elist);
    cudaGetSymbolAddress((void**)&kvb,  g_kvb);
    cudaGetSymbolAddress((void**)&xnx,  g_xnx);
    cudaGetSymbolAddress((void**)&xn2x, g_xn2x);
    cudaGetSymbolAddress((void**)&aox,  g_aox);
    cudaGetSymbolAddress((void**)&hx,   g_hx);
    cudaGetSymbolAddress((void**)&wqkvx, g_wqkvx);
    cudaGetSymbolAddress((void**)&wox,  g_wox);
    cudaGetSymbolAddress((void**)&iwqx, g_iwqx);
    cudaGetSymbolAddress((void**)&w1x,  g_w1x);
    cudaGetSymbolAddress((void**)&w2x,  g_w2x);

    const size_t WZ = (size_t)2 * Dz * Dz;   // per-matrix [hi;lo] weight size

    // ---- weight split ([hi;lo]) ----
    convw_kernel<<<1024, 256>>>(wq, wqkvx, Dz, Dz);
    convw_kernel<<<1024, 256>>>(wk, wqkvx + WZ, Dz, Dz);
    convw_kernel<<<1024, 256>>>(wv, wqkvx + 2 * WZ, Dz, Dz);
    convw_kernel<<<1024, 256>>>(wo, wox, Dz, Dz);
    convw_kernel<<<256, 256>>>(idx_wq, iwqx, Dz, HIz * DIz);
    for (int e = 0; e < Ez; e++) {
        convw_kernel<<<2048, 256>>>(w1 + (size_t)e * Dz * DFz,
                                    w1x + (size_t)e * 2 * Dz * DFz, Dz, DFz);
        convw_kernel<<<2048, 256>>>(w2 + (size_t)e * DFz * Dz,
                                    w2x + (size_t)e * 2 * DFz * Dz, DFz, Dz);
    }

    // ---- attention path ----
    rmsnorm2_kernel<<<Tz, 256>>>(x, n1w, xn, xnx);
    hgemm_kernel<5><<<dim3(8, 32, 3), 128>>>(xnx, wqkvx, q, kvb, Tz, Dz, Dz,
                                             nullptr, nullptr, nullptr, nullptr, nullptr,
                                             0, WZ, (size_t)Tz * Dz, 0);
    hgemm_kernel<0><<<dim3(2, 32), 128>>>(xnx, iwqx, qI, nullptr, Tz, HIz * DIz, Dz,
                                          nullptr, nullptr, nullptr, nullptr, nullptr,
                                          0, 0, 0, 0);
    sgemm_small_kernel<<<dim3(1, 32), 256>>>(xn, idx_wk, kI, Tz, DIz, Dz);
    sgemm_small_kernel<<<dim3(1, 32), 256>>>(xn, idx_ww, wI, Tz, HIz, Dz);

    idxscore_kernel<<<dim3(Sz / 64, Sz / 16, Bz), dim3(16, 16)>>>(qI, kI, wI, sc);
    topk_kernel<<<Tz, 256>>>(sc, selidx, selcnt);
    attn_kernel<<<Tz, 512>>>(q, kvb, kvb + (size_t)Tz * Dz, selidx, selcnt, aox);
    hgemm_kernel<1><<<dim3(8, 32), 128>>>(aox, wox, x2, nullptr, Tz, Dz, Dz,
                                          nullptr, x, nullptr, nullptr, nullptr,
                                          0, 0, 0, 0);

    // ---- MoE path (routed + expert-batched) ----
    rmsnorm2_kernel<<<Tz, 256>>>(x2, n2w, xn2, xn2x);
    gate_kernel<<<Tz, 256>>>(xn2, gate_w, wd, pr);
    route_zero_kernel<<<1, 32>>>(ecnt);
    route_kernel<<<Tz / 256, 256>>>(wd, ecnt, elist);
    route_pad_kernel<<<Ez, 128>>>(ecnt, elist);
    hgemm_kernel<2><<<dim3(32, 32, Ez), 128>>>(xn2x, w1x, nullptr, hx, Tz, DFz, Dz,
                                               b1, nullptr, nullptr, elist, ecnt,
                                               0, (size_t)2 * Dz * DFz,
                                               (size_t)Tz * 2 * DFz, DFz);
    hgemm_kernel<3><<<dim3(8, 32, Ez), 128>>>(hx, w2x, ffe, nullptr, Tz, Dz, DFz,
                                              b2, nullptr, wd, elist, ecnt,
                                              (size_t)Tz * 2 * DFz, (size_t)2 * DFz * Dz,
                                              (size_t)Tz * Dz, Dz);

    final_kernel<<<8192, 256>>>(x2, ffe, wd, out);
    aux_kernel<<<1, 256>>>(pr, wd, out + (out_size - 1));
}

// round 13
// speedup vs baseline: 3.0232x; 1.0592x over previous
#include <cuda_runtime.h>
#include <cuda_bf16.h>
#include <math.h>
#include <stdint.h>

// Problem dims (fixed by setup_inputs)
#define Bz 2
#define Sz 2048
#define Dz 1024
#define Tz 4096           // B*S
#define Hz 16
#define DHz 64
#define HIz 4
#define DIz 64
#define TKz 512
#define Ez 4
#define DFz 4096

typedef __nv_bfloat16 bf16;

// ---------------- scratch (device globals; no allocation allowed) --------------
__device__ float g_xn [Tz*Dz];
__device__ float g_q  [Tz*Dz];
__device__ float g_qI [Tz*HIz*DIz];
__device__ float g_kI [Tz*DIz];
__device__ float g_wI [Tz*HIz];
__device__ float g_sc [(size_t)Bz*Sz*Sz];
__device__ int   g_selidx[(size_t)Tz*TKz];
__device__ int   g_selcnt[Tz];
__device__ float g_x2 [Tz*Dz];
__device__ float g_xn2[Tz*Dz];
__device__ float g_wd [Tz*Ez];
__device__ float g_pr [Tz*Ez];
__device__ int   g_ecnt[Ez];
__device__ int   g_elist[Ez*Tz];
__device__ float g_ffe[(size_t)Ez*Tz*Dz];

// bf16 operands: split storage is [hi|lo] (2K); GEMM remaps k-blocks to get
// the 3-term product Ahi*Bhi + Ahi*Blo + Alo*Bhi.
__device__ bf16 g_kvb  [(size_t)2*Tz*Dz];
__device__ bf16 g_xnx  [(size_t)Tz*2*Dz];
__device__ bf16 g_xn2x [(size_t)Tz*2*Dz];
__device__ bf16 g_aox  [(size_t)Tz*2*Dz];
__device__ bf16 g_hx   [(size_t)Ez*Tz*2*DFz];
__device__ bf16 g_wqkvx[(size_t)3*2*Dz*Dz];
__device__ bf16 g_wox  [2*Dz*Dz];
__device__ bf16 g_iwqx [2*Dz*HIz*DIz];
__device__ bf16 g_w1x  [(size_t)Ez*2*Dz*DFz];
__device__ bf16 g_w2x  [(size_t)Ez*2*DFz*Dz];

// ---------------- helpers ------------------------------------------------------
__device__ __forceinline__ float gelu_f(float x) {
    float x3 = x * x * x;
    return 0.5f * x * (1.0f + tanhf(0.7978845608028654f * (x + 0.044715f * x3)));
}
__device__ __forceinline__ uint32_t smem_u32(const void* p) {
    return (uint32_t)__cvta_generic_to_shared(p);
}
__device__ __forceinline__ void ldsm4(uint32_t& r0, uint32_t& r1, uint32_t& r2,
                                      uint32_t& r3, uint32_t a) {
    asm volatile("ldmatrix.sync.aligned.m8n8.x4.shared.b16 {%0,%1,%2,%3}, [%4];\n"
                 : "=r"(r0), "=r"(r1), "=r"(r2), "=r"(r3) : "r"(a));
}
__device__ __forceinline__ void ldsm4t(uint32_t& r0, uint32_t& r1, uint32_t& r2,
                                       uint32_t& r3, uint32_t a) {
    asm volatile("ldmatrix.sync.aligned.m8n8.x4.trans.shared.b16 {%0,%1,%2,%3}, [%4];\n"
                 : "=r"(r0), "=r"(r1), "=r"(r2), "=r"(r3) : "r"(a));
}
__device__ __forceinline__ void mma_bf16(float c[4], uint32_t a0, uint32_t a1,
                                         uint32_t a2, uint32_t a3,
                                         uint32_t b0, uint32_t b1) {
    asm volatile("mma.sync.aligned.m16n8k16.row.col.f32.bf16.bf16.f32 "
                 "{%0,%1,%2,%3}, {%4,%5,%6,%7}, {%8,%9}, {%0,%1,%2,%3};\n"
                 : "+f"(c[0]), "+f"(c[1]), "+f"(c[2]), "+f"(c[3])
                 : "r"(a0), "r"(a1), "r"(a2), "r"(a3), "r"(b0), "r"(b1));
}
#define CPA16(dst, src) \
    asm volatile("cp.async.cg.shared.global [%0], [%1], 16;\n" :: "r"(dst), "l"(src))
#define CPA_COMMIT() asm volatile("cp.async.commit_group;\n" ::)
#define CPA_WAIT0()  asm volatile("cp.async.wait_group 0;\n" ::)

// ---------------- rmsnorm (fp32 out optional + bf16 [hi|lo] out) ---------------
__global__ void rmsnorm2_kernel(const float* __restrict__ x, const float* __restrict__ w,
                                float* __restrict__ y, bf16* __restrict__ yx) {
    int t = blockIdx.x;
    int tid = threadIdx.x;
    const float* xr = x + (size_t)t * Dz;
    float s = 0.f;
    for (int i = tid; i < Dz; i += 256) { float v = xr[i]; s += v * v; }
    __shared__ float red[256];
    red[tid] = s; __syncthreads();
    for (int off = 128; off; off >>= 1) {
        if (tid < off) red[tid] += red[tid + off];
        __syncthreads();
    }
    float inv = rsqrtf(red[0] * (1.0f / Dz) + 1e-6f);
    bf16* yr = yx + (size_t)t * 2 * Dz;
    for (int i = tid; i < Dz; i += 256) {
        float v = xr[i] * inv * w[i];
        if (y) y[(size_t)t * Dz + i] = v;
        bf16 hi = __float2bfloat16(v);
        bf16 lo = __float2bfloat16(v - __bfloat162float(hi));
        yr[i] = hi;
        yr[Dz + i] = lo;
    }
}

// ---------------- weight split: [K][N] fp32 -> [2K][N] bf16 [hi;lo] ------------
// N must be a power of two; logN = log2(N).
__global__ void convw_kernel(const float* __restrict__ src, bf16* __restrict__ dst,
                             int K, int logN) {
    int N = 1 << logN;
    unsigned nmask = (unsigned)(N - 1);
    size_t total = ((size_t)K << logN) >> 2;
    for (size_t i = blockIdx.x * blockDim.x + threadIdx.x; i < total;
         i += (size_t)gridDim.x * blockDim.x) {
        size_t base = i << 2;
        int k = (int)(base >> logN);
        int n = (int)(base & nmask);
        float4 a = ((const float4*)src)[i];
        __align__(8) bf16 hv[4], lv[4];
        hv[0] = __float2bfloat16(a.x); lv[0] = __float2bfloat16(a.x - __bfloat162float(hv[0]));
        hv[1] = __float2bfloat16(a.y); lv[1] = __float2bfloat16(a.y - __bfloat162float(hv[1]));
        hv[2] = __float2bfloat16(a.z); lv[2] = __float2bfloat16(a.z - __bfloat162float(hv[2]));
        hv[3] = __float2bfloat16(a.w); lv[3] = __float2bfloat16(a.w - __bfloat162float(hv[3]));
        *(uint2*)&dst[((size_t)k << logN) + n] = *(uint2*)hv;
        *(uint2*)&dst[((size_t)(K + k) << logN) + n] = *(uint2*)lv;
    }
}

// ---------------- bf16 tensor-core GEMM (z-batched, 3-term remap) ---------------
// Logical C[M,N] = A[M,3*Kthird] x B[3*Kthird,N] stored [hi|lo] (2*Kthird);
// k-block kt maps: A-block = kt<KB?kt:kt-KB, B-block = kt<2KB?kt:kt-2KB.
// 128 threads, 4 warps, warp tile 64x64, CTA tile 128x128.
// EPI 0: Cf = val
// EPI 1: Cf = val + resid
// EPI 2: gather A rows via elist[z]; Cb+z*c_zs [hi|lo] (stride 2N) of gelu(val+bias)
// EPI 3: scatter: (Cf+z*c_zs)[tok*N+c] = wdv[tok*Ez+z]*(val+bias[c])
// EPI 5: QKV: z==0 -> Cf fp32; z>=1 -> (Cb+(z-1)*c_zs) plain bf16
template<int EPI>
__global__ void __launch_bounds__(128, 2)
hgemm_kernel(const bf16* __restrict__ A, const bf16* __restrict__ B,
             float* __restrict__ Cf, bf16* __restrict__ Cb,
             int M, int N, int Kthird,
             const float* __restrict__ bias, const float* __restrict__ resid,
             const float* __restrict__ wdv,
             const int* __restrict__ elist, const int* __restrict__ ecnt,
             size_t a_zs, size_t b_zs, size_t c_zs, int bias_zs) {
    int z = blockIdx.z;
    int bm = blockIdx.y * 128, bn = blockIdx.x * 128;
    int cnt = M;
    if (ecnt) {
        cnt = ecnt[z];
        int padded = (cnt + 127) & ~127;
        if (bm >= padded) return;
    }
    A += (size_t)z * a_zs;
    B += (size_t)z * b_zs;
    if (bias) bias += (size_t)z * bias_zs;
    const int* lst = elist ? elist + (size_t)z * Tz : nullptr;

    __shared__ __align__(16) bf16 As[2][128][40];
    __shared__ __align__(16) bf16 Bs[2][32][136];
    int tid = threadIdx.x;
    int warp = tid >> 5, lane = tid & 31;
    int wm = (warp & 1) * 64, wn = (warp >> 1) * 64;

    const int KB = Kthird >> 5;
    const int KT = 3 * KB;
    const int AS = 2 * Kthird;

    int arow = tid >> 2, acol = (tid & 3) * 8;
    int brow = tid >> 4, bcol = (tid & 15) * 8;
    const bf16* Ag[4];
#pragma unroll
    for (int j = 0; j < 4; j++) {
        int r = bm + arow + 32 * j;
        if (EPI == 2) r = lst[r];
        Ag[j] = A + (size_t)r * AS + acol;
    }
    const bf16* Bg = B + (size_t)brow * N + bn + bcol;

    float c[4][8][4];
#pragma unroll
    for (int mi = 0; mi < 4; mi++)
#pragma unroll
        for (int ni = 0; ni < 8; ni++)
#pragma unroll
            for (int j = 0; j < 4; j++) c[mi][ni][j] = 0.f;

    {
#pragma unroll
        for (int j = 0; j < 4; j++)
            CPA16(smem_u32(&As[0][arow + 32 * j][acol]), Ag[j]);
#pragma unroll
        for (int j = 0; j < 4; j++)
            CPA16(smem_u32(&Bs[0][brow + 8 * j][bcol]), Bg + (size_t)(8 * j) * N);
        CPA_COMMIT();
    }
    int buf = 0;
    for (int kt = 0; kt < KT; kt++) {
        CPA_WAIT0();
        __syncthreads();
        if (kt + 1 < KT) {
            int nb = buf ^ 1;
            int k2 = kt + 1;
            int ak = (k2 < KB) ? k2 : k2 - KB;
            int bk = (k2 < 2 * KB) ? k2 : k2 - 2 * KB;
#pragma unroll
            for (int j = 0; j < 4; j++)
                CPA16(smem_u32(&As[nb][arow + 32 * j][acol]), Ag[j] + ak * 32);
#pragma unroll
            for (int j = 0; j < 4; j++)
                CPA16(smem_u32(&Bs[nb][brow + 8 * j][bcol]),
                      Bg + (size_t)(bk * 32 + 8 * j) * N);
            CPA_COMMIT();
        }
#pragma unroll
        for (int kk = 0; kk < 32; kk += 16) {
            uint32_t a[4][4], b[8][2];
#pragma unroll
            for (int mi = 0; mi < 4; mi++) {
                uint32_t addr = smem_u32(
                    &As[buf][wm + mi * 16 + (lane & 15)][kk + ((lane >> 4) << 3)]);
                ldsm4(a[mi][0], a[mi][1], a[mi][2], a[mi][3], addr);
            }
#pragma unroll
            for (int nj = 0; nj < 4; nj++) {
                uint32_t addr = smem_u32(
                    &Bs[buf][kk + (lane & 15)][wn + nj * 16 + ((lane >> 4) << 3)]);
                ldsm4t(b[2 * nj][0], b[2 * nj][1], b[2 * nj + 1][0], b[2 * nj + 1][1], addr);
            }
#pragma unroll
            for (int mi = 0; mi < 4; mi++)
#pragma unroll
                for (int ni = 0; ni < 8; ni++)
                    mma_bf16(c[mi][ni], a[mi][0], a[mi][1], a[mi][2], a[mi][3],
                             b[ni][0], b[ni][1]);
        }
        buf ^= 1;
    }

#pragma unroll
    for (int mi = 0; mi < 4; mi++) {
#pragma unroll
        for (int rr = 0; rr < 2; rr++) {
            int r = bm + wm + mi * 16 + (lane >> 2) + rr * 8;
            if (EPI == 3) {
                if (r < cnt) {
                    int tok = lst[r];
                    float rsc = wdv[(size_t)tok * Ez + z];
                    float* dst = Cf + (size_t)z * c_zs;
#pragma unroll
                    for (int ni = 0; ni < 8; ni++)
#pragma unroll
                        for (int cc = 0; cc < 2; cc++) {
                            int col = bn + wn + ni * 8 + (lane & 3) * 2 + cc;
                            dst[(size_t)tok * N + col] =
                                rsc * (c[mi][ni][rr * 2 + cc] + bias[col]);
                        }
                }
            } else if (EPI == 5) {
                if (z == 0) {
#pragma unroll
                    for (int ni = 0; ni < 8; ni++)
#pragma unroll
                        for (int cc = 0; cc < 2; cc++) {
                            int col = bn + wn + ni * 8 + (lane & 3) * 2 + cc;
                            Cf[(size_t)r * N + col] = c[mi][ni][rr * 2 + cc];
                        }
                } else {
                    bf16* dst = Cb + (size_t)(z - 1) * c_zs;
#pragma unroll
                    for (int ni = 0; ni < 8; ni++) {
                        int colb = bn + wn + ni * 8 + (lane & 3) * 2;
                        __nv_bfloat162 p;
                        p.x = __float2bfloat16(c[mi][ni][rr * 2]);
                        p.y = __float2bfloat16(c[mi][ni][rr * 2 + 1]);
                        *(__nv_bfloat162*)&dst[(size_t)r * N + colb] = p;
                    }
                }
            } else if (EPI == 2) {
                bf16* dstb = Cb + (size_t)z * c_zs;
#pragma unroll
                for (int ni = 0; ni < 8; ni++)
#pragma unroll
                    for (int cc = 0; cc < 2; cc++) {
                        int col = bn + wn + ni * 8 + (lane & 3) * 2 + cc;
                        float g = gelu_f(c[mi][ni][rr * 2 + cc] + bias[col]);
                        bf16 hi = __float2bfloat16(g);
                        bf16 lo = __float2bfloat16(g - __bfloat162float(hi));
                        size_t base = (size_t)r * 2 * N;
                        dstb[base + col] = hi;
                        dstb[base + N + col] = lo;
                    }
            } else {
#pragma unroll
                for (int ni = 0; ni < 8; ni++)
#pragma unroll
                    for (int cc = 0; cc < 2; cc++) {
                        int col = bn + wn + ni * 8 + (lane & 3) * 2 + cc;
                        float val = c[mi][ni][rr * 2 + cc];
                        if (EPI == 0) Cf[(size_t)r * N + col] = val;
                        else          Cf[(size_t)r * N + col] = val + resid[(size_t)r * N + col];
                    }
            }
        }
    }
}

// ---------------- small fp32 GEMM (kI: N=64, wI: N=4) --------------------------
__global__ void __launch_bounds__(256, 2)
sgemm_small_kernel(const float* __restrict__ A, const float* __restrict__ B,
                   float* __restrict__ C, int M, int N, int K) {
    const int BM = 128, BN = 128, BK = 8, TM = 8, TN = 8;
    __shared__ float As[BK][BM];
    __shared__ float Bs[BK][BN];
    int tid = threadIdx.x;
    int bm = blockIdx.y * BM;
    int bn = blockIdx.x * BN;
    int trow = (tid / 16) * TM;
    int tcol = (tid % 16) * TN;
    float acc[TM][TN];
#pragma unroll
    for (int i = 0; i < TM; i++)
#pragma unroll
        for (int j = 0; j < TN; j++) acc[i][j] = 0.f;
    int arow = tid >> 1, acol = (tid & 1) * 4;
    int brow = tid >> 5, bcol = (tid & 31) * 4;
    const float* Aptr = A + (size_t)(bm + arow) * K;
    for (int k0 = 0; k0 < K; k0 += BK) {
        float4 av = *(const float4*)(Aptr + k0 + acol);
        As[acol + 0][arow] = av.x; As[acol + 1][arow] = av.y;
        As[acol + 2][arow] = av.z; As[acol + 3][arow] = av.w;
        int bc = bn + bcol;
#pragma unroll
        for (int j = 0; j < 4; j++)
            Bs[brow][bcol + j] = (bc + j < N) ? B[(size_t)(k0 + brow) * N + bc + j] : 0.f;
        __syncthreads();
#pragma unroll
        for (int kk = 0; kk < BK; kk++) {
            float ar[TM], br[TN];
#pragma unroll
            for (int i = 0; i < TM; i++) ar[i] = As[kk][trow + i];
#pragma unroll
            for (int j = 0; j < TN; j++) br[j] = Bs[kk][tcol + j];
#pragma unroll
            for (int i = 0; i < TM; i++)
#pragma unroll
                for (int j = 0; j < TN; j++) acc[i][j] += ar[i] * br[j];
        }
        __syncthreads();
    }
#pragma unroll
    for (int i = 0; i < TM; i++) {
        int r = bm + trow + i;
#pragma unroll
        for (int j = 0; j < TN; j++) {
            int cidx = bn + tcol + j;
            if (cidx < N) C[(size_t)r * N + cidx] = acc[i][j];
        }
    }
}

// ---------------- indexer scores ------------------------------------------------
__global__ void idxscore_kernel(const float* __restrict__ qI, const float* __restrict__ kI,
                                const float* __restrict__ wI, float* __restrict__ sc) {
    int b  = blockIdx.z;
    int t0 = blockIdx.y * 16;
    int s0 = blockIdx.x * 64;
    if (s0 > t0 + 15) return;
    __shared__ float qIs[16][257];
    __shared__ float kIs[64][65];
    __shared__ float wIs[16][4];
    int tx = threadIdx.x, ty = threadIdx.y;
    int tid = ty * 16 + tx;
    for (int idx = tid; idx < 16 * 256; idx += 256) {
        int r = idx >> 8, c = idx & 255;
        qIs[r][c] = qI[((size_t)(b * Sz + t0 + r)) * 256 + c];
    }
    for (int idx = tid; idx < 64 * 64; idx += 256) {
        int r = idx >> 6, c = idx & 63;
        kIs[r][c] = kI[((size_t)(b * Sz + s0 + r)) * 64 + c];
    }
    if (tid < 64) wIs[tid >> 2][tid & 3] = wI[((size_t)(b * Sz + (tid >> 2) + t0)) * 4 + (tid & 3)];
    __syncthreads();

    float acc4[4] = {0.f, 0.f, 0.f, 0.f};
#pragma unroll
    for (int h = 0; h < 4; h++) {
        float dot[4] = {0.f, 0.f, 0.f, 0.f};
#pragma unroll
        for (int d = 0; d < 64; d++) {
            float qv = qIs[ty][h * 64 + d];
            dot[0] += qv * kIs[tx +  0][d];
            dot[1] += qv * kIs[tx + 16][d];
            dot[2] += qv * kIs[tx + 32][d];
            dot[3] += qv * kIs[tx + 48][d];
        }
        float wv = wIs[ty][h];
#pragma unroll
        for (int j = 0; j < 4; j++) acc4[j] += wv * fmaxf(dot[j], 0.f);
    }
    int t = t0 + ty;
#pragma unroll
    for (int j = 0; j < 4; j++) {
        int s = s0 + tx + 16 * j;
        if (s <= t) sc[((size_t)(b * Sz + t)) * Sz + s] = acc4[j];
    }
}

// ---------------- top-k (512) per (b,t): radix select, jax tie-break -----------
__global__ void topk_kernel(const float* __restrict__ sc, int* __restrict__ selidx,
                            int* __restrict__ selcnt) {
    int bt = blockIdx.x;
    int t = bt & (Sz - 1);
    int n = t + 1;
    int tid = threadIdx.x;
    int* outp = selidx + (size_t)bt * TKz;
    if (n <= TKz) {
        for (int i = tid; i < n; i += 256) outp[i] = i;
        if (tid == 0) selcnt[bt] = n;
        return;
    }
    const float* row = sc + (size_t)bt * Sz;
    __shared__ unsigned keys[Sz];
    for (int i = tid; i < n; i += 256) {
        unsigned u = __float_as_uint(row[i]);
        keys[i] = (u & 0x80000000u) ? ~u : (u | 0x80000000u);
    }
    __shared__ int hist[256];
    __shared__ unsigned p_s;
    __shared__ int need_s;
    if (tid == 0) { p_s = 0; need_s = TKz; }
    __syncthreads();
    for (int byte = 3; byte >= 0; byte--) {
        int sh = byte * 8;
        for (int i = tid; i < 256; i += 256) hist[i] = 0;
        __syncthreads();
        unsigned p = p_s;
        unsigned mask_hi = (byte == 3) ? 0u : (0xFFFFFFFFu << (sh + 8));
        for (int i = tid; i < n; i += 256) {
            unsigned k = keys[i];
            if ((k & mask_hi) == p) atomicAdd(&hist[(k >> sh) & 255u], 1);
        }
        __syncthreads();
        if (tid == 0) {
            int need = need_s;
            int acc = 0;
            int chosen = 0;
            for (int b2 = 255; b2 >= 0; b2--) {
                if (acc + hist[b2] >= need) { chosen = b2; break; }
                acc += hist[b2];
            }
            need_s = need - acc;
            p_s = p | ((unsigned)chosen << sh);
        }
        __syncthreads();
    }
    unsigned p = p_s;   // exact TKz-th largest key
    __shared__ int pos;
    if (tid == 0) pos = 0;
    __syncthreads();
    for (int i = tid; i < n; i += 256)
        if (keys[i] > p) { int j = atomicAdd(&pos, 1); outp[j] = i; }
    __syncthreads();
    if (tid == 0) {
        int j = pos;
        for (int i = 0; i < n && j < TKz; i++)
            if (keys[i] == p) outp[j++] = i;
        selcnt[bt] = TKz;
    }
}

// ---------------- sparse attention (bf16 K/V), two-phase ------------------------
__global__ void __launch_bounds__(512)
attn_kernel(const float* __restrict__ q, const bf16* __restrict__ kb,
            const bf16* __restrict__ vb, const int* __restrict__ selidx,
            const int* __restrict__ selcnt, bf16* __restrict__ aox) {
    int bt = blockIdx.x;
    int b = bt >> 11;
    int tid = threadIdx.x;
    __shared__ float qs[Hz * DHz];
    __shared__ int sels[TKz + 4];
    __shared__ float sscore[Hz][TKz];
    int n = selcnt[bt];
    int n4 = (n + 3) & ~3;
    for (int i = tid; i < Dz; i += 512) qs[i] = q[(size_t)bt * Dz + i];
    for (int i = tid; i < n; i += 512) sels[i] = selidx[(size_t)bt * TKz + i];
    if (tid < 4) sels[n + tid] = selidx[(size_t)bt * TKz];   // pad with sel 0
    __syncthreads();
    int h = tid >> 5, lane = tid & 31;
    float q0 = qs[h * 64 + 2 * lane], q1 = qs[h * 64 + 2 * lane + 1];
    size_t hoff = h * 64 + 2 * lane;
    float m = -3.0e38f;
    // Phase A: all scores -> smem (4-way unrolled, overlapped shuffle chains)
    for (int i = 0; i < n4; i += 4) {
        float part[4];
#pragma unroll
        for (int j = 0; j < 4; j++) {
            int s = sels[i + j];
            float2 kf = __bfloat1622float2(
                *(const __nv_bfloat162*)(kb + ((size_t)(b * Sz + s)) * Dz + hoff));
            part[j] = q0 * kf.x + q1 * kf.y;
        }
#pragma unroll
        for (int off = 16; off; off >>= 1)
#pragma unroll
            for (int j = 0; j < 4; j++)
                part[j] += __shfl_xor_sync(0xffffffffu, part[j], off);
#pragma unroll
        for (int j = 0; j < 4; j++) {
            float scv = part[j] * 0.125f;
            sscore[h][i + j] = scv;
            m = fmaxf(m, scv);
        }
    }
    // Phase B: independent accumulation (MLP-friendly)
    float l = 0.f, o0 = 0.f, o1 = 0.f;
#pragma unroll 4
    for (int i = 0; i < n; i++) {
        float pw = __expf(sscore[h][i] - m);
        int s = sels[i];
        float2 vf = __bfloat1622float2(
            *(const __nv_bfloat162*)(vb + ((size_t)(b * Sz + s)) * Dz + hoff));
        o0 += pw * vf.x;
        o1 += pw * vf.y;
        l += pw;
    }
    float inv = 1.0f / l;
    o0 *= inv; o1 *= inv;
    size_t base = (size_t)bt * 2 * Dz;
    int c0 = h * 64 + 2 * lane, c1 = c0 + 1;
    bf16 h0 = __float2bfloat16(o0);
    bf16 l0 = __float2bfloat16(o0 - __bfloat162float(h0));
    bf16 h1 = __float2bfloat16(o1);
    bf16 l1 = __float2bfloat16(o1 - __bfloat162float(h1));
    aox[base + c0] = h0;       aox[base + c1] = h1;
    aox[base + Dz + c0] = l0;  aox[base + Dz + c1] = l1;
}

// ---------------- gate: softmax(4) + top-2 + combine weights -------------------
__global__ void gate_kernel(const float* __restrict__ xn2, const float* __restrict__ gw,
                            float* __restrict__ wdense, float* __restrict__ probsb) {
    int t = blockIdx.x;
    int tid = threadIdx.x;
    const float* xr = xn2 + (size_t)t * Dz;
    float le[4] = {0.f, 0.f, 0.f, 0.f};
    for (int d = tid; d < Dz; d += 256) {
        float xv = xr[d];
        const float* g = gw + (size_t)d * 4;
        le[0] += xv * g[0]; le[1] += xv * g[1];
        le[2] += xv * g[2]; le[3] += xv * g[3];
    }
    __shared__ float red[4][256];
    for (int e = 0; e < 4; e++) red[e][tid] = le[e];
    __syncthreads();
    for (int off = 128; off; off >>= 1) {
        if (tid < off)
            for (int e = 0; e < 4; e++) red[e][tid] += red[e][tid + off];
        __syncthreads();
    }
    if (tid == 0) {
        float lg[4], pr[4];
        float mx = -3.0e38f;
        for (int e = 0; e < 4; e++) { lg[e] = red[e][0]; mx = fmaxf(mx, lg[e]); }
        float sum = 0.f;
        for (int e = 0; e < 4; e++) { pr[e] = expf(lg[e] - mx); sum += pr[e]; }
        float inv = 1.0f / sum;
        for (int e = 0; e < 4; e++) { pr[e] *= inv; probsb[(size_t)t * 4 + e] = pr[e]; }
        int i1 = 0;
        for (int e = 1; e < 4; e++) if (pr[e] > pr[i1]) i1 = e;
        int i2 = -1; float b2v = -1.f;
        for (int e = 0; e < 4; e++) if (e != i1 && pr[e] > b2v) { b2v = pr[e]; i2 = e; }
        float wsum = pr[i1] + pr[i2];
        float wd[4] = {0.f, 0.f, 0.f, 0.f};
        wd[i1] = pr[i1] / wsum;
        wd[i2] = pr[i2] / wsum;
        for (int e = 0; e < 4; e++) wdense[(size_t)t * 4 + e] = wd[e];
    }
}

// ---------------- routing -------------------------------------------------------
__global__ void route_zero_kernel(int* __restrict__ ecnt) {
    if (threadIdx.x < Ez) ecnt[threadIdx.x] = 0;
}
__global__ void route_kernel(const float* __restrict__ wd, int* __restrict__ ecnt,
                             int* __restrict__ elist) {
    int t = blockIdx.x * blockDim.x + threadIdx.x;
    if (t < Tz) {
#pragma unroll
        for (int e = 0; e < Ez; e++)
            if (wd[(size_t)t * Ez + e] > 0.f) {
                int p = atomicAdd(&ecnt[e], 1);
                elist[e * Tz + p] = t;
            }
    }
}
__global__ void route_pad_kernel(const int* __restrict__ ecnt, int* __restrict__ elist) {
    int e = blockIdx.x;
    int cnt = ecnt[e];
    int padded = (cnt + 127) & ~127;
    for (int i = cnt + threadIdx.x; i < padded; i += blockDim.x) elist[e * Tz + i] = 0;
}

// ---------------- aux loss ------------------------------------------------------
__global__ void aux_kernel(const float* __restrict__ probsb, const float* __restrict__ wdense,
                           float* __restrict__ out_aux) {
    int tid = threadIdx.x;
    float sP[4] = {0.f, 0.f, 0.f, 0.f}, sF[4] = {0.f, 0.f, 0.f, 0.f};
    for (int t = tid; t < Tz; t += 256)
        for (int e = 0; e < 4; e++) {
            sP[e] += probsb[(size_t)t * 4 + e];
            sF[e] += (wdense[(size_t)t * 4 + e] > 0.f) ? 1.f : 0.f;
        }
    __shared__ float rP[4][256], rF[4][256];
    for (int e = 0; e < 4; e++) { rP[e][tid] = sP[e]; rF[e][tid] = sF[e]; }
    __syncthreads();
    for (int off = 128; off; off >>= 1) {
        if (tid < off)
            for (int e = 0; e < 4; e++) {
                rP[e][tid] += rP[e][tid + off];
                rF[e][tid] += rF[e][tid + off];
            }
        __syncthreads();
    }
    if (tid == 0) {
        float aux = 0.f;
        for (int e = 0; e < 4; e++)
            aux += (rF[e][0] * (1.0f / Tz)) * (rP[e][0] * (1.0f / Tz));
        *out_aux = (float)Ez * aux;
    }
}

// ---------------- final: out = x2 + sum_e masked ffe[e] -------------------------
__global__ void final_kernel(const float* __restrict__ x2, const float* __restrict__ ffe,
                             const float* __restrict__ wd, float* __restrict__ out) {
    for (int i = blockIdx.x * blockDim.x + threadIdx.x; i < Tz * Dz;
         i += gridDim.x * blockDim.x) {
        int t = i >> 10;
        float s = x2[i];
#pragma unroll
        for (int e = 0; e < Ez; e++)
            if (wd[(size_t)t * Ez + e] > 0.f) s += ffe[(size_t)e * Tz * Dz + i];
        out[i] = s;
    }
}

// ---------------- launch -------------------------------------------------------
extern "C" void kernel_launch(void* const* d_in, const int* in_sizes, int n_in,
                              void* d_out, int out_size) {
    const float* x      = (const float*)d_in[0];
    const float* n1w    = (const float*)d_in[1];
    const float* n2w    = (const float*)d_in[2];
    const float* wq     = (const float*)d_in[3];
    const float* wk     = (const float*)d_in[4];
    const float* wv     = (const float*)d_in[5];
    const float* wo     = (const float*)d_in[6];
    const float* idx_wq = (const float*)d_in[7];
    const float* idx_wk = (const float*)d_in[8];
    const float* idx_ww = (const float*)d_in[9];
    const float* gate_w = (const float*)d_in[10];
    const float* w1     = (const float*)d_in[11];
    const float* b1     = (const float*)d_in[12];
    const float* w2     = (const float*)d_in[13];
    const float* b2     = (const float*)d_in[14];
    float* out = (float*)d_out;

    float *xn, *q, *qI, *kI, *wI, *sc, *x2, *xn2, *wd, *pr, *ffe;
    int *selidx, *selcnt, *ecnt, *elist;
    bf16 *kvb, *xnx, *xn2x, *aox, *hx, *wqkvx, *wox, *iwqx, *w1x, *w2x;
    cudaGetSymbolAddress((void**)&xn,  g_xn);
    cudaGetSymbolAddress((void**)&q,   g_q);
    cudaGetSymbolAddress((void**)&qI,  g_qI);
    cudaGetSymbolAddress((void**)&kI,  g_kI);
    cudaGetSymbolAddress((void**)&wI,  g_wI);
    cudaGetSymbolAddress((void**)&sc,  g_sc);
    cudaGetSymbolAddress((void**)&selidx, g_selidx);
    cudaGetSymbolAddress((void**)&selcnt, g_selcnt);
    cudaGetSymbolAddress((void**)&x2,  g_x2);
    cudaGetSymbolAddress((void**)&xn2, g_xn2);
    cudaGetSymbolAddress((void**)&wd,  g_wd);
    cudaGetSymbolAddress((void**)&pr,  g_pr);
    cudaGetSymbolAddress((void**)&ffe, g_ffe);
    cudaGetSymbolAddress((void**)&ecnt,  g_ecnt);
    cudaGetSymbolAddress((void**)&elist, g_elist);
    cudaGetSymbolAddress((void**)&kvb,  g_kvb);
    cudaGetSymbolAddress((void**)&xnx,  g_xnx);
    cudaGetSymbolAddress((void**)&xn2x, g_xn2x);
    cudaGetSymbolAddress((void**)&aox,  g_aox);
    cudaGetSymbolAddress((void**)&hx,   g_hx);
    cudaGetSymbolAddress((void**)&wqkvx, g_wqkvx);
    cudaGetSymbolAddress((void**)&wox,  g_wox);
    cudaGetSymbolAddress((void**)&iwqx, g_iwqx);
    cudaGetSymbolAddress((void**)&w1x,  g_w1x);
    cudaGetSymbolAddress((void**)&w2x,  g_w2x);

    const size_t WZ = (size_t)2 * Dz * Dz;

    // ---- weight split ([hi;lo]) ----
    convw_kernel<<<1024, 256>>>(wq, wqkvx, Dz, 10);
    convw_kernel<<<1024, 256>>>(wk, wqkvx + WZ, Dz, 10);
    convw_kernel<<<1024, 256>>>(wv, wqkvx + 2 * WZ, Dz, 10);
    convw_kernel<<<1024, 256>>>(wo, wox, Dz, 10);
    convw_kernel<<<256, 256>>>(idx_wq, iwqx, Dz, 8);
    for (int e = 0; e < Ez; e++) {
        convw_kernel<<<2048, 256>>>(w1 + (size_t)e * Dz * DFz,
                                    w1x + (size_t)e * 2 * Dz * DFz, Dz, 12);
        convw_kernel<<<2048, 256>>>(w2 + (size_t)e * DFz * Dz,
                                    w2x + (size_t)e * 2 * DFz * Dz, DFz, 10);
    }

    // ---- attention path ----
    rmsnorm2_kernel<<<Tz, 256>>>(x, n1w, xn, xnx);
    hgemm_kernel<5><<<dim3(8, 32, 3), 128>>>(xnx, wqkvx, q, kvb, Tz, Dz, Dz,
                                             nullptr, nullptr, nullptr, nullptr, nullptr,
                                             0, WZ, (size_t)Tz * Dz, 0);
    hgemm_kernel<0><<<dim3(2, 32), 128>>>(xnx, iwqx, qI, nullptr, Tz, HIz * DIz, Dz,
                                          nullptr, nullptr, nullptr, nullptr, nullptr,
                                          0, 0, 0, 0);
    sgemm_small_kernel<<<dim3(1, 32), 256>>>(xn, idx_wk, kI, Tz, DIz, Dz);
    sgemm_small_kernel<<<dim3(1, 32), 256>>>(xn, idx_ww, wI, Tz, HIz, Dz);

    idxscore_kernel<<<dim3(Sz / 64, Sz / 16, Bz), dim3(16, 16)>>>(qI, kI, wI, sc);
    topk_kernel<<<Tz, 256>>>(sc, selidx, selcnt);
    attn_kernel<<<Tz, 512>>>(q, kvb, kvb + (size_t)Tz * Dz, selidx, selcnt, aox);
    hgemm_kernel<1><<<dim3(8, 32), 128>>>(aox, wox, x2, nullptr, Tz, Dz, Dz,
                                          nullptr, x, nullptr, nullptr, nullptr,
                                          0, 0, 0, 0);

    // ---- MoE path (routed + expert-batched) ----
    rmsnorm2_kernel<<<Tz, 256>>>(x2, n2w, xn2, xn2x);
    gate_kernel<<<Tz, 256>>>(xn2, gate_w, wd, pr);
    route_zero_kernel<<<1, 32>>>(ecnt);
    route_kernel<<<Tz / 256, 256>>>(wd, ecnt, elist);
    route_pad_kernel<<<Ez, 128>>>(ecnt, elist);
    hgemm_kernel<2><<<dim3(32, 32, Ez), 128>>>(xn2x, w1x, nullptr, hx, Tz, DFz, Dz,
                                               b1, nullptr, nullptr, elist, ecnt,
                                               0, (size_t)2 * Dz * DFz,
                                               (size_t)Tz * 2 * DFz, DFz);
    hgemm_kernel<3><<<dim3(8, 32, Ez), 128>>>(hx, w2x, ffe, nullptr, Tz, Dz, DFz,
                                              b2, nullptr, wd, elist, ecnt,
                                              (size_t)Tz * 2 * DFz, (size_t)2 * DFz * Dz,
                                              (size_t)Tz * Dz, Dz);

    final_kernel<<<8192, 256>>>(x2, ffe, wd, out);
    aux_kernel<<<1, 256>>>(pr, wd, out + (out_size - 1));
}